// round 9
// baseline (speedup 1.0000x reference)
#include <cuda_runtime.h>
#include <cuda_fp16.h>
#include <math.h>
#include <stdint.h>

// ---------------- problem constants ----------------
#define RR 64
#define CC 256
#define EE 768
#define HH 12
#define DD 64
#define FF 3072
#define MM (RR*CC)          // 16384 tokens
#define QLD 2304            // packed qkv row stride (halves)

// ---------------- scratch (device globals; no allocation allowed) ----------------
__device__ float g_x   [MM*EE];       // residual stream (fp32)
__device__ float g_h   [MM*EE];       // reused as __half
__device__ float g_ctx [MM*EE];       // reused as __half
__device__ float g_aw  [HH*CC*RR*RR]; // fp32 scores (half p in-place post-softmax)
__device__ float g_big [MM*FF];       // reused: qkv (half) / ffn h1 (half)
__device__ float g_wt  [9437184/2 + 64];  // transposed half weights
__device__ float g_bias[4608];        // packed row/col qkv biases

// ---------------- helpers ----------------
__device__ __forceinline__ uint32_t smem_to_u32(const void* p) {
    uint32_t a;
    asm("{ .reg .u64 t; cvta.to.shared.u64 t, %1; cvt.u32.u64 %0, t; }" : "=r"(a) : "l"(p));
    return a;
}
__device__ __forceinline__ void cp_async16(uint32_t saddr, const void* gptr) {
    asm volatile("cp.async.cg.shared.global [%0], [%1], 16;" :: "r"(saddr), "l"(gptr));
}
#define CP_COMMIT() asm volatile("cp.async.commit_group;" ::: "memory")
#define CP_WAIT2()  asm volatile("cp.async.wait_group 2;" ::: "memory")
#define CP_WAIT1()  asm volatile("cp.async.wait_group 1;" ::: "memory")
#define CP_WAIT0()  asm volatile("cp.async.wait_group 0;" ::: "memory")

__device__ __forceinline__ void ldsm_x4(uint32_t* r, uint32_t addr) {
    asm volatile("ldmatrix.sync.aligned.m8n8.x4.shared.b16 {%0,%1,%2,%3}, [%4];"
        : "=r"(r[0]), "=r"(r[1]), "=r"(r[2]), "=r"(r[3]) : "r"(addr));
}
__device__ __forceinline__ void ldsm_x4_t(uint32_t* r, uint32_t addr) {
    asm volatile("ldmatrix.sync.aligned.m8n8.x4.trans.shared.b16 {%0,%1,%2,%3}, [%4];"
        : "=r"(r[0]), "=r"(r[1]), "=r"(r[2]), "=r"(r[3]) : "r"(addr));
}

__device__ __forceinline__ void mma_f16(float* d, const uint32_t* a, uint32_t b0, uint32_t b1) {
    asm volatile("mma.sync.aligned.m16n8k16.row.col.f32.f16.f16.f32 "
        "{%0,%1,%2,%3}, {%4,%5,%6,%7}, {%8,%9}, {%0,%1,%2,%3};"
        : "+f"(d[0]), "+f"(d[1]), "+f"(d[2]), "+f"(d[3])
        : "r"(a[0]), "r"(a[1]), "r"(a[2]), "r"(a[3]), "r"(b0), "r"(b1));
}

// ---------------- gelu (tanh approx) ----------------
__device__ __forceinline__ float gelu_f(float x) {
    float x3 = x * x * x;
    return 0.5f * x * (1.0f + tanhf(0.7978845608028654f * (x + 0.044715f * x3)));
}

// ---------------- fp16 mma.sync GEMM: 128x128 tile, 8 warps (4m x 2n), warp 32x64 ----------------
#define BKH 32
#define PITCH_H 40
#define TILE_H (128 * PITCH_H)
#define NSTAGE 4

__global__ void __launch_bounds__(256, 2) mma_gemm_f16(
    const __half* __restrict__ A, const __half* __restrict__ BT,
    const float* __restrict__ bias, const float* __restrict__ res,
    float* __restrict__ Cf, __half* __restrict__ Ch,
    int M, int N, int K, int act_gelu)
{
    extern __shared__ __half smh[];
    uint32_t sbase = smem_to_u32(smh);
    uint32_t AbufU[NSTAGE], BbufU[NSTAGE];
    #pragma unroll
    for (int s = 0; s < NSTAGE; s++) {
        AbufU[s] = sbase + (uint32_t)(2 * s    ) * TILE_H * 2;
        BbufU[s] = sbase + (uint32_t)(2 * s + 1) * TILE_H * 2;
    }

    int tid = threadIdx.x;
    int wid = tid >> 5, lane = tid & 31;
    int g = lane >> 2, t = lane & 3;
    int wm = wid & 3, wn = wid >> 2;
    int m0 = blockIdx.y * 128, n0 = blockIdx.x * 128;

    int l16 = lane & 15;
    uint32_t a_koff = (uint32_t)(lane >> 4) * 16;
    uint32_t offA[2];
    #pragma unroll
    for (int mt = 0; mt < 2; mt++)
        offA[mt] = (uint32_t)((wm * 32 + mt * 16 + l16) * PITCH_H) * 2 + a_koff;
    int l8 = lane & 7;
    int b_half16 = (lane >> 3) & 1;
    int b_grp8 = lane >> 4;
    uint32_t offB[4];
    #pragma unroll
    for (int p = 0; p < 4; p++)
        offB[p] = (uint32_t)((wn * 64 + p * 16 + b_grp8 * 8 + l8) * PITCH_H) * 2 + (uint32_t)b_half16 * 16;

    float acc[2][8][4];
    #pragma unroll
    for (int i = 0; i < 2; i++)
        #pragma unroll
        for (int j = 0; j < 8; j++)
            #pragma unroll
            for (int c = 0; c < 4; c++) acc[i][j][c] = 0.f;

    const int NT = K / BKH;   // >= 24 for all our shapes

    #define PREFETCH(kt, b) do {                                               \
        int k0p = (kt) * BKH;                                                  \
        _Pragma("unroll")                                                      \
        for (int i = 0; i < 2; i++) {                                          \
            int idx = i * 256 + tid;                                           \
            int row = idx >> 2, c8 = (idx & 3) * 8;                            \
            cp_async16(AbufU[b] + (uint32_t)(row * PITCH_H + c8) * 2,          \
                       A  + (size_t)(m0 + row) * K + k0p + c8);                \
            cp_async16(BbufU[b] + (uint32_t)(row * PITCH_H + c8) * 2,          \
                       BT + (size_t)(n0 + row) * K + k0p + c8);                \
        }                                                                      \
        CP_COMMIT();                                                           \
    } while (0)

    PREFETCH(0, 0);
    PREFETCH(1, 1);
    PREFETCH(2, 2);

    for (int kt = 0; kt < NT; kt++) {
        int b = kt & (NSTAGE - 1);
        CP_WAIT2();                    // group kt complete (3 real/empty groups in flight)
        __syncthreads();
        if (kt + 3 < NT) PREFETCH(kt + 3, (kt + 3) & (NSTAGE - 1)); else CP_COMMIT();

        uint32_t Ab = AbufU[b], Bb = BbufU[b];
        #pragma unroll
        for (int ks = 0; ks < 2; ks++) {
            uint32_t koff = (uint32_t)ks * 32;
            uint32_t af[2][4], bfr[4][4];
            ldsm_x4(af[0], Ab + offA[0] + koff);
            ldsm_x4(af[1], Ab + offA[1] + koff);
            #pragma unroll
            for (int p = 0; p < 4; p++)
                ldsm_x4(bfr[p], Bb + offB[p] + koff);
            #pragma unroll
            for (int mt = 0; mt < 2; mt++)
                #pragma unroll
                for (int p = 0; p < 4; p++) {
                    mma_f16(acc[mt][2 * p    ], af[mt], bfr[p][0], bfr[p][1]);
                    mma_f16(acc[mt][2 * p + 1], af[mt], bfr[p][2], bfr[p][3]);
                }
        }
    }
    #undef PREFETCH

    #pragma unroll
    for (int mt = 0; mt < 2; mt++) {
        #pragma unroll
        for (int nt = 0; nt < 8; nt++) {
            int m = m0 + wm * 32 + mt * 16 + g;
            int n = n0 + wn * 64 + nt * 8 + 2 * t;
            float bx = bias[n], by = bias[n + 1];
            #pragma unroll
            for (int half = 0; half < 2; half++) {
                int mr = m + half * 8;
                float vx = acc[mt][nt][half * 2 + 0] + bx;
                float vy = acc[mt][nt][half * 2 + 1] + by;
                if (act_gelu) { vx = gelu_f(vx); vy = gelu_f(vy); }
                if (res) {
                    const float2 r2 = *(const float2*)(res + (size_t)mr * N + n);
                    vx += r2.x; vy += r2.y;
                }
                if (Cf) {
                    float2 o; o.x = vx; o.y = vy;
                    *(float2*)(Cf + (size_t)mr * N + n) = o;
                } else {
                    *(__half2*)(Ch + (size_t)mr * N + n) = __floats2half2_rn(vx, vy);
                }
            }
        }
    }
}

// ---------------- fused transpose of ALL 10 weights + bias packing ----------------
struct TPArgs {
    const float* src[10];
    __half* dst[10];
    float scale[10];
    const float* rb[3];   // rq_b, rk_b, rv_b
    const float* cb[3];   // cq_b, ck_b, cv_b
    float* biasr;
    float* biasc;
    float row_scale, col_scale;
};
__global__ void transpose_all_kernel(TPArgs args) {
    __shared__ float tbuf[32][33];
    int bid = blockIdx.x;
    if (bid >= 9216) {   // bias packing: 2 blocks x 256 threads, 9 elems each
        int which = bid - 9216;  // 0 = row, 1 = col
        int tid = threadIdx.y * 32 + threadIdx.x;
        const float* const* src = which ? args.cb : args.rb;
        float* dst = which ? args.biasc : args.biasr;
        float qs = which ? args.col_scale : args.row_scale;
        for (int i = tid; i < 2304; i += 256) {
            int sec = i / 768, off = i % 768;
            float v = src[sec][off];
            if (sec == 0) v *= qs;
            dst[i] = v;
        }
        return;
    }
    int w, tx, ty, K, N;
    if (bid < 4608)      { w = bid / 576; int tt = bid % 576;  K = 768;  N = 768;  tx = tt % 24; ty = tt / 24; }
    else if (bid < 6912) { w = 8;         int tt = bid - 4608; K = 768;  N = 3072; tx = tt % 96; ty = tt / 96; }
    else                 { w = 9;         int tt = bid - 6912; K = 3072; N = 768;  tx = tt % 24; ty = tt / 24; }
    const float* in = args.src[w];
    __half* out = args.dst[w];
    float sc = args.scale[w];
    int x = tx * 32 + threadIdx.x;
    int y0 = ty * 32;
    #pragma unroll
    for (int i = threadIdx.y; i < 32; i += 8)
        tbuf[i][threadIdx.x] = in[(size_t)(y0 + i) * N + x];
    __syncthreads();
    int xo = ty * 32 + threadIdx.x;
    int yo0 = tx * 32;
    #pragma unroll
    for (int i = threadIdx.y; i < 32; i += 8)
        out[(size_t)(yo0 + i) * K + xo] = __float2half(tbuf[threadIdx.x][i] * sc);
}

// ---------------- layernorm: fp32 in, half out ----------------
__global__ void ln_kernel(const float* __restrict__ x, const float* __restrict__ s,
                          const float* __restrict__ b, __half* __restrict__ out) {
    __shared__ float red[256];
    int t = threadIdx.x;
    const float* xr = x + (size_t)blockIdx.x * EE;
    float v0 = xr[t], v1 = xr[t + 256], v2 = xr[t + 512];
    red[t] = v0 + v1 + v2;
    __syncthreads();
    for (int o = 128; o; o >>= 1) { if (t < o) red[t] += red[t + o]; __syncthreads(); }
    float mean = red[0] * (1.0f / EE);
    __syncthreads();
    float d0 = v0 - mean, d1 = v1 - mean, d2 = v2 - mean;
    red[t] = d0 * d0 + d1 * d1 + d2 * d2;
    __syncthreads();
    for (int o = 128; o; o >>= 1) { if (t < o) red[t] += red[t + o]; __syncthreads(); }
    float rstd = rsqrtf(red[0] * (1.0f / EE) + 1e-6f);
    __half* orow = out + (size_t)blockIdx.x * EE;
    orow[t      ] = __float2half(d0 * rstd * s[t      ] + b[t      ]);
    orow[t + 256] = __float2half(d1 * rstd * s[t + 256] + b[t + 256]);
    orow[t + 512] = __float2half(d2 * rstd * s[t + 512] + b[t + 512]);
}

// ================= tensor-core attention =================
#define AP 72   // smem pitch (halves) for 64-wide attention tiles

// ---- row scores: aw[h,i,j] = sum_{r,d} q.k ; CTA = 64i x 64j per head, r-loop ----
__global__ void __launch_bounds__(256) row_scores_mma(
    const __half* __restrict__ qkv, float* __restrict__ aw)
{
    __shared__ __half qs[2][64 * AP];
    __shared__ __half ks[2][64 * AP];
    int h = blockIdx.z;
    int i0 = blockIdx.y * 64, j0 = blockIdx.x * 64;
    int tid = threadIdx.x;
    int wid = tid >> 5, lane = tid & 31;
    int g = lane >> 2, t = lane & 3;
    int wm = wid & 3, wn = wid >> 2;     // 4(i) x 2(j); warp tile i16 x j32
    uint32_t qb[2] = { smem_to_u32(qs[0]), smem_to_u32(qs[1]) };
    uint32_t kb[2] = { smem_to_u32(ks[0]), smem_to_u32(ks[1]) };

    int l16 = lane & 15;
    uint32_t offA = (uint32_t)((wm * 16 + l16) * AP) * 2 + (uint32_t)(lane >> 4) * 16;
    int l8 = lane & 7;
    int bh = (lane >> 3) & 1, bg = lane >> 4;
    uint32_t offB[2];
    #pragma unroll
    for (int p = 0; p < 2; p++)
        offB[p] = (uint32_t)((wn * 32 + p * 16 + bg * 8 + l8) * AP) * 2 + (uint32_t)bh * 16;

    float acc[4][4];
    #pragma unroll
    for (int i = 0; i < 4; i++)
        #pragma unroll
        for (int c = 0; c < 4; c++) acc[i][c] = 0.f;

    int lrow = tid >> 2, lc8 = (tid & 3) * 16;

    #define LOADRS(r, b) do {                                                     \
        const __half* qr = qkv + (size_t)((r) * CC + i0 + lrow) * QLD + h * DD;    \
        const __half* kr = qkv + 768 + (size_t)((r) * CC + j0 + lrow) * QLD + h * DD; \
        cp_async16(qb[b] + (uint32_t)(lrow * AP + lc8) * 2,     qr + lc8);         \
        cp_async16(qb[b] + (uint32_t)(lrow * AP + lc8 + 8) * 2, qr + lc8 + 8);     \
        cp_async16(kb[b] + (uint32_t)(lrow * AP + lc8) * 2,     kr + lc8);         \
        cp_async16(kb[b] + (uint32_t)(lrow * AP + lc8 + 8) * 2, kr + lc8 + 8);     \
        CP_COMMIT();                                                               \
    } while (0)

    LOADRS(0, 0);
    for (int r = 0; r < RR; r++) {
        if (r + 1 < RR) { LOADRS(r + 1, (r + 1) & 1); CP_WAIT1(); } else CP_WAIT0();
        __syncthreads();
        int b = r & 1;
        #pragma unroll
        for (int ks_ = 0; ks_ < 4; ks_++) {
            uint32_t koff = (uint32_t)ks_ * 32;
            uint32_t af[4], bf0[4], bf1[4];
            ldsm_x4(af, qb[b] + offA + koff);
            ldsm_x4(bf0, kb[b] + offB[0] + koff);
            ldsm_x4(bf1, kb[b] + offB[1] + koff);
            mma_f16(acc[0], af, bf0[0], bf0[1]);
            mma_f16(acc[1], af, bf0[2], bf0[3]);
            mma_f16(acc[2], af, bf1[0], bf1[1]);
            mma_f16(acc[3], af, bf1[2], bf1[3]);
        }
        __syncthreads();
    }
    #undef LOADRS

    size_t base = (size_t)h * CC * CC;
    #pragma unroll
    for (int nt = 0; nt < 4; nt++) {
        int n = j0 + wn * 32 + (nt >> 1) * 16 + (nt & 1) * 8 + 2 * t;
        #pragma unroll
        for (int hf = 0; hf < 2; hf++) {
            int m = i0 + wm * 16 + g + hf * 8;
            float2 o; o.x = acc[nt][hf * 2]; o.y = acc[nt][hf * 2 + 1];
            *(float2*)(aw + base + (size_t)m * CC + n) = o;
        }
    }
}

// ---- col scores: one CTA per (h,c), 64x64x64 ----
__global__ void __launch_bounds__(256) col_scores_mma(
    const __half* __restrict__ qkv, float* __restrict__ aw)
{
    __shared__ __half qs[64 * AP];
    __shared__ __half ks[64 * AP];
    int c = blockIdx.x, h = blockIdx.y;
    int tid = threadIdx.x;
    int wid = tid >> 5, lane = tid & 31;
    int g = lane >> 2, t = lane & 3;
    int wm = wid & 3, wn = wid >> 2;
    uint32_t qb = smem_to_u32(qs), kb = smem_to_u32(ks);

    int lrow = tid >> 2, lc8 = (tid & 3) * 16;
    {
        const __half* qr = qkv + (size_t)(lrow * CC + c) * QLD + h * DD;
        const __half* kr = qkv + 768 + (size_t)(lrow * CC + c) * QLD + h * DD;
        cp_async16(qb + (uint32_t)(lrow * AP + lc8) * 2,     qr + lc8);
        cp_async16(qb + (uint32_t)(lrow * AP + lc8 + 8) * 2, qr + lc8 + 8);
        cp_async16(kb + (uint32_t)(lrow * AP + lc8) * 2,     kr + lc8);
        cp_async16(kb + (uint32_t)(lrow * AP + lc8 + 8) * 2, kr + lc8 + 8);
        CP_COMMIT(); CP_WAIT0();
    }
    __syncthreads();

    int l16 = lane & 15;
    uint32_t offA = (uint32_t)((wm * 16 + l16) * AP) * 2 + (uint32_t)(lane >> 4) * 16;
    int l8 = lane & 7;
    int bh = (lane >> 3) & 1, bg = lane >> 4;
    uint32_t offB[2];
    #pragma unroll
    for (int p = 0; p < 2; p++)
        offB[p] = (uint32_t)((wn * 32 + p * 16 + bg * 8 + l8) * AP) * 2 + (uint32_t)bh * 16;

    float acc[4][4];
    #pragma unroll
    for (int i = 0; i < 4; i++)
        #pragma unroll
        for (int cc2 = 0; cc2 < 4; cc2++) acc[i][cc2] = 0.f;

    #pragma unroll
    for (int ks_ = 0; ks_ < 4; ks_++) {
        uint32_t koff = (uint32_t)ks_ * 32;
        uint32_t af[4], bf0[4], bf1[4];
        ldsm_x4(af, qb + offA + koff);
        ldsm_x4(bf0, kb + offB[0] + koff);
        ldsm_x4(bf1, kb + offB[1] + koff);
        mma_f16(acc[0], af, bf0[0], bf0[1]);
        mma_f16(acc[1], af, bf0[2], bf0[3]);
        mma_f16(acc[2], af, bf1[0], bf1[1]);
        mma_f16(acc[3], af, bf1[2], bf1[3]);
    }

    size_t base = ((size_t)h * CC + c) * RR * RR;
    #pragma unroll
    for (int nt = 0; nt < 4; nt++) {
        int n = wn * 32 + (nt >> 1) * 16 + (nt & 1) * 8 + 2 * t;
        #pragma unroll
        for (int hf = 0; hf < 2; hf++) {
            int m = wm * 16 + g + hf * 8;
            float2 o; o.x = acc[nt][hf * 2]; o.y = acc[nt][hf * 2 + 1];
            *(float2*)(aw + base + (size_t)m * RR + n) = o;
        }
    }
}

// ---- softmax 256-wide, writes HALF in-place ----
__global__ void softmax256_kernel(float* __restrict__ p) {
    __shared__ float red[256];
    int t = threadIdx.x;
    float* pr = p + (size_t)blockIdx.x * 256;
    float v = pr[t];
    red[t] = v;
    __syncthreads();
    for (int o = 128; o; o >>= 1) { if (t < o) red[t] = fmaxf(red[t], red[t + o]); __syncthreads(); }
    float mx = red[0];
    __syncthreads();
    float e = expf(v - mx);
    red[t] = e;
    __syncthreads();
    for (int o = 128; o; o >>= 1) { if (t < o) red[t] += red[t + o]; __syncthreads(); }
    float inv = 1.0f / red[0];
    __syncthreads();
    ((__half*)pr)[t] = __float2half(e * inv);
}

// ---- softmax 64-wide (one warp per row), writes HALF in-place ----
__global__ void softmax64_kernel(float* __restrict__ p, int nrows) {
    int warp = (blockIdx.x * blockDim.x + threadIdx.x) >> 5;
    int lane = threadIdx.x & 31;
    if (warp >= nrows) return;
    float* pr = p + (size_t)warp * 64;
    float a = pr[lane], b = pr[lane + 32];
    float mx = fmaxf(a, b);
    #pragma unroll
    for (int o = 16; o; o >>= 1) mx = fmaxf(mx, __shfl_xor_sync(0xffffffffu, mx, o));
    a = expf(a - mx); b = expf(b - mx);
    float s = a + b;
    #pragma unroll
    for (int o = 16; o; o >>= 1) s += __shfl_xor_sync(0xffffffffu, s, o);
    float inv = 1.0f / s;
    __half* ph = (__half*)pr;
    ph[lane] = __float2half(a * inv); ph[lane + 32] = __float2half(b * inv);
}

// ---- row ctx: CTA = 128i x 64d per (h,r) ----
__global__ void __launch_bounds__(256) row_ctx_mma(
    const float* __restrict__ paw, const __half* __restrict__ qkv, __half* __restrict__ ctx)
{
    __shared__ __half ps[128 * AP];
    __shared__ __half vs[64 * AP];
    int i0 = blockIdx.x * 128;
    int r = blockIdx.y, h = blockIdx.z;
    int tid = threadIdx.x;
    int wid = tid >> 5, lane = tid & 31;
    int g = lane >> 2, t = lane & 3;
    int wm = wid & 3, wn = wid >> 2;
    uint32_t pb = smem_to_u32(ps), vb = smem_to_u32(vs);
    const __half* ph_g = (const __half*)paw;

    int l16 = lane & 15;
    uint32_t offA[2];
    #pragma unroll
    for (int mt = 0; mt < 2; mt++)
        offA[mt] = (uint32_t)((wm * 32 + mt * 16 + l16) * AP) * 2 + (uint32_t)(lane >> 4) * 16;
    int lr = lane & 7, sel = lane >> 3;
    uint32_t offBT[2];
    #pragma unroll
    for (int ng = 0; ng < 2; ng++)
        offBT[ng] = (uint32_t)(((sel & 1) * 8 + lr) * AP) * 2
                  + (uint32_t)(wn * 32 + ng * 16 + (sel >> 1) * 8) * 2;

    float acc[2][4][4];
    #pragma unroll
    for (int i = 0; i < 2; i++)
        #pragma unroll
        for (int j = 0; j < 4; j++)
            #pragma unroll
            for (int c = 0; c < 4; c++) acc[i][j][c] = 0.f;

    int prow = tid >> 1, pc0 = (tid & 1) * 32;
    int vrow = tid >> 2, vc8 = (tid & 3) * 16;

    for (int jc = 0; jc < CC; jc += 64) {
        const __half* pg = ph_g + (size_t)h * 131072 + (size_t)(i0 + prow) * 512 + jc;
        #pragma unroll
        for (int q = 0; q < 4; q++)
            cp_async16(pb + (uint32_t)(prow * AP + pc0 + q * 8) * 2, pg + pc0 + q * 8);
        const __half* vg = qkv + 1536 + (size_t)(r * CC + jc + vrow) * QLD + h * DD;
        cp_async16(vb + (uint32_t)(vrow * AP + vc8) * 2,     vg + vc8);
        cp_async16(vb + (uint32_t)(vrow * AP + vc8 + 8) * 2, vg + vc8 + 8);
        CP_COMMIT(); CP_WAIT0();
        __syncthreads();

        #pragma unroll
        for (int ks_ = 0; ks_ < 4; ks_++) {
            uint32_t koffA = (uint32_t)ks_ * 32;
            uint32_t koffB = (uint32_t)(ks_ * 16 * AP) * 2;
            uint32_t af[2][4], bt0[4], bt1[4];
            ldsm_x4(af[0], pb + offA[0] + koffA);
            ldsm_x4(af[1], pb + offA[1] + koffA);
            ldsm_x4_t(bt0, vb + offBT[0] + koffB);
            ldsm_x4_t(bt1, vb + offBT[1] + koffB);
            #pragma unroll
            for (int mt = 0; mt < 2; mt++) {
                mma_f16(acc[mt][0], af[mt], bt0[0], bt0[1]);
                mma_f16(acc[mt][1], af[mt], bt0[2], bt0[3]);
                mma_f16(acc[mt][2], af[mt], bt1[0], bt1[1]);
                mma_f16(acc[mt][3], af[mt], bt1[2], bt1[3]);
            }
        }
        __syncthreads();
    }

    #pragma unroll
    for (int mt = 0; mt < 2; mt++) {
        #pragma unroll
        for (int nt = 0; nt < 4; nt++) {
            int d = h * DD + wn * 32 + (nt >> 1) * 16 + (nt & 1) * 8 + 2 * t;
            #pragma unroll
            for (int hf = 0; hf < 2; hf++) {
                int m = i0 + wm * 32 + mt * 16 + g + hf * 8;
                *(__half2*)(ctx + (size_t)(r * CC + m) * EE + d) =
                    __floats2half2_rn(acc[mt][nt][hf * 2], acc[mt][nt][hf * 2 + 1]);
            }
        }
    }
}

// ---- col ctx: one CTA per (h,c) ----
__global__ void __launch_bounds__(256) col_ctx_mma(
    const float* __restrict__ paw, const __half* __restrict__ qkv, __half* __restrict__ ctx)
{
    __shared__ __half ps[64 * AP];
    __shared__ __half vs[64 * AP];
    int c = blockIdx.x, h = blockIdx.y;
    int tid = threadIdx.x;
    int wid = tid >> 5, lane = tid & 31;
    int g = lane >> 2, t = lane & 3;
    int wm = wid & 3, wn = wid >> 2;
    uint32_t pb = smem_to_u32(ps), vb = smem_to_u32(vs);
    const __half* ph_g = (const __half*)paw;

    int lrow = tid >> 2, lc8 = (tid & 3) * 16;
    {
        const __half* pg = ph_g + (((size_t)h * CC + c) * 4096 + (size_t)lrow * 64) * 2;
        cp_async16(pb + (uint32_t)(lrow * AP + lc8) * 2,     pg + lc8);
        cp_async16(pb + (uint32_t)(lrow * AP + lc8 + 8) * 2, pg + lc8 + 8);
        const __half* vg = qkv + 1536 + (size_t)(lrow * CC + c) * QLD + h * DD;
        cp_async16(vb + (uint32_t)(lrow * AP + lc8) * 2,     vg + lc8);
        cp_async16(vb + (uint32_t)(lrow * AP + lc8 + 8) * 2, vg + lc8 + 8);
        CP_COMMIT(); CP_WAIT0();
    }
    __syncthreads();

    int l16 = lane & 15;
    uint32_t offA = (uint32_t)((wm * 16 + l16) * AP) * 2 + (uint32_t)(lane >> 4) * 16;
    int lr = lane & 7, sel = lane >> 3;
    uint32_t offBT[2];
    #pragma unroll
    for (int ng = 0; ng < 2; ng++)
        offBT[ng] = (uint32_t)(((sel & 1) * 8 + lr) * AP) * 2
                  + (uint32_t)(wn * 32 + ng * 16 + (sel >> 1) * 8) * 2;

    float acc[4][4];
    #pragma unroll
    for (int i = 0; i < 4; i++)
        #pragma unroll
        for (int cc2 = 0; cc2 < 4; cc2++) acc[i][cc2] = 0.f;

    #pragma unroll
    for (int ks_ = 0; ks_ < 4; ks_++) {
        uint32_t koffA = (uint32_t)ks_ * 32;
        uint32_t koffB = (uint32_t)(ks_ * 16 * AP) * 2;
        uint32_t af[4], bt0[4], bt1[4];
        ldsm_x4(af, pb + offA + koffA);
        ldsm_x4_t(bt0, vb + offBT[0] + koffB);
        ldsm_x4_t(bt1, vb + offBT[1] + koffB);
        mma_f16(acc[0], af, bt0[0], bt0[1]);
        mma_f16(acc[1], af, bt0[2], bt0[3]);
        mma_f16(acc[2], af, bt1[0], bt1[1]);
        mma_f16(acc[3], af, bt1[2], bt1[3]);
    }

    #pragma unroll
    for (int nt = 0; nt < 4; nt++) {
        int d = h * DD + wn * 32 + (nt >> 1) * 16 + (nt & 1) * 8 + 2 * t;
        #pragma unroll
        for (int hf = 0; hf < 2; hf++) {
            int m = wm * 16 + g + hf * 8;
            *(__half2*)(ctx + (size_t)(m * CC + c) * EE + d) =
                __floats2half2_rn(acc[nt][hf * 2], acc[nt][hf * 2 + 1]);
        }
    }
}

// ---------------- host driver ----------------
#define GEMM_SMEM (NSTAGE * 2 * TILE_H * 2)   // 81920 bytes

static void run_gemm(const __half* A, const __half* BT, const float* bias, const float* res,
                     float* Cf, __half* Ch, int M, int N, int K, int gelu) {
    dim3 grid(N / 128, M / 128);
    mma_gemm_f16<<<grid, 256, GEMM_SMEM>>>(A, BT, bias, res, Cf, Ch, M, N, K, gelu);
}

extern "C" void kernel_launch(void* const* d_in, const int* in_sizes, int n_in,
                              void* d_out, int out_size) {
    const float* x_in = (const float*)d_in[0];
    const float* rq_w = (const float*)d_in[1];  const float* rq_b = (const float*)d_in[2];
    const float* rk_w = (const float*)d_in[3];  const float* rk_b = (const float*)d_in[4];
    const float* rv_w = (const float*)d_in[5];  const float* rv_b = (const float*)d_in[6];
    const float* ro_w = (const float*)d_in[7];  const float* ro_b = (const float*)d_in[8];
    const float* cq_w = (const float*)d_in[9];  const float* cq_b = (const float*)d_in[10];
    const float* ck_w = (const float*)d_in[11]; const float* ck_b = (const float*)d_in[12];
    const float* cv_w = (const float*)d_in[13]; const float* cv_b = (const float*)d_in[14];
    const float* co_w = (const float*)d_in[15]; const float* co_b = (const float*)d_in[16];
    const float* f1_w = (const float*)d_in[17]; const float* f1_b = (const float*)d_in[18];
    const float* f2_w = (const float*)d_in[19]; const float* f2_b = (const float*)d_in[20];
    const float* ln1_s = (const float*)d_in[21]; const float* ln1_b = (const float*)d_in[22];
    const float* ln2_s = (const float*)d_in[23]; const float* ln2_b = (const float*)d_in[24];
    const float* ln3_s = (const float*)d_in[25]; const float* ln3_b = (const float*)d_in[26];

    float *px, *paw, *pbias;
    void *vh, *vctx, *vbig, *vwt;
    cudaGetSymbolAddress((void**)&px,    g_x);
    cudaGetSymbolAddress(&vh,    g_h);
    cudaGetSymbolAddress(&vctx,  g_ctx);
    cudaGetSymbolAddress((void**)&paw,   g_aw);
    cudaGetSymbolAddress(&vbig,  g_big);
    cudaGetSymbolAddress(&vwt,   g_wt);
    cudaGetSymbolAddress((void**)&pbias, g_bias);
    __half* ph    = (__half*)vh;
    __half* pctx  = (__half*)vctx;
    __half* pqkv  = (__half*)vbig;
    __half* pffn  = (__half*)vbig;
    __half* pwt   = (__half*)vwt;

    cudaFuncSetAttribute(mma_gemm_f16, cudaFuncAttributeMaxDynamicSharedMemorySize, GEMM_SMEM);

    const float row_scale = 0.015625f;
    const float col_scale = 0.125f;

    const size_t WEE = (size_t)EE * EE;
    __half* rqkvT = pwt;
    __half* roT   = pwt + 3 * WEE;
    __half* cqkvT = pwt + 4 * WEE;
    __half* coT   = pwt + 7 * WEE;
    __half* f1T   = pwt + 8 * WEE;
    __half* f2T   = f1T + (size_t)EE * FF;
    float* biasr = pbias;
    float* biasc = pbias + 2304;

    // launch 1: all weight transposes + bias packing
    {
        TPArgs a;
        a.src[0] = rq_w; a.dst[0] = pwt + 0 * WEE; a.scale[0] = row_scale;
        a.src[1] = rk_w; a.dst[1] = pwt + 1 * WEE; a.scale[1] = 1.f;
        a.src[2] = rv_w; a.dst[2] = pwt + 2 * WEE; a.scale[2] = 1.f;
        a.src[3] = ro_w; a.dst[3] = roT;           a.scale[3] = 1.f;
        a.src[4] = cq_w; a.dst[4] = pwt + 4 * WEE; a.scale[4] = col_scale;
        a.src[5] = ck_w; a.dst[5] = pwt + 5 * WEE; a.scale[5] = 1.f;
        a.src[6] = cv_w; a.dst[6] = pwt + 6 * WEE; a.scale[6] = 1.f;
        a.src[7] = co_w; a.dst[7] = coT;           a.scale[7] = 1.f;
        a.src[8] = f1_w; a.dst[8] = f1T;           a.scale[8] = 1.f;
        a.src[9] = f2_w; a.dst[9] = f2T;           a.scale[9] = 1.f;
        a.rb[0] = rq_b; a.rb[1] = rk_b; a.rb[2] = rv_b;
        a.cb[0] = cq_b; a.cb[1] = ck_b; a.cb[2] = cv_b;
        a.biasr = biasr; a.biasc = biasc;
        a.row_scale = row_scale; a.col_scale = col_scale;
        dim3 b(32, 8);
        transpose_all_kernel<<<9218, b>>>(a);
    }

    // ===== row attention (ln1 reads x_in; residual fused via res=x_in) =====
    ln_kernel<<<MM, 256>>>(x_in, ln1_s, ln1_b, ph);
    run_gemm(ph, rqkvT, biasr, nullptr, nullptr, pqkv, MM, QLD, EE, 0);
    { dim3 g(4, 4, HH); row_scores_mma<<<g, 256>>>(pqkv, paw); }
    softmax256_kernel<<<HH * CC, 256>>>(paw);
    { dim3 g(2, RR, HH); row_ctx_mma<<<g, 256>>>(paw, pqkv, pctx); }
    run_gemm(pctx, roT, ro_b, x_in, px, nullptr, MM, EE, EE, 0);   // px = x_in + ctx@ro

    // ===== column attention =====
    ln_kernel<<<MM, 256>>>(px, ln2_s, ln2_b, ph);
    run_gemm(ph, cqkvT, biasc, nullptr, nullptr, pqkv, MM, QLD, EE, 0);
    { dim3 g(CC, HH); col_scores_mma<<<g, 256>>>(pqkv, paw); }
    { int nrows = HH * CC * RR; softmax64_kernel<<<(nrows * 32 + 255) / 256, 256>>>(paw, nrows); }
    { dim3 g(CC, HH); col_ctx_mma<<<g, 256>>>(paw, pqkv, pctx); }
    run_gemm(pctx, coT, co_b, px, px, nullptr, MM, EE, EE, 0);

    // ===== FFN =====
    ln_kernel<<<MM, 256>>>(px, ln3_s, ln3_b, ph);
    run_gemm(ph, f1T, f1_b, nullptr, nullptr, pffn, MM, FF, EE, 1);
    run_gemm(pffn, f2T, f2_b, px, (float*)d_out, nullptr, MM, EE, FF, 0);
}

// round 10
// speedup vs baseline: 1.0327x; 1.0327x over previous
#include <cuda_runtime.h>
#include <cuda_fp16.h>
#include <math.h>
#include <stdint.h>

// ---------------- problem constants ----------------
#define RR 64
#define CC 256
#define EE 768
#define HH 12
#define DD 64
#define FF 3072
#define MM (RR*CC)          // 16384 tokens
#define QLD 2304            // packed qkv row stride (halves)
#define PHSZ (HH*CC*CC)     // one row-scores partial: 786432 floats

// ---------------- scratch (device globals; no allocation allowed) ----------------
__device__ float g_x   [MM*EE];       // residual stream (fp32)
__device__ float g_h   [MM*EE];       // reused as __half
__device__ float g_ctx [MM*EE];       // reused as __half
__device__ float g_aw  [HH*CC*RR*RR]; // fp32 scores / 4 row-score partials (half p in-place post-softmax)
__device__ float g_big [MM*FF];       // reused: qkv (half) / ffn h1 (half)
__device__ float g_wt  [9437184/2 + 64];  // transposed half weights
__device__ float g_bias[4608];        // packed row/col qkv biases

// ---------------- helpers ----------------
__device__ __forceinline__ uint32_t smem_to_u32(const void* p) {
    uint32_t a;
    asm("{ .reg .u64 t; cvta.to.shared.u64 t, %1; cvt.u32.u64 %0, t; }" : "=r"(a) : "l"(p));
    return a;
}
__device__ __forceinline__ void cp_async16(uint32_t saddr, const void* gptr) {
    asm volatile("cp.async.cg.shared.global [%0], [%1], 16;" :: "r"(saddr), "l"(gptr));
}
#define CP_COMMIT() asm volatile("cp.async.commit_group;" ::: "memory")
#define CP_WAIT1()  asm volatile("cp.async.wait_group 1;" ::: "memory")
#define CP_WAIT0()  asm volatile("cp.async.wait_group 0;" ::: "memory")

__device__ __forceinline__ void ldsm_x4(uint32_t* r, uint32_t addr) {
    asm volatile("ldmatrix.sync.aligned.m8n8.x4.shared.b16 {%0,%1,%2,%3}, [%4];"
        : "=r"(r[0]), "=r"(r[1]), "=r"(r[2]), "=r"(r[3]) : "r"(addr));
}
__device__ __forceinline__ void ldsm_x4_t(uint32_t* r, uint32_t addr) {
    asm volatile("ldmatrix.sync.aligned.m8n8.x4.trans.shared.b16 {%0,%1,%2,%3}, [%4];"
        : "=r"(r[0]), "=r"(r[1]), "=r"(r[2]), "=r"(r[3]) : "r"(addr));
}

__device__ __forceinline__ void mma_f16(float* d, const uint32_t* a, uint32_t b0, uint32_t b1) {
    asm volatile("mma.sync.aligned.m16n8k16.row.col.f32.f16.f16.f32 "
        "{%0,%1,%2,%3}, {%4,%5,%6,%7}, {%8,%9}, {%0,%1,%2,%3};"
        : "+f"(d[0]), "+f"(d[1]), "+f"(d[2]), "+f"(d[3])
        : "r"(a[0]), "r"(a[1]), "r"(a[2]), "r"(a[3]), "r"(b0), "r"(b1));
}

// ---------------- gelu (tanh approx) ----------------
__device__ __forceinline__ float gelu_f(float x) {
    float x3 = x * x * x;
    return 0.5f * x * (1.0f + tanhf(0.7978845608028654f * (x + 0.044715f * x3)));
}

// ---------------- fp16 mma.sync GEMM: 128x128 tile, 8 warps (4m x 2n), warp 32x64 ----------------
#define BKH 32
#define PITCH_H 40
#define TILE_H (128 * PITCH_H)
#define NSTAGE 4

__global__ void __launch_bounds__(256, 2) mma_gemm_f16(
    const __half* __restrict__ A, const __half* __restrict__ BT,
    const float* __restrict__ bias, const float* __restrict__ res,
    float* __restrict__ Cf, __half* __restrict__ Ch,
    int M, int N, int K, int act_gelu)
{
    extern __shared__ __half smh[];
    uint32_t sbase = smem_to_u32(smh);
    uint32_t AbufU[NSTAGE], BbufU[NSTAGE];
    #pragma unroll
    for (int s = 0; s < NSTAGE; s++) {
        AbufU[s] = sbase + (uint32_t)(2 * s    ) * TILE_H * 2;
        BbufU[s] = sbase + (uint32_t)(2 * s + 1) * TILE_H * 2;
    }

    int tid = threadIdx.x;
    int wid = tid >> 5, lane = tid & 31;
    int g = lane >> 2, t = lane & 3;
    int wm = wid & 3, wn = wid >> 2;
    int m0 = blockIdx.y * 128, n0 = blockIdx.x * 128;

    int l16 = lane & 15;
    uint32_t a_koff = (uint32_t)(lane >> 4) * 16;
    uint32_t offA[2];
    #pragma unroll
    for (int mt = 0; mt < 2; mt++)
        offA[mt] = (uint32_t)((wm * 32 + mt * 16 + l16) * PITCH_H) * 2 + a_koff;
    int l8 = lane & 7;
    int b_half16 = (lane >> 3) & 1;
    int b_grp8 = lane >> 4;
    uint32_t offB[4];
    #pragma unroll
    for (int p = 0; p < 4; p++)
        offB[p] = (uint32_t)((wn * 64 + p * 16 + b_grp8 * 8 + l8) * PITCH_H) * 2 + (uint32_t)b_half16 * 16;

    float acc[2][8][4];
    #pragma unroll
    for (int i = 0; i < 2; i++)
        #pragma unroll
        for (int j = 0; j < 8; j++)
            #pragma unroll
            for (int c = 0; c < 4; c++) acc[i][j][c] = 0.f;

    const int NT = K / BKH;

    #define PREFETCH(kt, b) do {                                               \
        int k0p = (kt) * BKH;                                                  \
        _Pragma("unroll")                                                      \
        for (int i = 0; i < 2; i++) {                                          \
            int idx = i * 256 + tid;                                           \
            int row = idx >> 2, c8 = (idx & 3) * 8;                            \
            cp_async16(AbufU[b] + (uint32_t)(row * PITCH_H + c8) * 2,          \
                       A  + (size_t)(m0 + row) * K + k0p + c8);                \
            cp_async16(BbufU[b] + (uint32_t)(row * PITCH_H + c8) * 2,          \
                       BT + (size_t)(n0 + row) * K + k0p + c8);                \
        }                                                                      \
        CP_COMMIT();                                                           \
    } while (0)

    PREFETCH(0, 0);
    if (NT > 1) PREFETCH(1, 1);

    for (int kt = 0; kt < NT; kt++) {
        int b = kt % NSTAGE;
        if (kt + 1 < NT) CP_WAIT1(); else CP_WAIT0();
        __syncthreads();
        if (kt + 2 < NT) PREFETCH(kt + 2, (kt + 2) % NSTAGE);

        uint32_t Ab = AbufU[b], Bb = BbufU[b];
        #pragma unroll
        for (int ks = 0; ks < 2; ks++) {
            uint32_t koff = (uint32_t)ks * 32;
            uint32_t af[2][4], bfr[4][4];
            ldsm_x4(af[0], Ab + offA[0] + koff);
            ldsm_x4(af[1], Ab + offA[1] + koff);
            #pragma unroll
            for (int p = 0; p < 4; p++)
                ldsm_x4(bfr[p], Bb + offB[p] + koff);
            #pragma unroll
            for (int mt = 0; mt < 2; mt++)
                #pragma unroll
                for (int p = 0; p < 4; p++) {
                    mma_f16(acc[mt][2 * p    ], af[mt], bfr[p][0], bfr[p][1]);
                    mma_f16(acc[mt][2 * p + 1], af[mt], bfr[p][2], bfr[p][3]);
                }
        }
        __syncthreads();
    }
    #undef PREFETCH

    #pragma unroll
    for (int mt = 0; mt < 2; mt++) {
        #pragma unroll
        for (int nt = 0; nt < 8; nt++) {
            int m = m0 + wm * 32 + mt * 16 + g;
            int n = n0 + wn * 64 + nt * 8 + 2 * t;
            float bx = bias[n], by = bias[n + 1];
            #pragma unroll
            for (int half = 0; half < 2; half++) {
                int mr = m + half * 8;
                float vx = acc[mt][nt][half * 2 + 0] + bx;
                float vy = acc[mt][nt][half * 2 + 1] + by;
                if (act_gelu) { vx = gelu_f(vx); vy = gelu_f(vy); }
                if (res) {
                    const float2 r2 = *(const float2*)(res + (size_t)mr * N + n);
                    vx += r2.x; vy += r2.y;
                }
                if (Cf) {
                    float2 o; o.x = vx; o.y = vy;
                    *(float2*)(Cf + (size_t)mr * N + n) = o;
                } else {
                    *(__half2*)(Ch + (size_t)mr * N + n) = __floats2half2_rn(vx, vy);
                }
            }
        }
    }
}

// ---------------- fused transpose of ALL 10 weights + bias packing ----------------
struct TPArgs {
    const float* src[10];
    __half* dst[10];
    float scale[10];
    const float* rb[3];
    const float* cb[3];
    float* biasr;
    float* biasc;
    float row_scale, col_scale;
};
__global__ void transpose_all_kernel(TPArgs args) {
    __shared__ float tbuf[32][33];
    int bid = blockIdx.x;
    if (bid >= 9216) {
        int which = bid - 9216;
        int tid = threadIdx.y * 32 + threadIdx.x;
        const float* const* src = which ? args.cb : args.rb;
        float* dst = which ? args.biasc : args.biasr;
        float qs = which ? args.col_scale : args.row_scale;
        for (int i = tid; i < 2304; i += 256) {
            int sec = i / 768, off = i % 768;
            float v = src[sec][off];
            if (sec == 0) v *= qs;
            dst[i] = v;
        }
        return;
    }
    int w, tx, ty, K, N;
    if (bid < 4608)      { w = bid / 576; int tt = bid % 576;  K = 768;  N = 768;  tx = tt % 24; ty = tt / 24; }
    else if (bid < 6912) { w = 8;         int tt = bid - 4608; K = 768;  N = 3072; tx = tt % 96; ty = tt / 96; }
    else                 { w = 9;         int tt = bid - 6912; K = 3072; N = 768;  tx = tt % 24; ty = tt / 24; }
    const float* in = args.src[w];
    __half* out = args.dst[w];
    float sc = args.scale[w];
    int x = tx * 32 + threadIdx.x;
    int y0 = ty * 32;
    #pragma unroll
    for (int i = threadIdx.y; i < 32; i += 8)
        tbuf[i][threadIdx.x] = in[(size_t)(y0 + i) * N + x];
    __syncthreads();
    int xo = ty * 32 + threadIdx.x;
    int yo0 = tx * 32;
    #pragma unroll
    for (int i = threadIdx.y; i < 32; i += 8)
        out[(size_t)(yo0 + i) * K + xo] = __float2half(tbuf[threadIdx.x][i] * sc);
}

// ---------------- layernorm: fp32 in, half out ----------------
__global__ void ln_kernel(const float* __restrict__ x, const float* __restrict__ s,
                          const float* __restrict__ b, __half* __restrict__ out) {
    __shared__ float red[256];
    int t = threadIdx.x;
    const float* xr = x + (size_t)blockIdx.x * EE;
    float v0 = xr[t], v1 = xr[t + 256], v2 = xr[t + 512];
    red[t] = v0 + v1 + v2;
    __syncthreads();
    for (int o = 128; o; o >>= 1) { if (t < o) red[t] += red[t + o]; __syncthreads(); }
    float mean = red[0] * (1.0f / EE);
    __syncthreads();
    float d0 = v0 - mean, d1 = v1 - mean, d2 = v2 - mean;
    red[t] = d0 * d0 + d1 * d1 + d2 * d2;
    __syncthreads();
    for (int o = 128; o; o >>= 1) { if (t < o) red[t] += red[t + o]; __syncthreads(); }
    float rstd = rsqrtf(red[0] * (1.0f / EE) + 1e-6f);
    __half* orow = out + (size_t)blockIdx.x * EE;
    orow[t      ] = __float2half(d0 * rstd * s[t      ] + b[t      ]);
    orow[t + 256] = __float2half(d1 * rstd * s[t + 256] + b[t + 256]);
    orow[t + 512] = __float2half(d2 * rstd * s[t + 512] + b[t + 512]);
}

// ================= tensor-core attention =================
#define AP 72   // smem pitch (halves) for 64-wide attention tiles

// ---- row scores (split-r): partial[rc][h,i,j] = sum_{r in chunk rc} q.k ----
// CTA = 64i x 64j per (head, r-chunk); blockIdx.z = h * 4 + rc.
__global__ void __launch_bounds__(256) row_scores_mma(
    const __half* __restrict__ qkv, float* __restrict__ aw)
{
    __shared__ __half qs[2][64 * AP];
    __shared__ __half ks[2][64 * AP];
    int h = blockIdx.z >> 2;
    int rc = blockIdx.z & 3;
    int i0 = blockIdx.y * 64, j0 = blockIdx.x * 64;
    int tid = threadIdx.x;
    int wid = tid >> 5, lane = tid & 31;
    int g = lane >> 2, t = lane & 3;
    int wm = wid & 3, wn = wid >> 2;
    uint32_t qb[2] = { smem_to_u32(qs[0]), smem_to_u32(qs[1]) };
    uint32_t kb[2] = { smem_to_u32(ks[0]), smem_to_u32(ks[1]) };

    int l16 = lane & 15;
    uint32_t offA = (uint32_t)((wm * 16 + l16) * AP) * 2 + (uint32_t)(lane >> 4) * 16;
    int l8 = lane & 7;
    int bh = (lane >> 3) & 1, bg = lane >> 4;
    uint32_t offB[2];
    #pragma unroll
    for (int p = 0; p < 2; p++)
        offB[p] = (uint32_t)((wn * 32 + p * 16 + bg * 8 + l8) * AP) * 2 + (uint32_t)bh * 16;

    float acc[4][4];
    #pragma unroll
    for (int i = 0; i < 4; i++)
        #pragma unroll
        for (int c = 0; c < 4; c++) acc[i][c] = 0.f;

    int lrow = tid >> 2, lc8 = (tid & 3) * 16;
    int rbase = rc * 16;

    #define LOADRS(r, b) do {                                                     \
        const __half* qr = qkv + (size_t)((r) * CC + i0 + lrow) * QLD + h * DD;    \
        const __half* kr = qkv + 768 + (size_t)((r) * CC + j0 + lrow) * QLD + h * DD; \
        cp_async16(qb[b] + (uint32_t)(lrow * AP + lc8) * 2,     qr + lc8);         \
        cp_async16(qb[b] + (uint32_t)(lrow * AP + lc8 + 8) * 2, qr + lc8 + 8);     \
        cp_async16(kb[b] + (uint32_t)(lrow * AP + lc8) * 2,     kr + lc8);         \
        cp_async16(kb[b] + (uint32_t)(lrow * AP + lc8 + 8) * 2, kr + lc8 + 8);     \
        CP_COMMIT();                                                               \
    } while (0)

    LOADRS(rbase, 0);
    for (int rr = 0; rr < 16; rr++) {
        if (rr + 1 < 16) { LOADRS(rbase + rr + 1, (rr + 1) & 1); CP_WAIT1(); } else CP_WAIT0();
        __syncthreads();
        int b = rr & 1;
        #pragma unroll
        for (int ks_ = 0; ks_ < 4; ks_++) {
            uint32_t koff = (uint32_t)ks_ * 32;
            uint32_t af[4], bf0[4], bf1[4];
            ldsm_x4(af, qb[b] + offA + koff);
            ldsm_x4(bf0, kb[b] + offB[0] + koff);
            ldsm_x4(bf1, kb[b] + offB[1] + koff);
            mma_f16(acc[0], af, bf0[0], bf0[1]);
            mma_f16(acc[1], af, bf0[2], bf0[3]);
            mma_f16(acc[2], af, bf1[0], bf1[1]);
            mma_f16(acc[3], af, bf1[2], bf1[3]);
        }
        __syncthreads();
    }
    #undef LOADRS

    float* out = aw + (size_t)rc * PHSZ + (size_t)h * CC * CC;
    #pragma unroll
    for (int nt = 0; nt < 4; nt++) {
        int n = j0 + wn * 32 + (nt >> 1) * 16 + (nt & 1) * 8 + 2 * t;
        #pragma unroll
        for (int hf = 0; hf < 2; hf++) {
            int m = i0 + wm * 16 + g + hf * 8;
            float2 o; o.x = acc[nt][hf * 2]; o.y = acc[nt][hf * 2 + 1];
            *(float2*)(out + (size_t)m * CC + n) = o;
        }
    }
}

// ---- col scores: one CTA per (h,c), 64x64x64 ----
__global__ void __launch_bounds__(256) col_scores_mma(
    const __half* __restrict__ qkv, float* __restrict__ aw)
{
    __shared__ __half qs[64 * AP];
    __shared__ __half ks[64 * AP];
    int c = blockIdx.x, h = blockIdx.y;
    int tid = threadIdx.x;
    int wid = tid >> 5, lane = tid & 31;
    int g = lane >> 2, t = lane & 3;
    int wm = wid & 3, wn = wid >> 2;
    uint32_t qb = smem_to_u32(qs), kb = smem_to_u32(ks);

    int lrow = tid >> 2, lc8 = (tid & 3) * 16;
    {
        const __half* qr = qkv + (size_t)(lrow * CC + c) * QLD + h * DD;
        const __half* kr = qkv + 768 + (size_t)(lrow * CC + c) * QLD + h * DD;
        cp_async16(qb + (uint32_t)(lrow * AP + lc8) * 2,     qr + lc8);
        cp_async16(qb + (uint32_t)(lrow * AP + lc8 + 8) * 2, qr + lc8 + 8);
        cp_async16(kb + (uint32_t)(lrow * AP + lc8) * 2,     kr + lc8);
        cp_async16(kb + (uint32_t)(lrow * AP + lc8 + 8) * 2, kr + lc8 + 8);
        CP_COMMIT(); CP_WAIT0();
    }
    __syncthreads();

    int l16 = lane & 15;
    uint32_t offA = (uint32_t)((wm * 16 + l16) * AP) * 2 + (uint32_t)(lane >> 4) * 16;
    int l8 = lane & 7;
    int bh = (lane >> 3) & 1, bg = lane >> 4;
    uint32_t offB[2];
    #pragma unroll
    for (int p = 0; p < 2; p++)
        offB[p] = (uint32_t)((wn * 32 + p * 16 + bg * 8 + l8) * AP) * 2 + (uint32_t)bh * 16;

    float acc[4][4];
    #pragma unroll
    for (int i = 0; i < 4; i++)
        #pragma unroll
        for (int cc2 = 0; cc2 < 4; cc2++) acc[i][cc2] = 0.f;

    #pragma unroll
    for (int ks_ = 0; ks_ < 4; ks_++) {
        uint32_t koff = (uint32_t)ks_ * 32;
        uint32_t af[4], bf0[4], bf1[4];
        ldsm_x4(af, qb + offA + koff);
        ldsm_x4(bf0, kb + offB[0] + koff);
        ldsm_x4(bf1, kb + offB[1] + koff);
        mma_f16(acc[0], af, bf0[0], bf0[1]);
        mma_f16(acc[1], af, bf0[2], bf0[3]);
        mma_f16(acc[2], af, bf1[0], bf1[1]);
        mma_f16(acc[3], af, bf1[2], bf1[3]);
    }

    size_t base = ((size_t)h * CC + c) * RR * RR;
    #pragma unroll
    for (int nt = 0; nt < 4; nt++) {
        int n = wn * 32 + (nt >> 1) * 16 + (nt & 1) * 8 + 2 * t;
        #pragma unroll
        for (int hf = 0; hf < 2; hf++) {
            int m = wm * 16 + g + hf * 8;
            float2 o; o.x = acc[nt][hf * 2]; o.y = acc[nt][hf * 2 + 1];
            *(float2*)(aw + base + (size_t)m * RR + n) = o;
        }
    }
}

// ---- softmax 256-wide over summed partials; writes HALF in-place at partial 0 ----
__global__ void softmax256_kernel(float* __restrict__ p) {
    __shared__ float red[256];
    int t = threadIdx.x;
    float* pr = p + (size_t)blockIdx.x * 256;
    float v = pr[t] + pr[t + PHSZ] + pr[t + 2 * (size_t)PHSZ] + pr[t + 3 * (size_t)PHSZ];
    red[t] = v;
    __syncthreads();
    for (int o = 128; o; o >>= 1) { if (t < o) red[t] = fmaxf(red[t], red[t + o]); __syncthreads(); }
    float mx = red[0];
    __syncthreads();
    float e = expf(v - mx);
    red[t] = e;
    __syncthreads();
    for (int o = 128; o; o >>= 1) { if (t < o) red[t] += red[t + o]; __syncthreads(); }
    float inv = 1.0f / red[0];
    __syncthreads();
    ((__half*)pr)[t] = __float2half(e * inv);
}

// ---- softmax 64-wide (one warp per row), writes HALF in-place ----
__global__ void softmax64_kernel(float* __restrict__ p, int nrows) {
    int warp = (blockIdx.x * blockDim.x + threadIdx.x) >> 5;
    int lane = threadIdx.x & 31;
    if (warp >= nrows) return;
    float* pr = p + (size_t)warp * 64;
    float a = pr[lane], b = pr[lane + 32];
    float mx = fmaxf(a, b);
    #pragma unroll
    for (int o = 16; o; o >>= 1) mx = fmaxf(mx, __shfl_xor_sync(0xffffffffu, mx, o));
    a = expf(a - mx); b = expf(b - mx);
    float s = a + b;
    #pragma unroll
    for (int o = 16; o; o >>= 1) s += __shfl_xor_sync(0xffffffffu, s, o);
    float inv = 1.0f / s;
    __half* ph = (__half*)pr;
    ph[lane] = __float2half(a * inv); ph[lane + 32] = __float2half(b * inv);
}

// ---- row ctx: CTA = 128i x 64d per (h,r) ----
__global__ void __launch_bounds__(256) row_ctx_mma(
    const float* __restrict__ paw, const __half* __restrict__ qkv, __half* __restrict__ ctx)
{
    __shared__ __half ps[128 * AP];
    __shared__ __half vs[64 * AP];
    int i0 = blockIdx.x * 128;
    int r = blockIdx.y, h = blockIdx.z;
    int tid = threadIdx.x;
    int wid = tid >> 5, lane = tid & 31;
    int g = lane >> 2, t = lane & 3;
    int wm = wid & 3, wn = wid >> 2;
    uint32_t pb = smem_to_u32(ps), vb = smem_to_u32(vs);
    const __half* ph_g = (const __half*)paw;

    int l16 = lane & 15;
    uint32_t offA[2];
    #pragma unroll
    for (int mt = 0; mt < 2; mt++)
        offA[mt] = (uint32_t)((wm * 32 + mt * 16 + l16) * AP) * 2 + (uint32_t)(lane >> 4) * 16;
    int lr = lane & 7, sel = lane >> 3;
    uint32_t offBT[2];
    #pragma unroll
    for (int ng = 0; ng < 2; ng++)
        offBT[ng] = (uint32_t)(((sel & 1) * 8 + lr) * AP) * 2
                  + (uint32_t)(wn * 32 + ng * 16 + (sel >> 1) * 8) * 2;

    float acc[2][4][4];
    #pragma unroll
    for (int i = 0; i < 2; i++)
        #pragma unroll
        for (int j = 0; j < 4; j++)
            #pragma unroll
            for (int c = 0; c < 4; c++) acc[i][j][c] = 0.f;

    int prow = tid >> 1, pc0 = (tid & 1) * 32;
    int vrow = tid >> 2, vc8 = (tid & 3) * 16;

    for (int jc = 0; jc < CC; jc += 64) {
        const __half* pg = ph_g + (size_t)h * 131072 + (size_t)(i0 + prow) * 512 + jc;
        #pragma unroll
        for (int q = 0; q < 4; q++)
            cp_async16(pb + (uint32_t)(prow * AP + pc0 + q * 8) * 2, pg + pc0 + q * 8);
        const __half* vg = qkv + 1536 + (size_t)(r * CC + jc + vrow) * QLD + h * DD;
        cp_async16(vb + (uint32_t)(vrow * AP + vc8) * 2,     vg + vc8);
        cp_async16(vb + (uint32_t)(vrow * AP + vc8 + 8) * 2, vg + vc8 + 8);
        CP_COMMIT(); CP_WAIT0();
        __syncthreads();

        #pragma unroll
        for (int ks_ = 0; ks_ < 4; ks_++) {
            uint32_t koffA = (uint32_t)ks_ * 32;
            uint32_t koffB = (uint32_t)(ks_ * 16 * AP) * 2;
            uint32_t af[2][4], bt0[4], bt1[4];
            ldsm_x4(af[0], pb + offA[0] + koffA);
            ldsm_x4(af[1], pb + offA[1] + koffA);
            ldsm_x4_t(bt0, vb + offBT[0] + koffB);
            ldsm_x4_t(bt1, vb + offBT[1] + koffB);
            #pragma unroll
            for (int mt = 0; mt < 2; mt++) {
                mma_f16(acc[mt][0], af[mt], bt0[0], bt0[1]);
                mma_f16(acc[mt][1], af[mt], bt0[2], bt0[3]);
                mma_f16(acc[mt][2], af[mt], bt1[0], bt1[1]);
                mma_f16(acc[mt][3], af[mt], bt1[2], bt1[3]);
            }
        }
        __syncthreads();
    }

    #pragma unroll
    for (int mt = 0; mt < 2; mt++) {
        #pragma unroll
        for (int nt = 0; nt < 4; nt++) {
            int d = h * DD + wn * 32 + (nt >> 1) * 16 + (nt & 1) * 8 + 2 * t;
            #pragma unroll
            for (int hf = 0; hf < 2; hf++) {
                int m = i0 + wm * 32 + mt * 16 + g + hf * 8;
                *(__half2*)(ctx + (size_t)(r * CC + m) * EE + d) =
                    __floats2half2_rn(acc[mt][nt][hf * 2], acc[mt][nt][hf * 2 + 1]);
            }
        }
    }
}

// ---- col ctx: one CTA per (h,c) ----
__global__ void __launch_bounds__(256) col_ctx_mma(
    const float* __restrict__ paw, const __half* __restrict__ qkv, __half* __restrict__ ctx)
{
    __shared__ __half ps[64 * AP];
    __shared__ __half vs[64 * AP];
    int c = blockIdx.x, h = blockIdx.y;
    int tid = threadIdx.x;
    int wid = tid >> 5, lane = tid & 31;
    int g = lane >> 2, t = lane & 3;
    int wm = wid & 3, wn = wid >> 2;
    uint32_t pb = smem_to_u32(ps), vb = smem_to_u32(vs);
    const __half* ph_g = (const __half*)paw;

    int lrow = tid >> 2, lc8 = (tid & 3) * 16;
    {
        const __half* pg = ph_g + (((size_t)h * CC + c) * 4096 + (size_t)lrow * 64) * 2;
        cp_async16(pb + (uint32_t)(lrow * AP + lc8) * 2,     pg + lc8);
        cp_async16(pb + (uint32_t)(lrow * AP + lc8 + 8) * 2, pg + lc8 + 8);
        const __half* vg = qkv + 1536 + (size_t)(lrow * CC + c) * QLD + h * DD;
        cp_async16(vb + (uint32_t)(lrow * AP + lc8) * 2,     vg + lc8);
        cp_async16(vb + (uint32_t)(lrow * AP + lc8 + 8) * 2, vg + lc8 + 8);
        CP_COMMIT(); CP_WAIT0();
    }
    __syncthreads();

    int l16 = lane & 15;
    uint32_t offA = (uint32_t)((wm * 16 + l16) * AP) * 2 + (uint32_t)(lane >> 4) * 16;
    int lr = lane & 7, sel = lane >> 3;
    uint32_t offBT[2];
    #pragma unroll
    for (int ng = 0; ng < 2; ng++)
        offBT[ng] = (uint32_t)(((sel & 1) * 8 + lr) * AP) * 2
                  + (uint32_t)(wn * 32 + ng * 16 + (sel >> 1) * 8) * 2;

    float acc[4][4];
    #pragma unroll
    for (int i = 0; i < 4; i++)
        #pragma unroll
        for (int cc2 = 0; cc2 < 4; cc2++) acc[i][cc2] = 0.f;

    #pragma unroll
    for (int ks_ = 0; ks_ < 4; ks_++) {
        uint32_t koffA = (uint32_t)ks_ * 32;
        uint32_t koffB = (uint32_t)(ks_ * 16 * AP) * 2;
        uint32_t af[4], bt0[4], bt1[4];
        ldsm_x4(af, pb + offA + koffA);
        ldsm_x4_t(bt0, vb + offBT[0] + koffB);
        ldsm_x4_t(bt1, vb + offBT[1] + koffB);
        mma_f16(acc[0], af, bt0[0], bt0[1]);
        mma_f16(acc[1], af, bt0[2], bt0[3]);
        mma_f16(acc[2], af, bt1[0], bt1[1]);
        mma_f16(acc[3], af, bt1[2], bt1[3]);
    }

    #pragma unroll
    for (int nt = 0; nt < 4; nt++) {
        int d = h * DD + wn * 32 + (nt >> 1) * 16 + (nt & 1) * 8 + 2 * t;
        #pragma unroll
        for (int hf = 0; hf < 2; hf++) {
            int m = wm * 16 + g + hf * 8;
            *(__half2*)(ctx + (size_t)(m * CC + c) * EE + d) =
                __floats2half2_rn(acc[nt][hf * 2], acc[nt][hf * 2 + 1]);
        }
    }
}

// ---------------- host driver ----------------
#define GEMM_SMEM (NSTAGE * 2 * TILE_H * 2)   // 81920 bytes

static void run_gemm(const __half* A, const __half* BT, const float* bias, const float* res,
                     float* Cf, __half* Ch, int M, int N, int K, int gelu) {
    dim3 grid(N / 128, M / 128);
    mma_gemm_f16<<<grid, 256, GEMM_SMEM>>>(A, BT, bias, res, Cf, Ch, M, N, K, gelu);
}

extern "C" void kernel_launch(void* const* d_in, const int* in_sizes, int n_in,
                              void* d_out, int out_size) {
    const float* x_in = (const float*)d_in[0];
    const float* rq_w = (const float*)d_in[1];  const float* rq_b = (const float*)d_in[2];
    const float* rk_w = (const float*)d_in[3];  const float* rk_b = (const float*)d_in[4];
    const float* rv_w = (const float*)d_in[5];  const float* rv_b = (const float*)d_in[6];
    const float* ro_w = (const float*)d_in[7];  const float* ro_b = (const float*)d_in[8];
    const float* cq_w = (const float*)d_in[9];  const float* cq_b = (const float*)d_in[10];
    const float* ck_w = (const float*)d_in[11]; const float* ck_b = (const float*)d_in[12];
    const float* cv_w = (const float*)d_in[13]; const float* cv_b = (const float*)d_in[14];
    const float* co_w = (const float*)d_in[15]; const float* co_b = (const float*)d_in[16];
    const float* f1_w = (const float*)d_in[17]; const float* f1_b = (const float*)d_in[18];
    const float* f2_w = (const float*)d_in[19]; const float* f2_b = (const float*)d_in[20];
    const float* ln1_s = (const float*)d_in[21]; const float* ln1_b = (const float*)d_in[22];
    const float* ln2_s = (const float*)d_in[23]; const float* ln2_b = (const float*)d_in[24];
    const float* ln3_s = (const float*)d_in[25]; const float* ln3_b = (const float*)d_in[26];

    float *px, *paw, *pbias;
    void *vh, *vctx, *vbig, *vwt;
    cudaGetSymbolAddress((void**)&px,    g_x);
    cudaGetSymbolAddress(&vh,    g_h);
    cudaGetSymbolAddress(&vctx,  g_ctx);
    cudaGetSymbolAddress((void**)&paw,   g_aw);
    cudaGetSymbolAddress(&vbig,  g_big);
    cudaGetSymbolAddress(&vwt,   g_wt);
    cudaGetSymbolAddress((void**)&pbias, g_bias);
    __half* ph    = (__half*)vh;
    __half* pctx  = (__half*)vctx;
    __half* pqkv  = (__half*)vbig;
    __half* pffn  = (__half*)vbig;
    __half* pwt   = (__half*)vwt;

    cudaFuncSetAttribute(mma_gemm_f16, cudaFuncAttributeMaxDynamicSharedMemorySize, GEMM_SMEM);

    const float row_scale = 0.015625f;
    const float col_scale = 0.125f;

    const size_t WEE = (size_t)EE * EE;
    __half* rqkvT = pwt;
    __half* roT   = pwt + 3 * WEE;
    __half* cqkvT = pwt + 4 * WEE;
    __half* coT   = pwt + 7 * WEE;
    __half* f1T   = pwt + 8 * WEE;
    __half* f2T   = f1T + (size_t)EE * FF;
    float* biasr = pbias;
    float* biasc = pbias + 2304;

    {
        TPArgs a;
        a.src[0] = rq_w; a.dst[0] = pwt + 0 * WEE; a.scale[0] = row_scale;
        a.src[1] = rk_w; a.dst[1] = pwt + 1 * WEE; a.scale[1] = 1.f;
        a.src[2] = rv_w; a.dst[2] = pwt + 2 * WEE; a.scale[2] = 1.f;
        a.src[3] = ro_w; a.dst[3] = roT;           a.scale[3] = 1.f;
        a.src[4] = cq_w; a.dst[4] = pwt + 4 * WEE; a.scale[4] = col_scale;
        a.src[5] = ck_w; a.dst[5] = pwt + 5 * WEE; a.scale[5] = 1.f;
        a.src[6] = cv_w; a.dst[6] = pwt + 6 * WEE; a.scale[6] = 1.f;
        a.src[7] = co_w; a.dst[7] = coT;           a.scale[7] = 1.f;
        a.src[8] = f1_w; a.dst[8] = f1T;           a.scale[8] = 1.f;
        a.src[9] = f2_w; a.dst[9] = f2T;           a.scale[9] = 1.f;
        a.rb[0] = rq_b; a.rb[1] = rk_b; a.rb[2] = rv_b;
        a.cb[0] = cq_b; a.cb[1] = ck_b; a.cb[2] = cv_b;
        a.biasr = biasr; a.biasc = biasc;
        a.row_scale = row_scale; a.col_scale = col_scale;
        dim3 b(32, 8);
        transpose_all_kernel<<<9218, b>>>(a);
    }

    // ===== row attention =====
    ln_kernel<<<MM, 256>>>(x_in, ln1_s, ln1_b, ph);
    run_gemm(ph, rqkvT, biasr, nullptr, nullptr, pqkv, MM, QLD, EE, 0);
    { dim3 g(4, 4, HH * 4); row_scores_mma<<<g, 256>>>(pqkv, paw); }   // split-r, 768 CTAs
    softmax256_kernel<<<HH * CC, 256>>>(paw);
    { dim3 g(2, RR, HH); row_ctx_mma<<<g, 256>>>(paw, pqkv, pctx); }
    run_gemm(pctx, roT, ro_b, x_in, px, nullptr, MM, EE, EE, 0);

    // ===== column attention =====
    ln_kernel<<<MM, 256>>>(px, ln2_s, ln2_b, ph);
    run_gemm(ph, cqkvT, biasc, nullptr, nullptr, pqkv, MM, QLD, EE, 0);
    { dim3 g(CC, HH); col_scores_mma<<<g, 256>>>(pqkv, paw); }
    { int nrows = HH * CC * RR; softmax64_kernel<<<(nrows * 32 + 255) / 256, 256>>>(paw, nrows); }
    { dim3 g(CC, HH); col_ctx_mma<<<g, 256>>>(paw, pqkv, pctx); }
    run_gemm(pctx, coT, co_b, px, px, nullptr, MM, EE, EE, 0);

    // ===== FFN =====
    ln_kernel<<<MM, 256>>>(px, ln3_s, ln3_b, ph);
    run_gemm(ph, f1T, f1_b, nullptr, nullptr, pffn, MM, FF, EE, 1);
    run_gemm(pffn, f2T, f2_b, px, (float*)d_out, nullptr, MM, EE, FF, 0);
}

// round 11
// speedup vs baseline: 1.0545x; 1.0211x over previous
#include <cuda_runtime.h>
#include <cuda_fp16.h>
#include <math.h>
#include <stdint.h>

// ---------------- problem constants ----------------
#define RR 64
#define CC 256
#define EE 768
#define HH 12
#define DD 64
#define FF 3072
#define MM (RR*CC)          // 16384 tokens
#define QLD 2304            // packed qkv row stride (halves)
#define PHSZ (HH*CC*CC)     // one row-scores partial: 786432 floats

// ---------------- scratch (device globals; no allocation allowed) ----------------
__device__ float g_x   [MM*EE];       // residual stream (fp32)
__device__ float g_h   [MM*EE];       // reused as __half
__device__ float g_ctx [MM*EE];       // reused as __half
__device__ float g_aw  [HH*CC*RR*RR]; // row-score partials (half p in-place post-softmax)
__device__ float g_big [MM*FF];       // reused: qkv (half) / ffn h1 (half)
__device__ float g_wt  [9437184/2 + 64];  // transposed half weights
__device__ float g_bias[4608];        // packed row/col qkv biases

// ---------------- helpers ----------------
__device__ __forceinline__ uint32_t smem_to_u32(const void* p) {
    uint32_t a;
    asm("{ .reg .u64 t; cvta.to.shared.u64 t, %1; cvt.u32.u64 %0, t; }" : "=r"(a) : "l"(p));
    return a;
}
__device__ __forceinline__ void cp_async16(uint32_t saddr, const void* gptr) {
    asm volatile("cp.async.cg.shared.global [%0], [%1], 16;" :: "r"(saddr), "l"(gptr));
}
#define CP_COMMIT() asm volatile("cp.async.commit_group;" ::: "memory")
#define CP_WAIT1()  asm volatile("cp.async.wait_group 1;" ::: "memory")
#define CP_WAIT0()  asm volatile("cp.async.wait_group 0;" ::: "memory")

__device__ __forceinline__ void ldsm_x4(uint32_t* r, uint32_t addr) {
    asm volatile("ldmatrix.sync.aligned.m8n8.x4.shared.b16 {%0,%1,%2,%3}, [%4];"
        : "=r"(r[0]), "=r"(r[1]), "=r"(r[2]), "=r"(r[3]) : "r"(addr));
}
__device__ __forceinline__ void ldsm_x4_t(uint32_t* r, uint32_t addr) {
    asm volatile("ldmatrix.sync.aligned.m8n8.x4.trans.shared.b16 {%0,%1,%2,%3}, [%4];"
        : "=r"(r[0]), "=r"(r[1]), "=r"(r[2]), "=r"(r[3]) : "r"(addr));
}

__device__ __forceinline__ void mma_f16(float* d, const uint32_t* a, uint32_t b0, uint32_t b1) {
    asm volatile("mma.sync.aligned.m16n8k16.row.col.f32.f16.f16.f32 "
        "{%0,%1,%2,%3}, {%4,%5,%6,%7}, {%8,%9}, {%0,%1,%2,%3};"
        : "+f"(d[0]), "+f"(d[1]), "+f"(d[2]), "+f"(d[3])
        : "r"(a[0]), "r"(a[1]), "r"(a[2]), "r"(a[3]), "r"(b0), "r"(b1));
}

// ---------------- gelu (tanh approx) ----------------
__device__ __forceinline__ float gelu_f(float x) {
    float x3 = x * x * x;
    return 0.5f * x * (1.0f + tanhf(0.7978845608028654f * (x + 0.044715f * x3)));
}

// ---------------- fp16 mma.sync GEMM: 128x128 tile, 8 warps (4m x 2n), warp 32x64 ----------------
#define BKH 32
#define PITCH_H 40
#define TILE_H (128 * PITCH_H)
#define NSTAGE 4

__global__ void __launch_bounds__(256, 2) mma_gemm_f16(
    const __half* __restrict__ A, const __half* __restrict__ BT,
    const float* __restrict__ bias, const float* __restrict__ res,
    float* __restrict__ Cf, __half* __restrict__ Ch,
    int M, int N, int K, int act_gelu)
{
    extern __shared__ __half smh[];
    uint32_t sbase = smem_to_u32(smh);
    uint32_t AbufU[NSTAGE], BbufU[NSTAGE];
    #pragma unroll
    for (int s = 0; s < NSTAGE; s++) {
        AbufU[s] = sbase + (uint32_t)(2 * s    ) * TILE_H * 2;
        BbufU[s] = sbase + (uint32_t)(2 * s + 1) * TILE_H * 2;
    }

    int tid = threadIdx.x;
    int wid = tid >> 5, lane = tid & 31;
    int g = lane >> 2, t = lane & 3;
    int wm = wid & 3, wn = wid >> 2;
    int m0 = blockIdx.y * 128, n0 = blockIdx.x * 128;

    int l16 = lane & 15;
    uint32_t a_koff = (uint32_t)(lane >> 4) * 16;
    uint32_t offA[2];
    #pragma unroll
    for (int mt = 0; mt < 2; mt++)
        offA[mt] = (uint32_t)((wm * 32 + mt * 16 + l16) * PITCH_H) * 2 + a_koff;
    int l8 = lane & 7;
    int b_half16 = (lane >> 3) & 1;
    int b_grp8 = lane >> 4;
    uint32_t offB[4];
    #pragma unroll
    for (int p = 0; p < 4; p++)
        offB[p] = (uint32_t)((wn * 64 + p * 16 + b_grp8 * 8 + l8) * PITCH_H) * 2 + (uint32_t)b_half16 * 16;

    float acc[2][8][4];
    #pragma unroll
    for (int i = 0; i < 2; i++)
        #pragma unroll
        for (int j = 0; j < 8; j++)
            #pragma unroll
            for (int c = 0; c < 4; c++) acc[i][j][c] = 0.f;

    const int NT = K / BKH;

    #define PREFETCH(kt, b) do {                                               \
        int k0p = (kt) * BKH;                                                  \
        _Pragma("unroll")                                                      \
        for (int i = 0; i < 2; i++) {                                          \
            int idx = i * 256 + tid;                                           \
            int row = idx >> 2, c8 = (idx & 3) * 8;                            \
            cp_async16(AbufU[b] + (uint32_t)(row * PITCH_H + c8) * 2,          \
                       A  + (size_t)(m0 + row) * K + k0p + c8);                \
            cp_async16(BbufU[b] + (uint32_t)(row * PITCH_H + c8) * 2,          \
                       BT + (size_t)(n0 + row) * K + k0p + c8);                \
        }                                                                      \
        CP_COMMIT();                                                           \
    } while (0)

    PREFETCH(0, 0);
    if (NT > 1) PREFETCH(1, 1);

    for (int kt = 0; kt < NT; kt++) {
        int b = kt % NSTAGE;
        if (kt + 1 < NT) CP_WAIT1(); else CP_WAIT0();
        __syncthreads();
        if (kt + 2 < NT) PREFETCH(kt + 2, (kt + 2) % NSTAGE);

        uint32_t Ab = AbufU[b], Bb = BbufU[b];
        #pragma unroll
        for (int ks = 0; ks < 2; ks++) {
            uint32_t koff = (uint32_t)ks * 32;
            uint32_t af[2][4], bfr[4][4];
            ldsm_x4(af[0], Ab + offA[0] + koff);
            ldsm_x4(af[1], Ab + offA[1] + koff);
            #pragma unroll
            for (int p = 0; p < 4; p++)
                ldsm_x4(bfr[p], Bb + offB[p] + koff);
            #pragma unroll
            for (int mt = 0; mt < 2; mt++)
                #pragma unroll
                for (int p = 0; p < 4; p++) {
                    mma_f16(acc[mt][2 * p    ], af[mt], bfr[p][0], bfr[p][1]);
                    mma_f16(acc[mt][2 * p + 1], af[mt], bfr[p][2], bfr[p][3]);
                }
        }
        __syncthreads();
    }
    #undef PREFETCH

    #pragma unroll
    for (int mt = 0; mt < 2; mt++) {
        #pragma unroll
        for (int nt = 0; nt < 8; nt++) {
            int m = m0 + wm * 32 + mt * 16 + g;
            int n = n0 + wn * 64 + nt * 8 + 2 * t;
            float bx = bias[n], by = bias[n + 1];
            #pragma unroll
            for (int half = 0; half < 2; half++) {
                int mr = m + half * 8;
                float vx = acc[mt][nt][half * 2 + 0] + bx;
                float vy = acc[mt][nt][half * 2 + 1] + by;
                if (act_gelu) { vx = gelu_f(vx); vy = gelu_f(vy); }
                if (res) {
                    const float2 r2 = *(const float2*)(res + (size_t)mr * N + n);
                    vx += r2.x; vy += r2.y;
                }
                if (Cf) {
                    float2 o; o.x = vx; o.y = vy;
                    *(float2*)(Cf + (size_t)mr * N + n) = o;
                } else {
                    *(__half2*)(Ch + (size_t)mr * N + n) = __floats2half2_rn(vx, vy);
                }
            }
        }
    }
}

// ---------------- fused transpose of ALL 10 weights + bias packing ----------------
struct TPArgs {
    const float* src[10];
    __half* dst[10];
    float scale[10];
    const float* rb[3];
    const float* cb[3];
    float* biasr;
    float* biasc;
    float row_scale, col_scale;
};
__global__ void transpose_all_kernel(TPArgs args) {
    __shared__ float tbuf[32][33];
    int bid = blockIdx.x;
    if (bid >= 9216) {
        int which = bid - 9216;
        int tid = threadIdx.y * 32 + threadIdx.x;
        const float* const* src = which ? args.cb : args.rb;
        float* dst = which ? args.biasc : args.biasr;
        float qs = which ? args.col_scale : args.row_scale;
        for (int i = tid; i < 2304; i += 256) {
            int sec = i / 768, off = i % 768;
            float v = src[sec][off];
            if (sec == 0) v *= qs;
            dst[i] = v;
        }
        return;
    }
    int w, tx, ty, K, N;
    if (bid < 4608)      { w = bid / 576; int tt = bid % 576;  K = 768;  N = 768;  tx = tt % 24; ty = tt / 24; }
    else if (bid < 6912) { w = 8;         int tt = bid - 4608; K = 768;  N = 3072; tx = tt % 96; ty = tt / 96; }
    else                 { w = 9;         int tt = bid - 6912; K = 3072; N = 768;  tx = tt % 24; ty = tt / 24; }
    const float* in = args.src[w];
    __half* out = args.dst[w];
    float sc = args.scale[w];
    int x = tx * 32 + threadIdx.x;
    int y0 = ty * 32;
    #pragma unroll
    for (int i = threadIdx.y; i < 32; i += 8)
        tbuf[i][threadIdx.x] = in[(size_t)(y0 + i) * N + x];
    __syncthreads();
    int xo = ty * 32 + threadIdx.x;
    int yo0 = tx * 32;
    #pragma unroll
    for (int i = threadIdx.y; i < 32; i += 8)
        out[(size_t)(yo0 + i) * K + xo] = __float2half(tbuf[threadIdx.x][i] * sc);
}

// ---------------- layernorm: fp32 in, half out ----------------
__global__ void ln_kernel(const float* __restrict__ x, const float* __restrict__ s,
                          const float* __restrict__ b, __half* __restrict__ out) {
    __shared__ float red[256];
    int t = threadIdx.x;
    const float* xr = x + (size_t)blockIdx.x * EE;
    float v0 = xr[t], v1 = xr[t + 256], v2 = xr[t + 512];
    red[t] = v0 + v1 + v2;
    __syncthreads();
    for (int o = 128; o; o >>= 1) { if (t < o) red[t] += red[t + o]; __syncthreads(); }
    float mean = red[0] * (1.0f / EE);
    __syncthreads();
    float d0 = v0 - mean, d1 = v1 - mean, d2 = v2 - mean;
    red[t] = d0 * d0 + d1 * d1 + d2 * d2;
    __syncthreads();
    for (int o = 128; o; o >>= 1) { if (t < o) red[t] += red[t + o]; __syncthreads(); }
    float rstd = rsqrtf(red[0] * (1.0f / EE) + 1e-6f);
    __half* orow = out + (size_t)blockIdx.x * EE;
    orow[t      ] = __float2half(d0 * rstd * s[t      ] + b[t      ]);
    orow[t + 256] = __float2half(d1 * rstd * s[t + 256] + b[t + 256]);
    orow[t + 512] = __float2half(d2 * rstd * s[t + 512] + b[t + 512]);
}

// ================= tensor-core attention =================
#define AP 72   // smem pitch (halves) for 64-wide attention tiles

// ---- row scores (split-r, wide j): partial[rc][h,i,j] over 64i x 128j tiles ----
// blockIdx: x = j0/128 (2), y = i0/64 (4), z = h*4 + rc (48)
__global__ void __launch_bounds__(256) row_scores_mma(
    const __half* __restrict__ qkv, float* __restrict__ aw)
{
    __shared__ __half qs[2][64 * AP];
    __shared__ __half ks[2][128 * AP];
    int h = blockIdx.z >> 2;
    int rc = blockIdx.z & 3;
    int i0 = blockIdx.y * 64, j0 = blockIdx.x * 128;
    int tid = threadIdx.x;
    int wid = tid >> 5, lane = tid & 31;
    int g = lane >> 2, t = lane & 3;
    int wm = wid & 3, wn = wid >> 2;     // 4(i16) x 2(j64)
    uint32_t qb[2] = { smem_to_u32(qs[0]), smem_to_u32(qs[1]) };
    uint32_t kb[2] = { smem_to_u32(ks[0]), smem_to_u32(ks[1]) };

    int l16 = lane & 15;
    uint32_t offA = (uint32_t)((wm * 16 + l16) * AP) * 2 + (uint32_t)(lane >> 4) * 16;
    int l8 = lane & 7;
    int bh = (lane >> 3) & 1, bg = lane >> 4;
    uint32_t offB[4];
    #pragma unroll
    for (int p = 0; p < 4; p++)
        offB[p] = (uint32_t)((wn * 64 + p * 16 + bg * 8 + l8) * AP) * 2 + (uint32_t)bh * 16;

    float acc[8][4];
    #pragma unroll
    for (int i = 0; i < 8; i++)
        #pragma unroll
        for (int c = 0; c < 4; c++) acc[i][c] = 0.f;

    int rbase = rc * 16;

    // per-r load: 64 q rows + 128 k rows, 8x16B chunks per row -> 1536 cp / 256 thr = 6 each
    #define LOADRS(r, b) do {                                                       \
        _Pragma("unroll")                                                           \
        for (int i = 0; i < 6; i++) {                                               \
            int idx = i * 256 + tid;                                                \
            int row = idx >> 3, c8 = (idx & 7) * 8;                                 \
            if (i < 2) {                                                            \
                cp_async16(qb[b] + (uint32_t)(row * AP + c8) * 2,                   \
                    qkv + (size_t)((r) * CC + i0 + row) * QLD + h * DD + c8);       \
            } else {                                                                \
                int krow = row - 64;                                                \
                cp_async16(kb[b] + (uint32_t)(krow * AP + c8) * 2,                  \
                    qkv + 768 + (size_t)((r) * CC + j0 + krow) * QLD + h * DD + c8);\
            }                                                                       \
        }                                                                           \
        CP_COMMIT();                                                                \
    } while (0)

    LOADRS(rbase, 0);
    for (int rr = 0; rr < 16; rr++) {
        if (rr + 1 < 16) { LOADRS(rbase + rr + 1, (rr + 1) & 1); CP_WAIT1(); } else CP_WAIT0();
        __syncthreads();
        int b = rr & 1;
        #pragma unroll
        for (int ks_ = 0; ks_ < 4; ks_++) {
            uint32_t koff = (uint32_t)ks_ * 32;
            uint32_t af[4], bfr[4][4];
            ldsm_x4(af, qb[b] + offA + koff);
            #pragma unroll
            for (int p = 0; p < 4; p++)
                ldsm_x4(bfr[p], kb[b] + offB[p] + koff);
            #pragma unroll
            for (int p = 0; p < 4; p++) {
                mma_f16(acc[2 * p    ], af, bfr[p][0], bfr[p][1]);
                mma_f16(acc[2 * p + 1], af, bfr[p][2], bfr[p][3]);
            }
        }
        __syncthreads();
    }
    #undef LOADRS

    float* out = aw + (size_t)rc * PHSZ + (size_t)h * CC * CC;
    #pragma unroll
    for (int nt = 0; nt < 8; nt++) {
        int n = j0 + wn * 64 + (nt >> 1) * 16 + (nt & 1) * 8 + 2 * t;
        #pragma unroll
        for (int hf = 0; hf < 2; hf++) {
            int m = i0 + wm * 16 + g + hf * 8;
            float2 o; o.x = acc[nt][hf * 2]; o.y = acc[nt][hf * 2 + 1];
            *(float2*)(out + (size_t)m * CC + n) = o;
        }
    }
}

// ---- softmax 256-wide over summed partials; writes HALF in-place at partial 0 ----
__global__ void softmax256_kernel(float* __restrict__ p) {
    __shared__ float red[256];
    int t = threadIdx.x;
    float* pr = p + (size_t)blockIdx.x * 256;
    float v = pr[t] + pr[t + PHSZ] + pr[t + 2 * (size_t)PHSZ] + pr[t + 3 * (size_t)PHSZ];
    red[t] = v;
    __syncthreads();
    for (int o = 128; o; o >>= 1) { if (t < o) red[t] = fmaxf(red[t], red[t + o]); __syncthreads(); }
    float mx = red[0];
    __syncthreads();
    float e = expf(v - mx);
    red[t] = e;
    __syncthreads();
    for (int o = 128; o; o >>= 1) { if (t < o) red[t] += red[t + o]; __syncthreads(); }
    float inv = 1.0f / red[0];
    __syncthreads();
    ((__half*)pr)[t] = __float2half(e * inv);
}

// ---- row ctx: CTA = 128i x 64d per (h,r) ----
__global__ void __launch_bounds__(256) row_ctx_mma(
    const float* __restrict__ paw, const __half* __restrict__ qkv, __half* __restrict__ ctx)
{
    __shared__ __half ps[128 * AP];
    __shared__ __half vs[64 * AP];
    int i0 = blockIdx.x * 128;
    int r = blockIdx.y, h = blockIdx.z;
    int tid = threadIdx.x;
    int wid = tid >> 5, lane = tid & 31;
    int g = lane >> 2, t = lane & 3;
    int wm = wid & 3, wn = wid >> 2;
    uint32_t pb = smem_to_u32(ps), vb = smem_to_u32(vs);
    const __half* ph_g = (const __half*)paw;

    int l16 = lane & 15;
    uint32_t offA[2];
    #pragma unroll
    for (int mt = 0; mt < 2; mt++)
        offA[mt] = (uint32_t)((wm * 32 + mt * 16 + l16) * AP) * 2 + (uint32_t)(lane >> 4) * 16;
    int lr = lane & 7, sel = lane >> 3;
    uint32_t offBT[2];
    #pragma unroll
    for (int ng = 0; ng < 2; ng++)
        offBT[ng] = (uint32_t)(((sel & 1) * 8 + lr) * AP) * 2
                  + (uint32_t)(wn * 32 + ng * 16 + (sel >> 1) * 8) * 2;

    float acc[2][4][4];
    #pragma unroll
    for (int i = 0; i < 2; i++)
        #pragma unroll
        for (int j = 0; j < 4; j++)
            #pragma unroll
            for (int c = 0; c < 4; c++) acc[i][j][c] = 0.f;

    int prow = tid >> 1, pc0 = (tid & 1) * 32;
    int vrow = tid >> 2, vc8 = (tid & 3) * 16;

    for (int jc = 0; jc < CC; jc += 64) {
        const __half* pg = ph_g + (size_t)h * 131072 + (size_t)(i0 + prow) * 512 + jc;
        #pragma unroll
        for (int q = 0; q < 4; q++)
            cp_async16(pb + (uint32_t)(prow * AP + pc0 + q * 8) * 2, pg + pc0 + q * 8);
        const __half* vg = qkv + 1536 + (size_t)(r * CC + jc + vrow) * QLD + h * DD;
        cp_async16(vb + (uint32_t)(vrow * AP + vc8) * 2,     vg + vc8);
        cp_async16(vb + (uint32_t)(vrow * AP + vc8 + 8) * 2, vg + vc8 + 8);
        CP_COMMIT(); CP_WAIT0();
        __syncthreads();

        #pragma unroll
        for (int ks_ = 0; ks_ < 4; ks_++) {
            uint32_t koffA = (uint32_t)ks_ * 32;
            uint32_t koffB = (uint32_t)(ks_ * 16 * AP) * 2;
            uint32_t af[2][4], bt0[4], bt1[4];
            ldsm_x4(af[0], pb + offA[0] + koffA);
            ldsm_x4(af[1], pb + offA[1] + koffA);
            ldsm_x4_t(bt0, vb + offBT[0] + koffB);
            ldsm_x4_t(bt1, vb + offBT[1] + koffB);
            #pragma unroll
            for (int mt = 0; mt < 2; mt++) {
                mma_f16(acc[mt][0], af[mt], bt0[0], bt0[1]);
                mma_f16(acc[mt][1], af[mt], bt0[2], bt0[3]);
                mma_f16(acc[mt][2], af[mt], bt1[0], bt1[1]);
                mma_f16(acc[mt][3], af[mt], bt1[2], bt1[3]);
            }
        }
        __syncthreads();
    }

    #pragma unroll
    for (int mt = 0; mt < 2; mt++) {
        #pragma unroll
        for (int nt = 0; nt < 4; nt++) {
            int d = h * DD + wn * 32 + (nt >> 1) * 16 + (nt & 1) * 8 + 2 * t;
            #pragma unroll
            for (int hf = 0; hf < 2; hf++) {
                int m = i0 + wm * 32 + mt * 16 + g + hf * 8;
                *(__half2*)(ctx + (size_t)(r * CC + m) * EE + d) =
                    __floats2half2_rn(acc[mt][nt][hf * 2], acc[mt][nt][hf * 2 + 1]);
            }
        }
    }
}

// ---- FUSED col attention: scores + softmax + P@V per (h,c) CTA ----
__global__ void __launch_bounds__(256) col_attn_fused(
    const __half* __restrict__ qkv, __half* __restrict__ ctx)
{
    __shared__ __half qs[64 * AP];
    __shared__ __half ks[64 * AP];
    __shared__ __half vs[64 * AP];
    __shared__ float  Ss[64 * 68];
    __shared__ __half pshalf[64 * AP];
    int c = blockIdx.x, h = blockIdx.y;
    int tid = threadIdx.x;
    int wid = tid >> 5, lane = tid & 31;
    int g = lane >> 2, t = lane & 3;
    int wm = wid & 3, wn = wid >> 2;
    uint32_t qb = smem_to_u32(qs), kb = smem_to_u32(ks);
    uint32_t vb = smem_to_u32(vs), pb = smem_to_u32(pshalf);

    // load q, k, v tiles (64 rows x 64 halves each)
    int lrow = tid >> 2, lc8 = (tid & 3) * 16;
    {
        const __half* qr = qkv + (size_t)(lrow * CC + c) * QLD + h * DD;
        const __half* kr = qr + 768;
        const __half* vr = qr + 1536;
        cp_async16(qb + (uint32_t)(lrow * AP + lc8) * 2,     qr + lc8);
        cp_async16(qb + (uint32_t)(lrow * AP + lc8 + 8) * 2, qr + lc8 + 8);
        cp_async16(kb + (uint32_t)(lrow * AP + lc8) * 2,     kr + lc8);
        cp_async16(kb + (uint32_t)(lrow * AP + lc8 + 8) * 2, kr + lc8 + 8);
        cp_async16(vb + (uint32_t)(lrow * AP + lc8) * 2,     vr + lc8);
        cp_async16(vb + (uint32_t)(lrow * AP + lc8 + 8) * 2, vr + lc8 + 8);
        CP_COMMIT(); CP_WAIT0();
    }
    __syncthreads();

    // ---- scores: S = q @ k^T ----
    int l16 = lane & 15;
    uint32_t offA = (uint32_t)((wm * 16 + l16) * AP) * 2 + (uint32_t)(lane >> 4) * 16;
    int l8 = lane & 7;
    int bhv = (lane >> 3) & 1, bg = lane >> 4;
    uint32_t offB[2];
    #pragma unroll
    for (int p = 0; p < 2; p++)
        offB[p] = (uint32_t)((wn * 32 + p * 16 + bg * 8 + l8) * AP) * 2 + (uint32_t)bhv * 16;

    float acc[4][4];
    #pragma unroll
    for (int i = 0; i < 4; i++)
        #pragma unroll
        for (int cc2 = 0; cc2 < 4; cc2++) acc[i][cc2] = 0.f;

    #pragma unroll
    for (int ks_ = 0; ks_ < 4; ks_++) {
        uint32_t koff = (uint32_t)ks_ * 32;
        uint32_t af[4], bf0[4], bf1[4];
        ldsm_x4(af, qb + offA + koff);
        ldsm_x4(bf0, kb + offB[0] + koff);
        ldsm_x4(bf1, kb + offB[1] + koff);
        mma_f16(acc[0], af, bf0[0], bf0[1]);
        mma_f16(acc[1], af, bf0[2], bf0[3]);
        mma_f16(acc[2], af, bf1[0], bf1[1]);
        mma_f16(acc[3], af, bf1[2], bf1[3]);
    }

    // stash scores to smem fp32
    #pragma unroll
    for (int nt = 0; nt < 4; nt++) {
        int n = wn * 32 + (nt >> 1) * 16 + (nt & 1) * 8 + 2 * t;
        #pragma unroll
        for (int hf = 0; hf < 2; hf++) {
            int m = wm * 16 + g + hf * 8;
            Ss[m * 68 + n    ] = acc[nt][hf * 2];
            Ss[m * 68 + n + 1] = acc[nt][hf * 2 + 1];
        }
    }
    __syncthreads();

    // ---- softmax over n (64), row per 4-lane group ----
    {
        int row = tid >> 2;              // 0..63
        int part = tid & 3;              // 16 cols each
        float* Sr = Ss + row * 68 + part * 16;
        float e[16];
        float mx = -1e30f;
        #pragma unroll
        for (int i = 0; i < 16; i++) { e[i] = Sr[i]; mx = fmaxf(mx, e[i]); }
        mx = fmaxf(mx, __shfl_xor_sync(0xffffffffu, mx, 1));
        mx = fmaxf(mx, __shfl_xor_sync(0xffffffffu, mx, 2));
        float sum = 0.f;
        #pragma unroll
        for (int i = 0; i < 16; i++) { e[i] = expf(e[i] - mx); sum += e[i]; }
        sum += __shfl_xor_sync(0xffffffffu, sum, 1);
        sum += __shfl_xor_sync(0xffffffffu, sum, 2);
        float inv = 1.0f / sum;
        __half* pr = pshalf + row * AP + part * 16;
        #pragma unroll
        for (int i = 0; i < 8; i++)
            *(__half2*)(pr + 2 * i) = __floats2half2_rn(e[2 * i] * inv, e[2 * i + 1] * inv);
    }
    __syncthreads();

    // ---- ctx: P @ V ----
    int lr = lane & 7, sel = lane >> 3;
    uint32_t offBT[2];
    #pragma unroll
    for (int ng = 0; ng < 2; ng++)
        offBT[ng] = (uint32_t)(((sel & 1) * 8 + lr) * AP) * 2
                  + (uint32_t)(wn * 32 + ng * 16 + (sel >> 1) * 8) * 2;

    float acc2[4][4];
    #pragma unroll
    for (int i = 0; i < 4; i++)
        #pragma unroll
        for (int cc2 = 0; cc2 < 4; cc2++) acc2[i][cc2] = 0.f;

    #pragma unroll
    for (int ks_ = 0; ks_ < 4; ks_++) {
        uint32_t koffA = (uint32_t)ks_ * 32;
        uint32_t koffB = (uint32_t)(ks_ * 16 * AP) * 2;
        uint32_t af[4], bt0[4], bt1[4];
        ldsm_x4(af, pb + offA + koffA);
        ldsm_x4_t(bt0, vb + offBT[0] + koffB);
        ldsm_x4_t(bt1, vb + offBT[1] + koffB);
        mma_f16(acc2[0], af, bt0[0], bt0[1]);
        mma_f16(acc2[1], af, bt0[2], bt0[3]);
        mma_f16(acc2[2], af, bt1[0], bt1[1]);
        mma_f16(acc2[3], af, bt1[2], bt1[3]);
    }

    #pragma unroll
    for (int nt = 0; nt < 4; nt++) {
        int d = h * DD + wn * 32 + (nt >> 1) * 16 + (nt & 1) * 8 + 2 * t;
        #pragma unroll
        for (int hf = 0; hf < 2; hf++) {
            int m = wm * 16 + g + hf * 8;
            *(__half2*)(ctx + (size_t)(m * CC + c) * EE + d) =
                __floats2half2_rn(acc2[nt][hf * 2], acc2[nt][hf * 2 + 1]);
        }
    }
}

// ---------------- host driver ----------------
#define GEMM_SMEM (NSTAGE * 2 * TILE_H * 2)   // 81920 bytes

static void run_gemm(const __half* A, const __half* BT, const float* bias, const float* res,
                     float* Cf, __half* Ch, int M, int N, int K, int gelu) {
    dim3 grid(N / 128, M / 128);
    mma_gemm_f16<<<grid, 256, GEMM_SMEM>>>(A, BT, bias, res, Cf, Ch, M, N, K, gelu);
}

extern "C" void kernel_launch(void* const* d_in, const int* in_sizes, int n_in,
                              void* d_out, int out_size) {
    const float* x_in = (const float*)d_in[0];
    const float* rq_w = (const float*)d_in[1];  const float* rq_b = (const float*)d_in[2];
    const float* rk_w = (const float*)d_in[3];  const float* rk_b = (const float*)d_in[4];
    const float* rv_w = (const float*)d_in[5];  const float* rv_b = (const float*)d_in[6];
    const float* ro_w = (const float*)d_in[7];  const float* ro_b = (const float*)d_in[8];
    const float* cq_w = (const float*)d_in[9];  const float* cq_b = (const float*)d_in[10];
    const float* ck_w = (const float*)d_in[11]; const float* ck_b = (const float*)d_in[12];
    const float* cv_w = (const float*)d_in[13]; const float* cv_b = (const float*)d_in[14];
    const float* co_w = (const float*)d_in[15]; const float* co_b = (const float*)d_in[16];
    const float* f1_w = (const float*)d_in[17]; const float* f1_b = (const float*)d_in[18];
    const float* f2_w = (const float*)d_in[19]; const float* f2_b = (const float*)d_in[20];
    const float* ln1_s = (const float*)d_in[21]; const float* ln1_b = (const float*)d_in[22];
    const float* ln2_s = (const float*)d_in[23]; const float* ln2_b = (const float*)d_in[24];
    const float* ln3_s = (const float*)d_in[25]; const float* ln3_b = (const float*)d_in[26];

    float *px, *paw, *pbias;
    void *vh, *vctx, *vbig, *vwt;
    cudaGetSymbolAddress((void**)&px,    g_x);
    cudaGetSymbolAddress(&vh,    g_h);
    cudaGetSymbolAddress(&vctx,  g_ctx);
    cudaGetSymbolAddress((void**)&paw,   g_aw);
    cudaGetSymbolAddress(&vbig,  g_big);
    cudaGetSymbolAddress(&vwt,   g_wt);
    cudaGetSymbolAddress((void**)&pbias, g_bias);
    __half* ph    = (__half*)vh;
    __half* pctx  = (__half*)vctx;
    __half* pqkv  = (__half*)vbig;
    __half* pffn  = (__half*)vbig;
    __half* pwt   = (__half*)vwt;

    cudaFuncSetAttribute(mma_gemm_f16, cudaFuncAttributeMaxDynamicSharedMemorySize, GEMM_SMEM);

    const float row_scale = 0.015625f;
    const float col_scale = 0.125f;

    const size_t WEE = (size_t)EE * EE;
    __half* rqkvT = pwt;
    __half* roT   = pwt + 3 * WEE;
    __half* cqkvT = pwt + 4 * WEE;
    __half* coT   = pwt + 7 * WEE;
    __half* f1T   = pwt + 8 * WEE;
    __half* f2T   = f1T + (size_t)EE * FF;
    float* biasr = pbias;
    float* biasc = pbias + 2304;

    {
        TPArgs a;
        a.src[0] = rq_w; a.dst[0] = pwt + 0 * WEE; a.scale[0] = row_scale;
        a.src[1] = rk_w; a.dst[1] = pwt + 1 * WEE; a.scale[1] = 1.f;
        a.src[2] = rv_w; a.dst[2] = pwt + 2 * WEE; a.scale[2] = 1.f;
        a.src[3] = ro_w; a.dst[3] = roT;           a.scale[3] = 1.f;
        a.src[4] = cq_w; a.dst[4] = pwt + 4 * WEE; a.scale[4] = col_scale;
        a.src[5] = ck_w; a.dst[5] = pwt + 5 * WEE; a.scale[5] = 1.f;
        a.src[6] = cv_w; a.dst[6] = pwt + 6 * WEE; a.scale[6] = 1.f;
        a.src[7] = co_w; a.dst[7] = coT;           a.scale[7] = 1.f;
        a.src[8] = f1_w; a.dst[8] = f1T;           a.scale[8] = 1.f;
        a.src[9] = f2_w; a.dst[9] = f2T;           a.scale[9] = 1.f;
        a.rb[0] = rq_b; a.rb[1] = rk_b; a.rb[2] = rv_b;
        a.cb[0] = cq_b; a.cb[1] = ck_b; a.cb[2] = cv_b;
        a.biasr = biasr; a.biasc = biasc;
        a.row_scale = row_scale; a.col_scale = col_scale;
        dim3 b(32, 8);
        transpose_all_kernel<<<9218, b>>>(a);
    }

    // ===== row attention =====
    ln_kernel<<<MM, 256>>>(x_in, ln1_s, ln1_b, ph);
    run_gemm(ph, rqkvT, biasr, nullptr, nullptr, pqkv, MM, QLD, EE, 0);
    { dim3 g(2, 4, HH * 4); row_scores_mma<<<g, 256>>>(pqkv, paw); }   // 64i x 128j tiles, split-r
    softmax256_kernel<<<HH * CC, 256>>>(paw);
    { dim3 g(2, RR, HH); row_ctx_mma<<<g, 256>>>(paw, pqkv, pctx); }
    run_gemm(pctx, roT, ro_b, x_in, px, nullptr, MM, EE, EE, 0);

    // ===== column attention (fused scores+softmax+ctx) =====
    ln_kernel<<<MM, 256>>>(px, ln2_s, ln2_b, ph);
    run_gemm(ph, cqkvT, biasc, nullptr, nullptr, pqkv, MM, QLD, EE, 0);
    { dim3 g(CC, HH); col_attn_fused<<<g, 256>>>(pqkv, pctx); }
    run_gemm(pctx, coT, co_b, px, px, nullptr, MM, EE, EE, 0);

    // ===== FFN =====
    ln_kernel<<<MM, 256>>>(px, ln3_s, ln3_b, ph);
    run_gemm(ph, f1T, f1_b, nullptr, nullptr, pffn, MM, FF, EE, 1);
    run_gemm(pffn, f2T, f2_b, px, (float*)d_out, nullptr, MM, EE, FF, 0);
}

// round 12
// speedup vs baseline: 1.0910x; 1.0346x over previous
#include <cuda_runtime.h>
#include <cuda_fp16.h>
#include <math.h>
#include <stdint.h>

// ---------------- problem constants ----------------
#define RR 64
#define CC 256
#define EE 768
#define HH 12
#define DD 64
#define FF 3072
#define MM (RR*CC)          // 16384 tokens
#define QLD 2304            // packed qkv row stride (halves)
#define PHSZ (HH*CC*CC)     // one row-scores partial: 786432 floats

// ---------------- scratch (device globals; no allocation allowed) ----------------
__device__ float g_x   [MM*EE];       // residual stream (fp32)
__device__ float g_h   [MM*EE];       // reused as __half
__device__ float g_ctx [MM*EE];       // reused as __half
__device__ float g_aw  [HH*CC*RR*RR]; // row-score partials (half p in-place post-softmax)
__device__ float g_big [MM*FF];       // reused: qkv (half) / ffn h1 (half)
__device__ float g_wt  [9437184/2 + 64];  // transposed half weights
__device__ float g_bias[4608];        // packed row/col qkv biases

// ---------------- helpers ----------------
__device__ __forceinline__ uint32_t smem_to_u32(const void* p) {
    uint32_t a;
    asm("{ .reg .u64 t; cvta.to.shared.u64 t, %1; cvt.u32.u64 %0, t; }" : "=r"(a) : "l"(p));
    return a;
}
__device__ __forceinline__ void cp_async16(uint32_t saddr, const void* gptr) {
    asm volatile("cp.async.cg.shared.global [%0], [%1], 16;" :: "r"(saddr), "l"(gptr));
}
#define CP_COMMIT() asm volatile("cp.async.commit_group;" ::: "memory")
#define CP_WAIT1()  asm volatile("cp.async.wait_group 1;" ::: "memory")
#define CP_WAIT0()  asm volatile("cp.async.wait_group 0;" ::: "memory")

__device__ __forceinline__ void ldsm_x4(uint32_t* r, uint32_t addr) {
    asm volatile("ldmatrix.sync.aligned.m8n8.x4.shared.b16 {%0,%1,%2,%3}, [%4];"
        : "=r"(r[0]), "=r"(r[1]), "=r"(r[2]), "=r"(r[3]) : "r"(addr));
}
__device__ __forceinline__ void ldsm_x4_t(uint32_t* r, uint32_t addr) {
    asm volatile("ldmatrix.sync.aligned.m8n8.x4.trans.shared.b16 {%0,%1,%2,%3}, [%4];"
        : "=r"(r[0]), "=r"(r[1]), "=r"(r[2]), "=r"(r[3]) : "r"(addr));
}

__device__ __forceinline__ void mma_f16(float* d, const uint32_t* a, uint32_t b0, uint32_t b1) {
    asm volatile("mma.sync.aligned.m16n8k16.row.col.f32.f16.f16.f32 "
        "{%0,%1,%2,%3}, {%4,%5,%6,%7}, {%8,%9}, {%0,%1,%2,%3};"
        : "+f"(d[0]), "+f"(d[1]), "+f"(d[2]), "+f"(d[3])
        : "r"(a[0]), "r"(a[1]), "r"(a[2]), "r"(a[3]), "r"(b0), "r"(b1));
}

// ---------------- gelu (tanh approx) ----------------
__device__ __forceinline__ float gelu_f(float x) {
    float x3 = x * x * x;
    return 0.5f * x * (1.0f + tanhf(0.7978845608028654f * (x + 0.044715f * x3)));
}

// ---------------- fp16 mma.sync GEMM: 128x128 tile, 8 warps (4m x 2n), warp 32x64 ----------------
#define BKH 32
#define PITCH_H 40
#define TILE_H (128 * PITCH_H)
#define NSTAGE 4

__global__ void __launch_bounds__(256, 2) mma_gemm_f16(
    const __half* __restrict__ A, const __half* __restrict__ BT,
    const float* __restrict__ bias, const float* __restrict__ res,
    float* __restrict__ Cf, __half* __restrict__ Ch,
    int M, int N, int K, int act_gelu)
{
    extern __shared__ __half smh[];
    uint32_t sbase = smem_to_u32(smh);
    uint32_t AbufU[NSTAGE], BbufU[NSTAGE];
    #pragma unroll
    for (int s = 0; s < NSTAGE; s++) {
        AbufU[s] = sbase + (uint32_t)(2 * s    ) * TILE_H * 2;
        BbufU[s] = sbase + (uint32_t)(2 * s + 1) * TILE_H * 2;
    }

    int tid = threadIdx.x;
    int wid = tid >> 5, lane = tid & 31;
    int g = lane >> 2, t = lane & 3;
    int wm = wid & 3, wn = wid >> 2;
    int m0 = blockIdx.y * 128, n0 = blockIdx.x * 128;

    int l16 = lane & 15;
    uint32_t a_koff = (uint32_t)(lane >> 4) * 16;
    uint32_t offA[2];
    #pragma unroll
    for (int mt = 0; mt < 2; mt++)
        offA[mt] = (uint32_t)((wm * 32 + mt * 16 + l16) * PITCH_H) * 2 + a_koff;
    int l8 = lane & 7;
    int b_half16 = (lane >> 3) & 1;
    int b_grp8 = lane >> 4;
    uint32_t offB[4];
    #pragma unroll
    for (int p = 0; p < 4; p++)
        offB[p] = (uint32_t)((wn * 64 + p * 16 + b_grp8 * 8 + l8) * PITCH_H) * 2 + (uint32_t)b_half16 * 16;

    float acc[2][8][4];
    #pragma unroll
    for (int i = 0; i < 2; i++)
        #pragma unroll
        for (int j = 0; j < 8; j++)
            #pragma unroll
            for (int c = 0; c < 4; c++) acc[i][j][c] = 0.f;

    const int NT = K / BKH;

    #define PREFETCH(kt, b) do {                                               \
        int k0p = (kt) * BKH;                                                  \
        _Pragma("unroll")                                                      \
        for (int i = 0; i < 2; i++) {                                          \
            int idx = i * 256 + tid;                                           \
            int row = idx >> 2, c8 = (idx & 3) * 8;                            \
            cp_async16(AbufU[b] + (uint32_t)(row * PITCH_H + c8) * 2,          \
                       A  + (size_t)(m0 + row) * K + k0p + c8);                \
            cp_async16(BbufU[b] + (uint32_t)(row * PITCH_H + c8) * 2,          \
                       BT + (size_t)(n0 + row) * K + k0p + c8);                \
        }                                                                      \
        CP_COMMIT();                                                           \
    } while (0)

    PREFETCH(0, 0);
    if (NT > 1) PREFETCH(1, 1);

    for (int kt = 0; kt < NT; kt++) {
        int b = kt % NSTAGE;
        if (kt + 1 < NT) CP_WAIT1(); else CP_WAIT0();
        __syncthreads();
        if (kt + 2 < NT) PREFETCH(kt + 2, (kt + 2) % NSTAGE);

        uint32_t Ab = AbufU[b], Bb = BbufU[b];
        #pragma unroll
        for (int ks = 0; ks < 2; ks++) {
            uint32_t koff = (uint32_t)ks * 32;
            uint32_t af[2][4], bfr[4][4];
            ldsm_x4(af[0], Ab + offA[0] + koff);
            ldsm_x4(af[1], Ab + offA[1] + koff);
            #pragma unroll
            for (int p = 0; p < 4; p++)
                ldsm_x4(bfr[p], Bb + offB[p] + koff);
            #pragma unroll
            for (int mt = 0; mt < 2; mt++)
                #pragma unroll
                for (int p = 0; p < 4; p++) {
                    mma_f16(acc[mt][2 * p    ], af[mt], bfr[p][0], bfr[p][1]);
                    mma_f16(acc[mt][2 * p + 1], af[mt], bfr[p][2], bfr[p][3]);
                }
        }
        __syncthreads();
    }
    #undef PREFETCH

    #pragma unroll
    for (int mt = 0; mt < 2; mt++) {
        #pragma unroll
        for (int nt = 0; nt < 8; nt++) {
            int m = m0 + wm * 32 + mt * 16 + g;
            int n = n0 + wn * 64 + nt * 8 + 2 * t;
            float bx = bias[n], by = bias[n + 1];
            #pragma unroll
            for (int half = 0; half < 2; half++) {
                int mr = m + half * 8;
                float vx = acc[mt][nt][half * 2 + 0] + bx;
                float vy = acc[mt][nt][half * 2 + 1] + by;
                if (act_gelu) { vx = gelu_f(vx); vy = gelu_f(vy); }
                if (res) {
                    const float2 r2 = *(const float2*)(res + (size_t)mr * N + n);
                    vx += r2.x; vy += r2.y;
                }
                if (Cf) {
                    float2 o; o.x = vx; o.y = vy;
                    *(float2*)(Cf + (size_t)mr * N + n) = o;
                } else {
                    *(__half2*)(Ch + (size_t)mr * N + n) = __floats2half2_rn(vx, vy);
                }
            }
        }
    }
}

// ---------------- fused transpose of ALL 10 weights + bias packing ----------------
struct TPArgs {
    const float* src[10];
    __half* dst[10];
    float scale[10];
    const float* rb[3];
    const float* cb[3];
    float* biasr;
    float* biasc;
    float row_scale, col_scale;
};
__global__ void transpose_all_kernel(TPArgs args) {
    __shared__ float tbuf[32][33];
    int bid = blockIdx.x;
    if (bid >= 9216) {
        int which = bid - 9216;
        int tid = threadIdx.y * 32 + threadIdx.x;
        const float* const* src = which ? args.cb : args.rb;
        float* dst = which ? args.biasc : args.biasr;
        float qs = which ? args.col_scale : args.row_scale;
        for (int i = tid; i < 2304; i += 256) {
            int sec = i / 768, off = i % 768;
            float v = src[sec][off];
            if (sec == 0) v *= qs;
            dst[i] = v;
        }
        return;
    }
    int w, tx, ty, K, N;
    if (bid < 4608)      { w = bid / 576; int tt = bid % 576;  K = 768;  N = 768;  tx = tt % 24; ty = tt / 24; }
    else if (bid < 6912) { w = 8;         int tt = bid - 4608; K = 768;  N = 3072; tx = tt % 96; ty = tt / 96; }
    else                 { w = 9;         int tt = bid - 6912; K = 3072; N = 768;  tx = tt % 24; ty = tt / 24; }
    const float* in = args.src[w];
    __half* out = args.dst[w];
    float sc = args.scale[w];
    int x = tx * 32 + threadIdx.x;
    int y0 = ty * 32;
    #pragma unroll
    for (int i = threadIdx.y; i < 32; i += 8)
        tbuf[i][threadIdx.x] = in[(size_t)(y0 + i) * N + x];
    __syncthreads();
    int xo = ty * 32 + threadIdx.x;
    int yo0 = tx * 32;
    #pragma unroll
    for (int i = threadIdx.y; i < 32; i += 8)
        out[(size_t)(yo0 + i) * K + xo] = __float2half(tbuf[threadIdx.x][i] * sc);
}

// ---------------- layernorm (shuffle reductions): fp32 in, half out ----------------
__global__ void ln_kernel(const float* __restrict__ x, const float* __restrict__ s,
                          const float* __restrict__ b, __half* __restrict__ out) {
    __shared__ float ws[8];
    __shared__ float ws2[8];
    int t = threadIdx.x;
    int warp = t >> 5, lane = t & 31;
    const float* xr = x + (size_t)blockIdx.x * EE;
    float v0 = xr[t], v1 = xr[t + 256], v2 = xr[t + 512];
    float sum = v0 + v1 + v2;
    #pragma unroll
    for (int o = 16; o; o >>= 1) sum += __shfl_xor_sync(0xffffffffu, sum, o);
    if (lane == 0) ws[warp] = sum;
    __syncthreads();
    float tot = ws[0] + ws[1] + ws[2] + ws[3] + ws[4] + ws[5] + ws[6] + ws[7];
    float mean = tot * (1.0f / EE);
    float d0 = v0 - mean, d1 = v1 - mean, d2 = v2 - mean;
    float vsum = d0 * d0 + d1 * d1 + d2 * d2;
    #pragma unroll
    for (int o = 16; o; o >>= 1) vsum += __shfl_xor_sync(0xffffffffu, vsum, o);
    if (lane == 0) ws2[warp] = vsum;
    __syncthreads();
    float vtot = ws2[0] + ws2[1] + ws2[2] + ws2[3] + ws2[4] + ws2[5] + ws2[6] + ws2[7];
    float rstd = rsqrtf(vtot * (1.0f / EE) + 1e-6f);
    __half* orow = out + (size_t)blockIdx.x * EE;
    orow[t      ] = __float2half(d0 * rstd * s[t      ] + b[t      ]);
    orow[t + 256] = __float2half(d1 * rstd * s[t + 256] + b[t + 256]);
    orow[t + 512] = __float2half(d2 * rstd * s[t + 512] + b[t + 512]);
}

// ================= tensor-core attention =================
#define AP 72   // smem pitch (halves) for 64-wide attention tiles

// ---- row scores (split-r, wide j): partial[rc][h,i,j] over 64i x 128j tiles ----
__global__ void __launch_bounds__(256) row_scores_mma(
    const __half* __restrict__ qkv, float* __restrict__ aw)
{
    __shared__ __half qs[2][64 * AP];
    __shared__ __half ks[2][128 * AP];
    int h = blockIdx.z >> 2;
    int rc = blockIdx.z & 3;
    int i0 = blockIdx.y * 64, j0 = blockIdx.x * 128;
    int tid = threadIdx.x;
    int wid = tid >> 5, lane = tid & 31;
    int g = lane >> 2, t = lane & 3;
    int wm = wid & 3, wn = wid >> 2;
    uint32_t qb[2] = { smem_to_u32(qs[0]), smem_to_u32(qs[1]) };
    uint32_t kb[2] = { smem_to_u32(ks[0]), smem_to_u32(ks[1]) };

    int l16 = lane & 15;
    uint32_t offA = (uint32_t)((wm * 16 + l16) * AP) * 2 + (uint32_t)(lane >> 4) * 16;
    int l8 = lane & 7;
    int bh = (lane >> 3) & 1, bg = lane >> 4;
    uint32_t offB[4];
    #pragma unroll
    for (int p = 0; p < 4; p++)
        offB[p] = (uint32_t)((wn * 64 + p * 16 + bg * 8 + l8) * AP) * 2 + (uint32_t)bh * 16;

    float acc[8][4];
    #pragma unroll
    for (int i = 0; i < 8; i++)
        #pragma unroll
        for (int c = 0; c < 4; c++) acc[i][c] = 0.f;

    int rbase = rc * 16;

    #define LOADRS(r, b) do {                                                       \
        _Pragma("unroll")                                                           \
        for (int i = 0; i < 6; i++) {                                               \
            int idx = i * 256 + tid;                                                \
            int row = idx >> 3, c8 = (idx & 7) * 8;                                 \
            if (i < 2) {                                                            \
                cp_async16(qb[b] + (uint32_t)(row * AP + c8) * 2,                   \
                    qkv + (size_t)((r) * CC + i0 + row) * QLD + h * DD + c8);       \
            } else {                                                                \
                int krow = row - 64;                                                \
                cp_async16(kb[b] + (uint32_t)(krow * AP + c8) * 2,                  \
                    qkv + 768 + (size_t)((r) * CC + j0 + krow) * QLD + h * DD + c8);\
            }                                                                       \
        }                                                                           \
        CP_COMMIT();                                                                \
    } while (0)

    LOADRS(rbase, 0);
    for (int rr = 0; rr < 16; rr++) {
        if (rr + 1 < 16) { LOADRS(rbase + rr + 1, (rr + 1) & 1); CP_WAIT1(); } else CP_WAIT0();
        __syncthreads();
        int b = rr & 1;
        #pragma unroll
        for (int ks_ = 0; ks_ < 4; ks_++) {
            uint32_t koff = (uint32_t)ks_ * 32;
            uint32_t af[4], bfr[4][4];
            ldsm_x4(af, qb[b] + offA + koff);
            #pragma unroll
            for (int p = 0; p < 4; p++)
                ldsm_x4(bfr[p], kb[b] + offB[p] + koff);
            #pragma unroll
            for (int p = 0; p < 4; p++) {
                mma_f16(acc[2 * p    ], af, bfr[p][0], bfr[p][1]);
                mma_f16(acc[2 * p + 1], af, bfr[p][2], bfr[p][3]);
            }
        }
        __syncthreads();
    }
    #undef LOADRS

    float* out = aw + (size_t)rc * PHSZ + (size_t)h * CC * CC;
    #pragma unroll
    for (int nt = 0; nt < 8; nt++) {
        int n = j0 + wn * 64 + (nt >> 1) * 16 + (nt & 1) * 8 + 2 * t;
        #pragma unroll
        for (int hf = 0; hf < 2; hf++) {
            int m = i0 + wm * 16 + g + hf * 8;
            float2 o; o.x = acc[nt][hf * 2]; o.y = acc[nt][hf * 2 + 1];
            *(float2*)(out + (size_t)m * CC + n) = o;
        }
    }
}

// ---- softmax 256-wide over summed partials; writes HALF in-place at partial 0 ----
__global__ void softmax256_kernel(float* __restrict__ p) {
    __shared__ float red[256];
    int t = threadIdx.x;
    float* pr = p + (size_t)blockIdx.x * 256;
    float v = pr[t] + pr[t + PHSZ] + pr[t + 2 * (size_t)PHSZ] + pr[t + 3 * (size_t)PHSZ];
    red[t] = v;
    __syncthreads();
    for (int o = 128; o; o >>= 1) { if (t < o) red[t] = fmaxf(red[t], red[t + o]); __syncthreads(); }
    float mx = red[0];
    __syncthreads();
    float e = expf(v - mx);
    red[t] = e;
    __syncthreads();
    for (int o = 128; o; o >>= 1) { if (t < o) red[t] += red[t + o]; __syncthreads(); }
    float inv = 1.0f / red[0];
    __syncthreads();
    ((__half*)pr)[t] = __float2half(e * inv);
}

// ---- row ctx: CTA = 128i x 64d per (h,r), double-buffered jc pipeline ----
__global__ void __launch_bounds__(256) row_ctx_mma(
    const float* __restrict__ paw, const __half* __restrict__ qkv, __half* __restrict__ ctx)
{
    __shared__ __half ps[2][128 * AP];
    __shared__ __half vs[2][64 * AP];
    int i0 = blockIdx.x * 128;
    int r = blockIdx.y, h = blockIdx.z;
    int tid = threadIdx.x;
    int wid = tid >> 5, lane = tid & 31;
    int g = lane >> 2, t = lane & 3;
    int wm = wid & 3, wn = wid >> 2;
    uint32_t pb[2] = { smem_to_u32(ps[0]), smem_to_u32(ps[1]) };
    uint32_t vb[2] = { smem_to_u32(vs[0]), smem_to_u32(vs[1]) };
    const __half* ph_g = (const __half*)paw;

    int l16 = lane & 15;
    uint32_t offA[2];
    #pragma unroll
    for (int mt = 0; mt < 2; mt++)
        offA[mt] = (uint32_t)((wm * 32 + mt * 16 + l16) * AP) * 2 + (uint32_t)(lane >> 4) * 16;
    int lr = lane & 7, sel = lane >> 3;
    uint32_t offBT[2];
    #pragma unroll
    for (int ng = 0; ng < 2; ng++)
        offBT[ng] = (uint32_t)(((sel & 1) * 8 + lr) * AP) * 2
                  + (uint32_t)(wn * 32 + ng * 16 + (sel >> 1) * 8) * 2;

    float acc[2][4][4];
    #pragma unroll
    for (int i = 0; i < 2; i++)
        #pragma unroll
        for (int j = 0; j < 4; j++)
            #pragma unroll
            for (int c = 0; c < 4; c++) acc[i][j][c] = 0.f;

    int prow = tid >> 1, pc0 = (tid & 1) * 32;
    int vrow = tid >> 2, vc8 = (tid & 3) * 16;

    #define LOADJC(jc, b) do {                                                        \
        const __half* pg = ph_g + (size_t)h * 131072 + (size_t)(i0 + prow) * 512 + (jc); \
        _Pragma("unroll")                                                             \
        for (int q = 0; q < 4; q++)                                                   \
            cp_async16(pb[b] + (uint32_t)(prow * AP + pc0 + q * 8) * 2, pg + pc0 + q * 8); \
        const __half* vg = qkv + 1536 + (size_t)(r * CC + (jc) + vrow) * QLD + h * DD; \
        cp_async16(vb[b] + (uint32_t)(vrow * AP + vc8) * 2,     vg + vc8);            \
        cp_async16(vb[b] + (uint32_t)(vrow * AP + vc8 + 8) * 2, vg + vc8 + 8);        \
        CP_COMMIT();                                                                  \
    } while (0)

    LOADJC(0, 0);
    #pragma unroll
    for (int it = 0; it < 4; it++) {
        if (it + 1 < 4) { LOADJC((it + 1) * 64, (it + 1) & 1); CP_WAIT1(); } else CP_WAIT0();
        __syncthreads();
        int b = it & 1;
        #pragma unroll
        for (int ks_ = 0; ks_ < 4; ks_++) {
            uint32_t koffA = (uint32_t)ks_ * 32;
            uint32_t koffB = (uint32_t)(ks_ * 16 * AP) * 2;
            uint32_t af[2][4], bt0[4], bt1[4];
            ldsm_x4(af[0], pb[b] + offA[0] + koffA);
            ldsm_x4(af[1], pb[b] + offA[1] + koffA);
            ldsm_x4_t(bt0, vb[b] + offBT[0] + koffB);
            ldsm_x4_t(bt1, vb[b] + offBT[1] + koffB);
            #pragma unroll
            for (int mt = 0; mt < 2; mt++) {
                mma_f16(acc[mt][0], af[mt], bt0[0], bt0[1]);
                mma_f16(acc[mt][1], af[mt], bt0[2], bt0[3]);
                mma_f16(acc[mt][2], af[mt], bt1[0], bt1[1]);
                mma_f16(acc[mt][3], af[mt], bt1[2], bt1[3]);
            }
        }
        __syncthreads();
    }
    #undef LOADJC

    #pragma unroll
    for (int mt = 0; mt < 2; mt++) {
        #pragma unroll
        for (int nt = 0; nt < 4; nt++) {
            int d = h * DD + wn * 32 + (nt >> 1) * 16 + (nt & 1) * 8 + 2 * t;
            #pragma unroll
            for (int hf = 0; hf < 2; hf++) {
                int m = i0 + wm * 32 + mt * 16 + g + hf * 8;
                *(__half2*)(ctx + (size_t)(r * CC + m) * EE + d) =
                    __floats2half2_rn(acc[mt][nt][hf * 2], acc[mt][nt][hf * 2 + 1]);
            }
        }
    }
}

// ---- FUSED col attention: scores + softmax + P@V per (h,c) CTA ----
__global__ void __launch_bounds__(256) col_attn_fused(
    const __half* __restrict__ qkv, __half* __restrict__ ctx)
{
    __shared__ __half qs[64 * AP];
    __shared__ __half ks[64 * AP];
    __shared__ __half vs[64 * AP];
    __shared__ float  Ss[64 * 68];
    __shared__ __half pshalf[64 * AP];
    int c = blockIdx.x, h = blockIdx.y;
    int tid = threadIdx.x;
    int wid = tid >> 5, lane = tid & 31;
    int g = lane >> 2, t = lane & 3;
    int wm = wid & 3, wn = wid >> 2;
    uint32_t qb = smem_to_u32(qs), kb = smem_to_u32(ks);
    uint32_t vb = smem_to_u32(vs), pb = smem_to_u32(pshalf);

    int lrow = tid >> 2, lc8 = (tid & 3) * 16;
    {
        const __half* qr = qkv + (size_t)(lrow * CC + c) * QLD + h * DD;
        const __half* kr = qr + 768;
        const __half* vr = qr + 1536;
        cp_async16(qb + (uint32_t)(lrow * AP + lc8) * 2,     qr + lc8);
        cp_async16(qb + (uint32_t)(lrow * AP + lc8 + 8) * 2, qr + lc8 + 8);
        cp_async16(kb + (uint32_t)(lrow * AP + lc8) * 2,     kr + lc8);
        cp_async16(kb + (uint32_t)(lrow * AP + lc8 + 8) * 2, kr + lc8 + 8);
        cp_async16(vb + (uint32_t)(lrow * AP + lc8) * 2,     vr + lc8);
        cp_async16(vb + (uint32_t)(lrow * AP + lc8 + 8) * 2, vr + lc8 + 8);
        CP_COMMIT(); CP_WAIT0();
    }
    __syncthreads();

    int l16 = lane & 15;
    uint32_t offA = (uint32_t)((wm * 16 + l16) * AP) * 2 + (uint32_t)(lane >> 4) * 16;
    int l8 = lane & 7;
    int bhv = (lane >> 3) & 1, bg = lane >> 4;
    uint32_t offB[2];
    #pragma unroll
    for (int p = 0; p < 2; p++)
        offB[p] = (uint32_t)((wn * 32 + p * 16 + bg * 8 + l8) * AP) * 2 + (uint32_t)bhv * 16;

    float acc[4][4];
    #pragma unroll
    for (int i = 0; i < 4; i++)
        #pragma unroll
        for (int cc2 = 0; cc2 < 4; cc2++) acc[i][cc2] = 0.f;

    #pragma unroll
    for (int ks_ = 0; ks_ < 4; ks_++) {
        uint32_t koff = (uint32_t)ks_ * 32;
        uint32_t af[4], bf0[4], bf1[4];
        ldsm_x4(af, qb + offA + koff);
        ldsm_x4(bf0, kb + offB[0] + koff);
        ldsm_x4(bf1, kb + offB[1] + koff);
        mma_f16(acc[0], af, bf0[0], bf0[1]);
        mma_f16(acc[1], af, bf0[2], bf0[3]);
        mma_f16(acc[2], af, bf1[0], bf1[1]);
        mma_f16(acc[3], af, bf1[2], bf1[3]);
    }

    #pragma unroll
    for (int nt = 0; nt < 4; nt++) {
        int n = wn * 32 + (nt >> 1) * 16 + (nt & 1) * 8 + 2 * t;
        #pragma unroll
        for (int hf = 0; hf < 2; hf++) {
            int m = wm * 16 + g + hf * 8;
            Ss[m * 68 + n    ] = acc[nt][hf * 2];
            Ss[m * 68 + n + 1] = acc[nt][hf * 2 + 1];
        }
    }
    __syncthreads();

    {
        int row = tid >> 2;
        int part = tid & 3;
        float* Sr = Ss + row * 68 + part * 16;
        float e[16];
        float mx = -1e30f;
        #pragma unroll
        for (int i = 0; i < 16; i++) { e[i] = Sr[i]; mx = fmaxf(mx, e[i]); }
        mx = fmaxf(mx, __shfl_xor_sync(0xffffffffu, mx, 1));
        mx = fmaxf(mx, __shfl_xor_sync(0xffffffffu, mx, 2));
        float sum = 0.f;
        #pragma unroll
        for (int i = 0; i < 16; i++) { e[i] = expf(e[i] - mx); sum += e[i]; }
        sum += __shfl_xor_sync(0xffffffffu, sum, 1);
        sum += __shfl_xor_sync(0xffffffffu, sum, 2);
        float inv = 1.0f / sum;
        __half* pr = pshalf + row * AP + part * 16;
        #pragma unroll
        for (int i = 0; i < 8; i++)
            *(__half2*)(pr + 2 * i) = __floats2half2_rn(e[2 * i] * inv, e[2 * i + 1] * inv);
    }
    __syncthreads();

    int lr = lane & 7, sel = lane >> 3;
    uint32_t offBT[2];
    #pragma unroll
    for (int ng = 0; ng < 2; ng++)
        offBT[ng] = (uint32_t)(((sel & 1) * 8 + lr) * AP) * 2
                  + (uint32_t)(wn * 32 + ng * 16 + (sel >> 1) * 8) * 2;

    float acc2[4][4];
    #pragma unroll
    for (int i = 0; i < 4; i++)
        #pragma unroll
        for (int cc2 = 0; cc2 < 4; cc2++) acc2[i][cc2] = 0.f;

    #pragma unroll
    for (int ks_ = 0; ks_ < 4; ks_++) {
        uint32_t koffA = (uint32_t)ks_ * 32;
        uint32_t koffB = (uint32_t)(ks_ * 16 * AP) * 2;
        uint32_t af[4], bt0[4], bt1[4];
        ldsm_x4(af, pb + offA + koffA);
        ldsm_x4_t(bt0, vb + offBT[0] + koffB);
        ldsm_x4_t(bt1, vb + offBT[1] + koffB);
        mma_f16(acc2[0], af, bt0[0], bt0[1]);
        mma_f16(acc2[1], af, bt0[2], bt0[3]);
        mma_f16(acc2[2], af, bt1[0], bt1[1]);
        mma_f16(acc2[3], af, bt1[2], bt1[3]);
    }

    #pragma unroll
    for (int nt = 0; nt < 4; nt++) {
        int d = h * DD + wn * 32 + (nt >> 1) * 16 + (nt & 1) * 8 + 2 * t;
        #pragma unroll
        for (int hf = 0; hf < 2; hf++) {
            int m = wm * 16 + g + hf * 8;
            *(__half2*)(ctx + (size_t)(m * CC + c) * EE + d) =
                __floats2half2_rn(acc2[nt][hf * 2], acc2[nt][hf * 2 + 1]);
        }
    }
}

// ---------------- host driver ----------------
#define GEMM_SMEM (NSTAGE * 2 * TILE_H * 2)   // 81920 bytes

static void run_gemm(const __half* A, const __half* BT, const float* bias, const float* res,
                     float* Cf, __half* Ch, int M, int N, int K, int gelu) {
    dim3 grid(N / 128, M / 128);
    mma_gemm_f16<<<grid, 256, GEMM_SMEM>>>(A, BT, bias, res, Cf, Ch, M, N, K, gelu);
}

extern "C" void kernel_launch(void* const* d_in, const int* in_sizes, int n_in,
                              void* d_out, int out_size) {
    const float* x_in = (const float*)d_in[0];
    const float* rq_w = (const float*)d_in[1];  const float* rq_b = (const float*)d_in[2];
    const float* rk_w = (const float*)d_in[3];  const float* rk_b = (const float*)d_in[4];
    const float* rv_w = (const float*)d_in[5];  const float* rv_b = (const float*)d_in[6];
    const float* ro_w = (const float*)d_in[7];  const float* ro_b = (const float*)d_in[8];
    const float* cq_w = (const float*)d_in[9];  const float* cq_b = (const float*)d_in[10];
    const float* ck_w = (const float*)d_in[11]; const float* ck_b = (const float*)d_in[12];
    const float* cv_w = (const float*)d_in[13]; const float* cv_b = (const float*)d_in[14];
    const float* co_w = (const float*)d_in[15]; const float* co_b = (const float*)d_in[16];
    const float* f1_w = (const float*)d_in[17]; const float* f1_b = (const float*)d_in[18];
    const float* f2_w = (const float*)d_in[19]; const float* f2_b = (const float*)d_in[20];
    const float* ln1_s = (const float*)d_in[21]; const float* ln1_b = (const float*)d_in[22];
    const float* ln2_s = (const float*)d_in[23]; const float* ln2_b = (const float*)d_in[24];
    const float* ln3_s = (const float*)d_in[25]; const float* ln3_b = (const float*)d_in[26];

    float *px, *paw, *pbias;
    void *vh, *vctx, *vbig, *vwt;
    cudaGetSymbolAddress((void**)&px,    g_x);
    cudaGetSymbolAddress(&vh,    g_h);
    cudaGetSymbolAddress(&vctx,  g_ctx);
    cudaGetSymbolAddress((void**)&paw,   g_aw);
    cudaGetSymbolAddress(&vbig,  g_big);
    cudaGetSymbolAddress(&vwt,   g_wt);
    cudaGetSymbolAddress((void**)&pbias, g_bias);
    __half* ph    = (__half*)vh;
    __half* pctx  = (__half*)vctx;
    __half* pqkv  = (__half*)vbig;
    __half* pffn  = (__half*)vbig;
    __half* pwt   = (__half*)vwt;

    cudaFuncSetAttribute(mma_gemm_f16, cudaFuncAttributeMaxDynamicSharedMemorySize, GEMM_SMEM);

    const float row_scale = 0.015625f;
    const float col_scale = 0.125f;

    const size_t WEE = (size_t)EE * EE;
    __half* rqkvT = pwt;
    __half* roT   = pwt + 3 * WEE;
    __half* cqkvT = pwt + 4 * WEE;
    __half* coT   = pwt + 7 * WEE;
    __half* f1T   = pwt + 8 * WEE;
    __half* f2T   = f1T + (size_t)EE * FF;
    float* biasr = pbias;
    float* biasc = pbias + 2304;

    {
        TPArgs a;
        a.src[0] = rq_w; a.dst[0] = pwt + 0 * WEE; a.scale[0] = row_scale;
        a.src[1] = rk_w; a.dst[1] = pwt + 1 * WEE; a.scale[1] = 1.f;
        a.src[2] = rv_w; a.dst[2] = pwt + 2 * WEE; a.scale[2] = 1.f;
        a.src[3] = ro_w; a.dst[3] = roT;           a.scale[3] = 1.f;
        a.src[4] = cq_w; a.dst[4] = pwt + 4 * WEE; a.scale[4] = col_scale;
        a.src[5] = ck_w; a.dst[5] = pwt + 5 * WEE; a.scale[5] = 1.f;
        a.src[6] = cv_w; a.dst[6] = pwt + 6 * WEE; a.scale[6] = 1.f;
        a.src[7] = co_w; a.dst[7] = coT;           a.scale[7] = 1.f;
        a.src[8] = f1_w; a.dst[8] = f1T;           a.scale[8] = 1.f;
        a.src[9] = f2_w; a.dst[9] = f2T;           a.scale[9] = 1.f;
        a.rb[0] = rq_b; a.rb[1] = rk_b; a.rb[2] = rv_b;
        a.cb[0] = cq_b; a.cb[1] = ck_b; a.cb[2] = cv_b;
        a.biasr = biasr; a.biasc = biasc;
        a.row_scale = row_scale; a.col_scale = col_scale;
        dim3 b(32, 8);
        transpose_all_kernel<<<9218, b>>>(a);
    }

    // ===== row attention =====
    ln_kernel<<<MM, 256>>>(x_in, ln1_s, ln1_b, ph);
    run_gemm(ph, rqkvT, biasr, nullptr, nullptr, pqkv, MM, QLD, EE, 0);
    { dim3 g(2, 4, HH * 4); row_scores_mma<<<g, 256>>>(pqkv, paw); }
    softmax256_kernel<<<HH * CC, 256>>>(paw);
    { dim3 g(2, RR, HH); row_ctx_mma<<<g, 256>>>(paw, pqkv, pctx); }
    run_gemm(pctx, roT, ro_b, x_in, px, nullptr, MM, EE, EE, 0);

    // ===== column attention (fused scores+softmax+ctx) =====
    ln_kernel<<<MM, 256>>>(px, ln2_s, ln2_b, ph);
    run_gemm(ph, cqkvT, biasc, nullptr, nullptr, pqkv, MM, QLD, EE, 0);
    { dim3 g(CC, HH); col_attn_fused<<<g, 256>>>(pqkv, pctx); }
    run_gemm(pctx, coT, co_b, px, px, nullptr, MM, EE, EE, 0);

    // ===== FFN =====
    ln_kernel<<<MM, 256>>>(px, ln3_s, ln3_b, ph);
    run_gemm(ph, f1T, f1_b, nullptr, nullptr, pffn, MM, FF, EE, 1);
    run_gemm(pffn, f2T, f2_b, px, (float*)d_out, nullptr, MM, EE, FF, 0);
}

// round 13
// speedup vs baseline: 1.0942x; 1.0030x over previous
#include <cuda_runtime.h>
#include <cuda_fp16.h>
#include <math.h>
#include <stdint.h>

// ---------------- problem constants ----------------
#define RR 64
#define CC 256
#define EE 768
#define HH 12
#define DD 64
#define FF 3072
#define MM (RR*CC)          // 16384 tokens
#define QLD 2304            // packed qkv row stride (halves)
#define PHSZ (HH*CC*CC)     // one row-scores partial: 786432 floats

// ---------------- scratch (device globals; no allocation allowed) ----------------
__device__ float g_x   [MM*EE];       // residual stream (fp32)
__device__ float g_h   [MM*EE];       // ln output (half) / row-score partials 4-7 (fp32)
__device__ float g_ctx [MM*EE];       // reused as __half
__device__ float g_aw  [HH*CC*RR*RR]; // row-score partials 0-3 (half p in-place post-softmax)
__device__ float g_big [MM*FF];       // reused: qkv (half) / ffn h1 (half)
__device__ float g_wt  [9437184/2 + 64];  // transposed half weights
__device__ float g_bias[4608];        // packed row/col qkv biases

// ---------------- helpers ----------------
__device__ __forceinline__ uint32_t smem_to_u32(const void* p) {
    uint32_t a;
    asm("{ .reg .u64 t; cvta.to.shared.u64 t, %1; cvt.u32.u64 %0, t; }" : "=r"(a) : "l"(p));
    return a;
}
__device__ __forceinline__ void cp_async16(uint32_t saddr, const void* gptr) {
    asm volatile("cp.async.cg.shared.global [%0], [%1], 16;" :: "r"(saddr), "l"(gptr));
}
#define CP_COMMIT() asm volatile("cp.async.commit_group;" ::: "memory")
#define CP_WAIT1()  asm volatile("cp.async.wait_group 1;" ::: "memory")
#define CP_WAIT0()  asm volatile("cp.async.wait_group 0;" ::: "memory")

__device__ __forceinline__ void ldsm_x4(uint32_t* r, uint32_t addr) {
    asm volatile("ldmatrix.sync.aligned.m8n8.x4.shared.b16 {%0,%1,%2,%3}, [%4];"
        : "=r"(r[0]), "=r"(r[1]), "=r"(r[2]), "=r"(r[3]) : "r"(addr));
}
__device__ __forceinline__ void ldsm_x4_t(uint32_t* r, uint32_t addr) {
    asm volatile("ldmatrix.sync.aligned.m8n8.x4.trans.shared.b16 {%0,%1,%2,%3}, [%4];"
        : "=r"(r[0]), "=r"(r[1]), "=r"(r[2]), "=r"(r[3]) : "r"(addr));
}

__device__ __forceinline__ void mma_f16(float* d, const uint32_t* a, uint32_t b0, uint32_t b1) {
    asm volatile("mma.sync.aligned.m16n8k16.row.col.f32.f16.f16.f32 "
        "{%0,%1,%2,%3}, {%4,%5,%6,%7}, {%8,%9}, {%0,%1,%2,%3};"
        : "+f"(d[0]), "+f"(d[1]), "+f"(d[2]), "+f"(d[3])
        : "r"(a[0]), "r"(a[1]), "r"(a[2]), "r"(a[3]), "r"(b0), "r"(b1));
}

// ---------------- gelu (tanh approx) ----------------
__device__ __forceinline__ float gelu_f(float x) {
    float x3 = x * x * x;
    return 0.5f * x * (1.0f + tanhf(0.7978845608028654f * (x + 0.044715f * x3)));
}

// ---------------- fp16 mma.sync GEMM: 128x128 tile, 8 warps (4m x 2n), warp 32x64 ----------------
#define BKH 32
#define PITCH_H 40
#define TILE_H (128 * PITCH_H)
#define NSTAGE 4

__global__ void __launch_bounds__(256, 2) mma_gemm_f16(
    const __half* __restrict__ A, const __half* __restrict__ BT,
    const float* __restrict__ bias, const float* __restrict__ res,
    float* __restrict__ Cf, __half* __restrict__ Ch,
    int M, int N, int K, int act_gelu)
{
    extern __shared__ __half smh[];
    uint32_t sbase = smem_to_u32(smh);
    uint32_t AbufU[NSTAGE], BbufU[NSTAGE];
    #pragma unroll
    for (int s = 0; s < NSTAGE; s++) {
        AbufU[s] = sbase + (uint32_t)(2 * s    ) * TILE_H * 2;
        BbufU[s] = sbase + (uint32_t)(2 * s + 1) * TILE_H * 2;
    }

    int tid = threadIdx.x;
    int wid = tid >> 5, lane = tid & 31;
    int g = lane >> 2, t = lane & 3;
    int wm = wid & 3, wn = wid >> 2;
    int m0 = blockIdx.y * 128, n0 = blockIdx.x * 128;

    int l16 = lane & 15;
    uint32_t a_koff = (uint32_t)(lane >> 4) * 16;
    uint32_t offA[2];
    #pragma unroll
    for (int mt = 0; mt < 2; mt++)
        offA[mt] = (uint32_t)((wm * 32 + mt * 16 + l16) * PITCH_H) * 2 + a_koff;
    int l8 = lane & 7;
    int b_half16 = (lane >> 3) & 1;
    int b_grp8 = lane >> 4;
    uint32_t offB[4];
    #pragma unroll
    for (int p = 0; p < 4; p++)
        offB[p] = (uint32_t)((wn * 64 + p * 16 + b_grp8 * 8 + l8) * PITCH_H) * 2 + (uint32_t)b_half16 * 16;

    float acc[2][8][4];
    #pragma unroll
    for (int i = 0; i < 2; i++)
        #pragma unroll
        for (int j = 0; j < 8; j++)
            #pragma unroll
            for (int c = 0; c < 4; c++) acc[i][j][c] = 0.f;

    const int NT = K / BKH;

    #define PREFETCH(kt, b) do {                                               \
        int k0p = (kt) * BKH;                                                  \
        _Pragma("unroll")                                                      \
        for (int i = 0; i < 2; i++) {                                          \
            int idx = i * 256 + tid;                                           \
            int row = idx >> 2, c8 = (idx & 3) * 8;                            \
            cp_async16(AbufU[b] + (uint32_t)(row * PITCH_H + c8) * 2,          \
                       A  + (size_t)(m0 + row) * K + k0p + c8);                \
            cp_async16(BbufU[b] + (uint32_t)(row * PITCH_H + c8) * 2,          \
                       BT + (size_t)(n0 + row) * K + k0p + c8);                \
        }                                                                      \
        CP_COMMIT();                                                           \
    } while (0)

    PREFETCH(0, 0);
    if (NT > 1) PREFETCH(1, 1);

    for (int kt = 0; kt < NT; kt++) {
        int b = kt % NSTAGE;
        if (kt + 1 < NT) CP_WAIT1(); else CP_WAIT0();
        __syncthreads();
        if (kt + 2 < NT) PREFETCH(kt + 2, (kt + 2) % NSTAGE);

        uint32_t Ab = AbufU[b], Bb = BbufU[b];
        #pragma unroll
        for (int ks = 0; ks < 2; ks++) {
            uint32_t koff = (uint32_t)ks * 32;
            uint32_t af[2][4], bfr[4][4];
            ldsm_x4(af[0], Ab + offA[0] + koff);
            ldsm_x4(af[1], Ab + offA[1] + koff);
            #pragma unroll
            for (int p = 0; p < 4; p++)
                ldsm_x4(bfr[p], Bb + offB[p] + koff);
            #pragma unroll
            for (int mt = 0; mt < 2; mt++)
                #pragma unroll
                for (int p = 0; p < 4; p++) {
                    mma_f16(acc[mt][2 * p    ], af[mt], bfr[p][0], bfr[p][1]);
                    mma_f16(acc[mt][2 * p + 1], af[mt], bfr[p][2], bfr[p][3]);
                }
        }
        __syncthreads();
    }
    #undef PREFETCH

    #pragma unroll
    for (int mt = 0; mt < 2; mt++) {
        #pragma unroll
        for (int nt = 0; nt < 8; nt++) {
            int m = m0 + wm * 32 + mt * 16 + g;
            int n = n0 + wn * 64 + nt * 8 + 2 * t;
            float bx = bias[n], by = bias[n + 1];
            #pragma unroll
            for (int half = 0; half < 2; half++) {
                int mr = m + half * 8;
                float vx = acc[mt][nt][half * 2 + 0] + bx;
                float vy = acc[mt][nt][half * 2 + 1] + by;
                if (act_gelu) { vx = gelu_f(vx); vy = gelu_f(vy); }
                if (res) {
                    const float2 r2 = *(const float2*)(res + (size_t)mr * N + n);
                    vx += r2.x; vy += r2.y;
                }
                if (Cf) {
                    float2 o; o.x = vx; o.y = vy;
                    *(float2*)(Cf + (size_t)mr * N + n) = o;
                } else {
                    *(__half2*)(Ch + (size_t)mr * N + n) = __floats2half2_rn(vx, vy);
                }
            }
        }
    }
}

// ---------------- fused transpose of ALL 10 weights + bias packing ----------------
struct TPArgs {
    const float* src[10];
    __half* dst[10];
    float scale[10];
    const float* rb[3];
    const float* cb[3];
    float* biasr;
    float* biasc;
    float row_scale, col_scale;
};
__global__ void transpose_all_kernel(TPArgs args) {
    __shared__ float tbuf[32][33];
    int bid = blockIdx.x;
    if (bid >= 9216) {
        int which = bid - 9216;
        int tid = threadIdx.y * 32 + threadIdx.x;
        const float* const* src = which ? args.cb : args.rb;
        float* dst = which ? args.biasc : args.biasr;
        float qs = which ? args.col_scale : args.row_scale;
        for (int i = tid; i < 2304; i += 256) {
            int sec = i / 768, off = i % 768;
            float v = src[sec][off];
            if (sec == 0) v *= qs;
            dst[i] = v;
        }
        return;
    }
    int w, tx, ty, K, N;
    if (bid < 4608)      { w = bid / 576; int tt = bid % 576;  K = 768;  N = 768;  tx = tt % 24; ty = tt / 24; }
    else if (bid < 6912) { w = 8;         int tt = bid - 4608; K = 768;  N = 3072; tx = tt % 96; ty = tt / 96; }
    else                 { w = 9;         int tt = bid - 6912; K = 3072; N = 768;  tx = tt % 24; ty = tt / 24; }
    const float* in = args.src[w];
    __half* out = args.dst[w];
    float sc = args.scale[w];
    int x = tx * 32 + threadIdx.x;
    int y0 = ty * 32;
    #pragma unroll
    for (int i = threadIdx.y; i < 32; i += 8)
        tbuf[i][threadIdx.x] = in[(size_t)(y0 + i) * N + x];
    __syncthreads();
    int xo = ty * 32 + threadIdx.x;
    int yo0 = tx * 32;
    #pragma unroll
    for (int i = threadIdx.y; i < 32; i += 8)
        out[(size_t)(yo0 + i) * K + xo] = __float2half(tbuf[threadIdx.x][i] * sc);
}

// ---------------- layernorm (shuffle reductions, vectorized I/O): fp32 in, half out ----------------
__global__ void ln_kernel(const float* __restrict__ x, const float* __restrict__ s,
                          const float* __restrict__ b, __half* __restrict__ out) {
    __shared__ float ws[8];
    __shared__ float ws2[8];
    int t = threadIdx.x;
    int warp = t >> 5, lane = t & 31;
    const float* xr = x + (size_t)blockIdx.x * EE;
    float2 va = *(const float2*)(xr + 2 * t);
    float v2 = xr[512 + t];
    float sum = va.x + va.y + v2;
    #pragma unroll
    for (int o = 16; o; o >>= 1) sum += __shfl_xor_sync(0xffffffffu, sum, o);
    if (lane == 0) ws[warp] = sum;
    __syncthreads();
    float tot = ws[0] + ws[1] + ws[2] + ws[3] + ws[4] + ws[5] + ws[6] + ws[7];
    float mean = tot * (1.0f / EE);
    float d0 = va.x - mean, d1 = va.y - mean, d2 = v2 - mean;
    float vsum = d0 * d0 + d1 * d1 + d2 * d2;
    #pragma unroll
    for (int o = 16; o; o >>= 1) vsum += __shfl_xor_sync(0xffffffffu, vsum, o);
    if (lane == 0) ws2[warp] = vsum;
    __syncthreads();
    float vtot = ws2[0] + ws2[1] + ws2[2] + ws2[3] + ws2[4] + ws2[5] + ws2[6] + ws2[7];
    float rstd = rsqrtf(vtot * (1.0f / EE) + 1e-6f);
    __half* orow = out + (size_t)blockIdx.x * EE;
    float2 sv = *(const float2*)(s + 2 * t);
    float2 bv = *(const float2*)(b + 2 * t);
    *(__half2*)(orow + 2 * t) =
        __floats2half2_rn(d0 * rstd * sv.x + bv.x, d1 * rstd * sv.y + bv.y);
    orow[512 + t] = __float2half(d2 * rstd * s[512 + t] + b[512 + t]);
}

// ================= tensor-core attention =================
#define AP 72   // smem pitch (halves) for 64-wide attention tiles

// ---- row scores (8-way split-r, wide j): partials over 64i x 128j tiles ----
// blockIdx: x = j0/128 (2), y = i0/64 (4), z = h*8 + rc (96)
__global__ void __launch_bounds__(256) row_scores_mma(
    const __half* __restrict__ qkv, float* __restrict__ aw, float* __restrict__ aw2)
{
    __shared__ __half qs[2][64 * AP];
    __shared__ __half ks[2][128 * AP];
    int h = blockIdx.z >> 3;
    int rc = blockIdx.z & 7;
    int i0 = blockIdx.y * 64, j0 = blockIdx.x * 128;
    int tid = threadIdx.x;
    int wid = tid >> 5, lane = tid & 31;
    int g = lane >> 2, t = lane & 3;
    int wm = wid & 3, wn = wid >> 2;
    uint32_t qb[2] = { smem_to_u32(qs[0]), smem_to_u32(qs[1]) };
    uint32_t kb[2] = { smem_to_u32(ks[0]), smem_to_u32(ks[1]) };

    int l16 = lane & 15;
    uint32_t offA = (uint32_t)((wm * 16 + l16) * AP) * 2 + (uint32_t)(lane >> 4) * 16;
    int l8 = lane & 7;
    int bh = (lane >> 3) & 1, bg = lane >> 4;
    uint32_t offB[4];
    #pragma unroll
    for (int p = 0; p < 4; p++)
        offB[p] = (uint32_t)((wn * 64 + p * 16 + bg * 8 + l8) * AP) * 2 + (uint32_t)bh * 16;

    float acc[8][4];
    #pragma unroll
    for (int i = 0; i < 8; i++)
        #pragma unroll
        for (int c = 0; c < 4; c++) acc[i][c] = 0.f;

    int rbase = rc * 8;

    #define LOADRS(r, b) do {                                                       \
        _Pragma("unroll")                                                           \
        for (int i = 0; i < 6; i++) {                                               \
            int idx = i * 256 + tid;                                                \
            int row = idx >> 3, c8 = (idx & 7) * 8;                                 \
            if (i < 2) {                                                            \
                cp_async16(qb[b] + (uint32_t)(row * AP + c8) * 2,                   \
                    qkv + (size_t)((r) * CC + i0 + row) * QLD + h * DD + c8);       \
            } else {                                                                \
                int krow = row - 64;                                                \
                cp_async16(kb[b] + (uint32_t)(krow * AP + c8) * 2,                  \
                    qkv + 768 + (size_t)((r) * CC + j0 + krow) * QLD + h * DD + c8);\
            }                                                                       \
        }                                                                           \
        CP_COMMIT();                                                                \
    } while (0)

    LOADRS(rbase, 0);
    for (int rr = 0; rr < 8; rr++) {
        if (rr + 1 < 8) { LOADRS(rbase + rr + 1, (rr + 1) & 1); CP_WAIT1(); } else CP_WAIT0();
        __syncthreads();
        int b = rr & 1;
        #pragma unroll
        for (int ks_ = 0; ks_ < 4; ks_++) {
            uint32_t koff = (uint32_t)ks_ * 32;
            uint32_t af[4], bfr[4][4];
            ldsm_x4(af, qb[b] + offA + koff);
            #pragma unroll
            for (int p = 0; p < 4; p++)
                ldsm_x4(bfr[p], kb[b] + offB[p] + koff);
            #pragma unroll
            for (int p = 0; p < 4; p++) {
                mma_f16(acc[2 * p    ], af, bfr[p][0], bfr[p][1]);
                mma_f16(acc[2 * p + 1], af, bfr[p][2], bfr[p][3]);
            }
        }
        __syncthreads();
    }
    #undef LOADRS

    float* out = (rc < 4 ? aw + (size_t)rc * PHSZ : aw2 + (size_t)(rc - 4) * PHSZ)
               + (size_t)h * CC * CC;
    #pragma unroll
    for (int nt = 0; nt < 8; nt++) {
        int n = j0 + wn * 64 + (nt >> 1) * 16 + (nt & 1) * 8 + 2 * t;
        #pragma unroll
        for (int hf = 0; hf < 2; hf++) {
            int m = i0 + wm * 16 + g + hf * 8;
            float2 o; o.x = acc[nt][hf * 2]; o.y = acc[nt][hf * 2 + 1];
            *(float2*)(out + (size_t)m * CC + n) = o;
        }
    }
}

// ---- softmax 256-wide over 8 summed partials; writes HALF in-place at aw partial 0 ----
__global__ void softmax256_kernel(float* __restrict__ p, const float* __restrict__ p2) {
    __shared__ float red[256];
    int t = threadIdx.x;
    float* pr = p + (size_t)blockIdx.x * 256;
    const float* pr2 = p2 + (size_t)blockIdx.x * 256;
    float v = pr[t] + pr[t + PHSZ] + pr[t + 2 * (size_t)PHSZ] + pr[t + 3 * (size_t)PHSZ]
            + pr2[t] + pr2[t + PHSZ] + pr2[t + 2 * (size_t)PHSZ] + pr2[t + 3 * (size_t)PHSZ];
    red[t] = v;
    __syncthreads();
    for (int o = 128; o; o >>= 1) { if (t < o) red[t] = fmaxf(red[t], red[t + o]); __syncthreads(); }
    float mx = red[0];
    __syncthreads();
    float e = expf(v - mx);
    red[t] = e;
    __syncthreads();
    for (int o = 128; o; o >>= 1) { if (t < o) red[t] += red[t + o]; __syncthreads(); }
    float inv = 1.0f / red[0];
    __syncthreads();
    ((__half*)pr)[t] = __float2half(e * inv);
}

// ---- row ctx: CTA = 128i x 64d per (h,r), double-buffered jc pipeline ----
__global__ void __launch_bounds__(256) row_ctx_mma(
    const float* __restrict__ paw, const __half* __restrict__ qkv, __half* __restrict__ ctx)
{
    __shared__ __half ps[2][128 * AP];
    __shared__ __half vs[2][64 * AP];
    int i0 = blockIdx.x * 128;
    int r = blockIdx.y, h = blockIdx.z;
    int tid = threadIdx.x;
    int wid = tid >> 5, lane = tid & 31;
    int g = lane >> 2, t = lane & 3;
    int wm = wid & 3, wn = wid >> 2;
    uint32_t pb[2] = { smem_to_u32(ps[0]), smem_to_u32(ps[1]) };
    uint32_t vb[2] = { smem_to_u32(vs[0]), smem_to_u32(vs[1]) };
    const __half* ph_g = (const __half*)paw;

    int l16 = lane & 15;
    uint32_t offA[2];
    #pragma unroll
    for (int mt = 0; mt < 2; mt++)
        offA[mt] = (uint32_t)((wm * 32 + mt * 16 + l16) * AP) * 2 + (uint32_t)(lane >> 4) * 16;
    int lr = lane & 7, sel = lane >> 3;
    uint32_t offBT[2];
    #pragma unroll
    for (int ng = 0; ng < 2; ng++)
        offBT[ng] = (uint32_t)(((sel & 1) * 8 + lr) * AP) * 2
                  + (uint32_t)(wn * 32 + ng * 16 + (sel >> 1) * 8) * 2;

    float acc[2][4][4];
    #pragma unroll
    for (int i = 0; i < 2; i++)
        #pragma unroll
        for (int j = 0; j < 4; j++)
            #pragma unroll
            for (int c = 0; c < 4; c++) acc[i][j][c] = 0.f;

    int prow = tid >> 1, pc0 = (tid & 1) * 32;
    int vrow = tid >> 2, vc8 = (tid & 3) * 16;

    #define LOADJC(jc, b) do {                                                        \
        const __half* pg = ph_g + (size_t)h * 131072 + (size_t)(i0 + prow) * 512 + (jc); \
        _Pragma("unroll")                                                             \
        for (int q = 0; q < 4; q++)                                                   \
            cp_async16(pb[b] + (uint32_t)(prow * AP + pc0 + q * 8) * 2, pg + pc0 + q * 8); \
        const __half* vg = qkv + 1536 + (size_t)(r * CC + (jc) + vrow) * QLD + h * DD; \
        cp_async16(vb[b] + (uint32_t)(vrow * AP + vc8) * 2,     vg + vc8);            \
        cp_async16(vb[b] + (uint32_t)(vrow * AP + vc8 + 8) * 2, vg + vc8 + 8);        \
        CP_COMMIT();                                                                  \
    } while (0)

    LOADJC(0, 0);
    #pragma unroll
    for (int it = 0; it < 4; it++) {
        if (it + 1 < 4) { LOADJC((it + 1) * 64, (it + 1) & 1); CP_WAIT1(); } else CP_WAIT0();
        __syncthreads();
        int b = it & 1;
        #pragma unroll
        for (int ks_ = 0; ks_ < 4; ks_++) {
            uint32_t koffA = (uint32_t)ks_ * 32;
            uint32_t koffB = (uint32_t)(ks_ * 16 * AP) * 2;
            uint32_t af[2][4], bt0[4], bt1[4];
            ldsm_x4(af[0], pb[b] + offA[0] + koffA);
            ldsm_x4(af[1], pb[b] + offA[1] + koffA);
            ldsm_x4_t(bt0, vb[b] + offBT[0] + koffB);
            ldsm_x4_t(bt1, vb[b] + offBT[1] + koffB);
            #pragma unroll
            for (int mt = 0; mt < 2; mt++) {
                mma_f16(acc[mt][0], af[mt], bt0[0], bt0[1]);
                mma_f16(acc[mt][1], af[mt], bt0[2], bt0[3]);
                mma_f16(acc[mt][2], af[mt], bt1[0], bt1[1]);
                mma_f16(acc[mt][3], af[mt], bt1[2], bt1[3]);
            }
        }
        __syncthreads();
    }
    #undef LOADJC

    #pragma unroll
    for (int mt = 0; mt < 2; mt++) {
        #pragma unroll
        for (int nt = 0; nt < 4; nt++) {
            int d = h * DD + wn * 32 + (nt >> 1) * 16 + (nt & 1) * 8 + 2 * t;
            #pragma unroll
            for (int hf = 0; hf < 2; hf++) {
                int m = i0 + wm * 32 + mt * 16 + g + hf * 8;
                *(__half2*)(ctx + (size_t)(r * CC + m) * EE + d) =
                    __floats2half2_rn(acc[mt][nt][hf * 2], acc[mt][nt][hf * 2 + 1]);
            }
        }
    }
}

// ---- FUSED col attention: scores + softmax + P@V per (h,c) CTA ----
__global__ void __launch_bounds__(256) col_attn_fused(
    const __half* __restrict__ qkv, __half* __restrict__ ctx)
{
    __shared__ __half qs[64 * AP];
    __shared__ __half ks[64 * AP];
    __shared__ __half vs[64 * AP];
    __shared__ float  Ss[64 * 68];
    __shared__ __half pshalf[64 * AP];
    int c = blockIdx.x, h = blockIdx.y;
    int tid = threadIdx.x;
    int wid = tid >> 5, lane = tid & 31;
    int g = lane >> 2, t = lane & 3;
    int wm = wid & 3, wn = wid >> 2;
    uint32_t qb = smem_to_u32(qs), kb = smem_to_u32(ks);
    uint32_t vb = smem_to_u32(vs), pb = smem_to_u32(pshalf);

    int lrow = tid >> 2, lc8 = (tid & 3) * 16;
    {
        const __half* qr = qkv + (size_t)(lrow * CC + c) * QLD + h * DD;
        const __half* kr = qr + 768;
        const __half* vr = qr + 1536;
        cp_async16(qb + (uint32_t)(lrow * AP + lc8) * 2,     qr + lc8);
        cp_async16(qb + (uint32_t)(lrow * AP + lc8 + 8) * 2, qr + lc8 + 8);
        cp_async16(kb + (uint32_t)(lrow * AP + lc8) * 2,     kr + lc8);
        cp_async16(kb + (uint32_t)(lrow * AP + lc8 + 8) * 2, kr + lc8 + 8);
        cp_async16(vb + (uint32_t)(lrow * AP + lc8) * 2,     vr + lc8);
        cp_async16(vb + (uint32_t)(lrow * AP + lc8 + 8) * 2, vr + lc8 + 8);
        CP_COMMIT(); CP_WAIT0();
    }
    __syncthreads();

    int l16 = lane & 15;
    uint32_t offA = (uint32_t)((wm * 16 + l16) * AP) * 2 + (uint32_t)(lane >> 4) * 16;
    int l8 = lane & 7;
    int bhv = (lane >> 3) & 1, bg = lane >> 4;
    uint32_t offB[2];
    #pragma unroll
    for (int p = 0; p < 2; p++)
        offB[p] = (uint32_t)((wn * 32 + p * 16 + bg * 8 + l8) * AP) * 2 + (uint32_t)bhv * 16;

    float acc[4][4];
    #pragma unroll
    for (int i = 0; i < 4; i++)
        #pragma unroll
        for (int cc2 = 0; cc2 < 4; cc2++) acc[i][cc2] = 0.f;

    #pragma unroll
    for (int ks_ = 0; ks_ < 4; ks_++) {
        uint32_t koff = (uint32_t)ks_ * 32;
        uint32_t af[4], bf0[4], bf1[4];
        ldsm_x4(af, qb + offA + koff);
        ldsm_x4(bf0, kb + offB[0] + koff);
        ldsm_x4(bf1, kb + offB[1] + koff);
        mma_f16(acc[0], af, bf0[0], bf0[1]);
        mma_f16(acc[1], af, bf0[2], bf0[3]);
        mma_f16(acc[2], af, bf1[0], bf1[1]);
        mma_f16(acc[3], af, bf1[2], bf1[3]);
    }

    #pragma unroll
    for (int nt = 0; nt < 4; nt++) {
        int n = wn * 32 + (nt >> 1) * 16 + (nt & 1) * 8 + 2 * t;
        #pragma unroll
        for (int hf = 0; hf < 2; hf++) {
            int m = wm * 16 + g + hf * 8;
            Ss[m * 68 + n    ] = acc[nt][hf * 2];
            Ss[m * 68 + n + 1] = acc[nt][hf * 2 + 1];
        }
    }
    __syncthreads();

    {
        int row = tid >> 2;
        int part = tid & 3;
        float* Sr = Ss + row * 68 + part * 16;
        float e[16];
        float mx = -1e30f;
        #pragma unroll
        for (int i = 0; i < 16; i++) { e[i] = Sr[i]; mx = fmaxf(mx, e[i]); }
        mx = fmaxf(mx, __shfl_xor_sync(0xffffffffu, mx, 1));
        mx = fmaxf(mx, __shfl_xor_sync(0xffffffffu, mx, 2));
        float sum = 0.f;
        #pragma unroll
        for (int i = 0; i < 16; i++) { e[i] = expf(e[i] - mx); sum += e[i]; }
        sum += __shfl_xor_sync(0xffffffffu, sum, 1);
        sum += __shfl_xor_sync(0xffffffffu, sum, 2);
        float inv = 1.0f / sum;
        __half* pr = pshalf + row * AP + part * 16;
        #pragma unroll
        for (int i = 0; i < 8; i++)
            *(__half2*)(pr + 2 * i) = __floats2half2_rn(e[2 * i] * inv, e[2 * i + 1] * inv);
    }
    __syncthreads();

    int lr = lane & 7, sel = lane >> 3;
    uint32_t offBT[2];
    #pragma unroll
    for (int ng = 0; ng < 2; ng++)
        offBT[ng] = (uint32_t)(((sel & 1) * 8 + lr) * AP) * 2
                  + (uint32_t)(wn * 32 + ng * 16 + (sel >> 1) * 8) * 2;

    float acc2[4][4];
    #pragma unroll
    for (int i = 0; i < 4; i++)
        #pragma unroll
        for (int cc2 = 0; cc2 < 4; cc2++) acc2[i][cc2] = 0.f;

    #pragma unroll
    for (int ks_ = 0; ks_ < 4; ks_++) {
        uint32_t koffA = (uint32_t)ks_ * 32;
        uint32_t koffB = (uint32_t)(ks_ * 16 * AP) * 2;
        uint32_t af[4], bt0[4], bt1[4];
        ldsm_x4(af, pb + offA + koffA);
        ldsm_x4_t(bt0, vb + offBT[0] + koffB);
        ldsm_x4_t(bt1, vb + offBT[1] + koffB);
        mma_f16(acc2[0], af, bt0[0], bt0[1]);
        mma_f16(acc2[1], af, bt0[2], bt0[3]);
        mma_f16(acc2[2], af, bt1[0], bt1[1]);
        mma_f16(acc2[3], af, bt1[2], bt1[3]);
    }

    #pragma unroll
    for (int nt = 0; nt < 4; nt++) {
        int d = h * DD + wn * 32 + (nt >> 1) * 16 + (nt & 1) * 8 + 2 * t;
        #pragma unroll
        for (int hf = 0; hf < 2; hf++) {
            int m = wm * 16 + g + hf * 8;
            *(__half2*)(ctx + (size_t)(m * CC + c) * EE + d) =
                __floats2half2_rn(acc2[nt][hf * 2], acc2[nt][hf * 2 + 1]);
        }
    }
}

// ---------------- host driver ----------------
#define GEMM_SMEM (NSTAGE * 2 * TILE_H * 2)   // 81920 bytes

static void run_gemm(const __half* A, const __half* BT, const float* bias, const float* res,
                     float* Cf, __half* Ch, int M, int N, int K, int gelu) {
    dim3 grid(N / 128, M / 128);
    mma_gemm_f16<<<grid, 256, GEMM_SMEM>>>(A, BT, bias, res, Cf, Ch, M, N, K, gelu);
}

extern "C" void kernel_launch(void* const* d_in, const int* in_sizes, int n_in,
                              void* d_out, int out_size) {
    const float* x_in = (const float*)d_in[0];
    const float* rq_w = (const float*)d_in[1];  const float* rq_b = (const float*)d_in[2];
    const float* rk_w = (const float*)d_in[3];  const float* rk_b = (const float*)d_in[4];
    const float* rv_w = (const float*)d_in[5];  const float* rv_b = (const float*)d_in[6];
    const float* ro_w = (const float*)d_in[7];  const float* ro_b = (const float*)d_in[8];
    const float* cq_w = (const float*)d_in[9];  const float* cq_b = (const float*)d_in[10];
    const float* ck_w = (const float*)d_in[11]; const float* ck_b = (const float*)d_in[12];
    const float* cv_w = (const float*)d_in[13]; const float* cv_b = (const float*)d_in[14];
    const float* co_w = (const float*)d_in[15]; const float* co_b = (const float*)d_in[16];
    const float* f1_w = (const float*)d_in[17]; const float* f1_b = (const float*)d_in[18];
    const float* f2_w = (const float*)d_in[19]; const float* f2_b = (const float*)d_in[20];
    const float* ln1_s = (const float*)d_in[21]; const float* ln1_b = (const float*)d_in[22];
    const float* ln2_s = (const float*)d_in[23]; const float* ln2_b = (const float*)d_in[24];
    const float* ln3_s = (const float*)d_in[25]; const float* ln3_b = (const float*)d_in[26];

    float *px, *paw, *pbias, *ph_f;
    void *vh, *vctx, *vbig, *vwt;
    cudaGetSymbolAddress((void**)&px,    g_x);
    cudaGetSymbolAddress(&vh,    g_h);
    cudaGetSymbolAddress(&vctx,  g_ctx);
    cudaGetSymbolAddress((void**)&paw,   g_aw);
    cudaGetSymbolAddress(&vbig,  g_big);
    cudaGetSymbolAddress(&vwt,   g_wt);
    cudaGetSymbolAddress((void**)&pbias, g_bias);
    __half* ph    = (__half*)vh;
    ph_f          = (float*)vh;          // row-score partials 4-7 (h is dead post-QKV)
    __half* pctx  = (__half*)vctx;
    __half* pqkv  = (__half*)vbig;
    __half* pffn  = (__half*)vbig;
    __half* pwt   = (__half*)vwt;

    cudaFuncSetAttribute(mma_gemm_f16, cudaFuncAttributeMaxDynamicSharedMemorySize, GEMM_SMEM);

    const float row_scale = 0.015625f;
    const float col_scale = 0.125f;

    const size_t WEE = (size_t)EE * EE;
    __half* rqkvT = pwt;
    __half* roT   = pwt + 3 * WEE;
    __half* cqkvT = pwt + 4 * WEE;
    __half* coT   = pwt + 7 * WEE;
    __half* f1T   = pwt + 8 * WEE;
    __half* f2T   = f1T + (size_t)EE * FF;
    float* biasr = pbias;
    float* biasc = pbias + 2304;

    {
        TPArgs a;
        a.src[0] = rq_w; a.dst[0] = pwt + 0 * WEE; a.scale[0] = row_scale;
        a.src[1] = rk_w; a.dst[1] = pwt + 1 * WEE; a.scale[1] = 1.f;
        a.src[2] = rv_w; a.dst[2] = pwt + 2 * WEE; a.scale[2] = 1.f;
        a.src[3] = ro_w; a.dst[3] = roT;           a.scale[3] = 1.f;
        a.src[4] = cq_w; a.dst[4] = pwt + 4 * WEE; a.scale[4] = col_scale;
        a.src[5] = ck_w; a.dst[5] = pwt + 5 * WEE; a.scale[5] = 1.f;
        a.src[6] = cv_w; a.dst[6] = pwt + 6 * WEE; a.scale[6] = 1.f;
        a.src[7] = co_w; a.dst[7] = coT;           a.scale[7] = 1.f;
        a.src[8] = f1_w; a.dst[8] = f1T;           a.scale[8] = 1.f;
        a.src[9] = f2_w; a.dst[9] = f2T;           a.scale[9] = 1.f;
        a.rb[0] = rq_b; a.rb[1] = rk_b; a.rb[2] = rv_b;
        a.cb[0] = cq_b; a.cb[1] = ck_b; a.cb[2] = cv_b;
        a.biasr = biasr; a.biasc = biasc;
        a.row_scale = row_scale; a.col_scale = col_scale;
        dim3 b(32, 8);
        transpose_all_kernel<<<9218, b>>>(a);
    }

    // ===== row attention =====
    ln_kernel<<<MM, 256>>>(x_in, ln1_s, ln1_b, ph);
    run_gemm(ph, rqkvT, biasr, nullptr, nullptr, pqkv, MM, QLD, EE, 0);
    { dim3 g(2, 4, HH * 8); row_scores_mma<<<g, 256>>>(pqkv, paw, ph_f); }  // 8-way split-r
    softmax256_kernel<<<HH * CC, 256>>>(paw, ph_f);
    { dim3 g(2, RR, HH); row_ctx_mma<<<g, 256>>>(paw, pqkv, pctx); }
    run_gemm(pctx, roT, ro_b, x_in, px, nullptr, MM, EE, EE, 0);

    // ===== column attention (fused scores+softmax+ctx) =====
    ln_kernel<<<MM, 256>>>(px, ln2_s, ln2_b, ph);
    run_gemm(ph, cqkvT, biasc, nullptr, nullptr, pqkv, MM, QLD, EE, 0);
    { dim3 g(CC, HH); col_attn_fused<<<g, 256>>>(pqkv, pctx); }
    run_gemm(pctx, coT, co_b, px, px, nullptr, MM, EE, EE, 0);

    // ===== FFN =====
    ln_kernel<<<MM, 256>>>(px, ln3_s, ln3_b, ph);
    run_gemm(ph, f1T, f1_b, nullptr, nullptr, pffn, MM, FF, EE, 1);
    run_gemm(pffn, f2T, f2_b, px, (float*)d_out, nullptr, MM, EE, FF, 0);
}

// round 14
// speedup vs baseline: 1.0988x; 1.0042x over previous
#include <cuda_runtime.h>
#include <cuda_fp16.h>
#include <math.h>
#include <stdint.h>

// ---------------- problem constants ----------------
#define RR 64
#define CC 256
#define EE 768
#define HH 12
#define DD 64
#define FF 3072
#define MM (RR*CC)          // 16384 tokens
#define QLD 2304            // packed qkv row stride (halves)
#define PHSZ (HH*CC*CC)     // one row-scores partial: 786432 floats

// ---------------- scratch (device globals; no allocation allowed) ----------------
__device__ float g_x   [MM*EE];       // residual stream (fp32)
__device__ float g_h   [MM*EE];       // ln output (half) / row-score partials 4-7 (fp32)
__device__ float g_ctx [MM*EE];       // reused as __half
__device__ float g_aw  [HH*CC*RR*RR]; // row-score partials 0-3 (half p in-place post-softmax)
__device__ float g_big [MM*FF];       // reused: qkv (half) / ffn h1 (half)
__device__ float g_wt  [9437184/2 + 64];  // transposed half weights
__device__ float g_bias[4608];        // packed row/col qkv biases

// ---------------- helpers ----------------
__device__ __forceinline__ uint32_t smem_to_u32(const void* p) {
    uint32_t a;
    asm("{ .reg .u64 t; cvta.to.shared.u64 t, %1; cvt.u32.u64 %0, t; }" : "=r"(a) : "l"(p));
    return a;
}
__device__ __forceinline__ void cp_async16(uint32_t saddr, const void* gptr) {
    asm volatile("cp.async.cg.shared.global [%0], [%1], 16;" :: "r"(saddr), "l"(gptr));
}
#define CP_COMMIT() asm volatile("cp.async.commit_group;" ::: "memory")
#define CP_WAIT1()  asm volatile("cp.async.wait_group 1;" ::: "memory")
#define CP_WAIT0()  asm volatile("cp.async.wait_group 0;" ::: "memory")

__device__ __forceinline__ void ldsm_x4(uint32_t* r, uint32_t addr) {
    asm volatile("ldmatrix.sync.aligned.m8n8.x4.shared.b16 {%0,%1,%2,%3}, [%4];"
        : "=r"(r[0]), "=r"(r[1]), "=r"(r[2]), "=r"(r[3]) : "r"(addr));
}
__device__ __forceinline__ void ldsm_x4_t(uint32_t* r, uint32_t addr) {
    asm volatile("ldmatrix.sync.aligned.m8n8.x4.trans.shared.b16 {%0,%1,%2,%3}, [%4];"
        : "=r"(r[0]), "=r"(r[1]), "=r"(r[2]), "=r"(r[3]) : "r"(addr));
}

__device__ __forceinline__ void mma_f16(float* d, const uint32_t* a, uint32_t b0, uint32_t b1) {
    asm volatile("mma.sync.aligned.m16n8k16.row.col.f32.f16.f16.f32 "
        "{%0,%1,%2,%3}, {%4,%5,%6,%7}, {%8,%9}, {%0,%1,%2,%3};"
        : "+f"(d[0]), "+f"(d[1]), "+f"(d[2]), "+f"(d[3])
        : "r"(a[0]), "r"(a[1]), "r"(a[2]), "r"(a[3]), "r"(b0), "r"(b1));
}

// ---------------- gelu (tanh approx) ----------------
__device__ __forceinline__ float gelu_f(float x) {
    float x3 = x * x * x;
    return 0.5f * x * (1.0f + tanhf(0.7978845608028654f * (x + 0.044715f * x3)));
}

// ---------------- fp16 mma.sync GEMM: 128x128 tile, 8 warps (4m x 2n), warp 32x64 ----------------
// Single barrier per k-tile: prefetch(kt+2) writes buffer (kt+2)%4, last read at kt-2,
// whose readers are ordered by the leading barriers of kt-1 and kt.
#define BKH 32
#define PITCH_H 40
#define TILE_H (128 * PITCH_H)
#define NSTAGE 4

__global__ void __launch_bounds__(256, 2) mma_gemm_f16(
    const __half* __restrict__ A, const __half* __restrict__ BT,
    const float* __restrict__ bias, const float* __restrict__ res,
    float* __restrict__ Cf, __half* __restrict__ Ch,
    int M, int N, int K, int act_gelu)
{
    extern __shared__ __half smh[];
    uint32_t sbase = smem_to_u32(smh);
    uint32_t AbufU[NSTAGE], BbufU[NSTAGE];
    #pragma unroll
    for (int s = 0; s < NSTAGE; s++) {
        AbufU[s] = sbase + (uint32_t)(2 * s    ) * TILE_H * 2;
        BbufU[s] = sbase + (uint32_t)(2 * s + 1) * TILE_H * 2;
    }

    int tid = threadIdx.x;
    int wid = tid >> 5, lane = tid & 31;
    int g = lane >> 2, t = lane & 3;
    int wm = wid & 3, wn = wid >> 2;
    int m0 = blockIdx.y * 128, n0 = blockIdx.x * 128;

    int l16 = lane & 15;
    uint32_t a_koff = (uint32_t)(lane >> 4) * 16;
    uint32_t offA[2];
    #pragma unroll
    for (int mt = 0; mt < 2; mt++)
        offA[mt] = (uint32_t)((wm * 32 + mt * 16 + l16) * PITCH_H) * 2 + a_koff;
    int l8 = lane & 7;
    int b_half16 = (lane >> 3) & 1;
    int b_grp8 = lane >> 4;
    uint32_t offB[4];
    #pragma unroll
    for (int p = 0; p < 4; p++)
        offB[p] = (uint32_t)((wn * 64 + p * 16 + b_grp8 * 8 + l8) * PITCH_H) * 2 + (uint32_t)b_half16 * 16;

    float acc[2][8][4];
    #pragma unroll
    for (int i = 0; i < 2; i++)
        #pragma unroll
        for (int j = 0; j < 8; j++)
            #pragma unroll
            for (int c = 0; c < 4; c++) acc[i][j][c] = 0.f;

    const int NT = K / BKH;

    #define PREFETCH(kt, b) do {                                               \
        int k0p = (kt) * BKH;                                                  \
        _Pragma("unroll")                                                      \
        for (int i = 0; i < 2; i++) {                                          \
            int idx = i * 256 + tid;                                           \
            int row = idx >> 2, c8 = (idx & 3) * 8;                            \
            cp_async16(AbufU[b] + (uint32_t)(row * PITCH_H + c8) * 2,          \
                       A  + (size_t)(m0 + row) * K + k0p + c8);                \
            cp_async16(BbufU[b] + (uint32_t)(row * PITCH_H + c8) * 2,          \
                       BT + (size_t)(n0 + row) * K + k0p + c8);                \
        }                                                                      \
        CP_COMMIT();                                                           \
    } while (0)

    PREFETCH(0, 0);
    if (NT > 1) PREFETCH(1, 1);

    for (int kt = 0; kt < NT; kt++) {
        int b = kt % NSTAGE;
        if (kt + 1 < NT) CP_WAIT1(); else CP_WAIT0();
        __syncthreads();
        if (kt + 2 < NT) PREFETCH(kt + 2, (kt + 2) % NSTAGE);

        uint32_t Ab = AbufU[b], Bb = BbufU[b];
        #pragma unroll
        for (int ks = 0; ks < 2; ks++) {
            uint32_t koff = (uint32_t)ks * 32;
            uint32_t af[2][4], bfr[4][4];
            ldsm_x4(af[0], Ab + offA[0] + koff);
            ldsm_x4(af[1], Ab + offA[1] + koff);
            #pragma unroll
            for (int p = 0; p < 4; p++)
                ldsm_x4(bfr[p], Bb + offB[p] + koff);
            #pragma unroll
            for (int mt = 0; mt < 2; mt++)
                #pragma unroll
                for (int p = 0; p < 4; p++) {
                    mma_f16(acc[mt][2 * p    ], af[mt], bfr[p][0], bfr[p][1]);
                    mma_f16(acc[mt][2 * p + 1], af[mt], bfr[p][2], bfr[p][3]);
                }
        }
        // no trailing barrier: buffer reuse distance (4 stages) is covered by leading barriers
    }
    #undef PREFETCH

    #pragma unroll
    for (int mt = 0; mt < 2; mt++) {
        #pragma unroll
        for (int nt = 0; nt < 8; nt++) {
            int m = m0 + wm * 32 + mt * 16 + g;
            int n = n0 + wn * 64 + nt * 8 + 2 * t;
            float bx = bias[n], by = bias[n + 1];
            #pragma unroll
            for (int half = 0; half < 2; half++) {
                int mr = m + half * 8;
                float vx = acc[mt][nt][half * 2 + 0] + bx;
                float vy = acc[mt][nt][half * 2 + 1] + by;
                if (act_gelu) { vx = gelu_f(vx); vy = gelu_f(vy); }
                if (res) {
                    const float2 r2 = *(const float2*)(res + (size_t)mr * N + n);
                    vx += r2.x; vy += r2.y;
                }
                if (Cf) {
                    float2 o; o.x = vx; o.y = vy;
                    *(float2*)(Cf + (size_t)mr * N + n) = o;
                } else {
                    *(__half2*)(Ch + (size_t)mr * N + n) = __floats2half2_rn(vx, vy);
                }
            }
        }
    }
}

// ---------------- fused transpose of ALL 10 weights + bias packing ----------------
struct TPArgs {
    const float* src[10];
    __half* dst[10];
    float scale[10];
    const float* rb[3];
    const float* cb[3];
    float* biasr;
    float* biasc;
    float row_scale, col_scale;
};
__global__ void transpose_all_kernel(TPArgs args) {
    __shared__ float tbuf[32][33];
    int bid = blockIdx.x;
    if (bid >= 9216) {
        int which = bid - 9216;
        int tid = threadIdx.y * 32 + threadIdx.x;
        const float* const* src = which ? args.cb : args.rb;
        float* dst = which ? args.biasc : args.biasr;
        float qs = which ? args.col_scale : args.row_scale;
        for (int i = tid; i < 2304; i += 256) {
            int sec = i / 768, off = i % 768;
            float v = src[sec][off];
            if (sec == 0) v *= qs;
            dst[i] = v;
        }
        return;
    }
    int w, tx, ty, K, N;
    if (bid < 4608)      { w = bid / 576; int tt = bid % 576;  K = 768;  N = 768;  tx = tt % 24; ty = tt / 24; }
    else if (bid < 6912) { w = 8;         int tt = bid - 4608; K = 768;  N = 3072; tx = tt % 96; ty = tt / 96; }
    else                 { w = 9;         int tt = bid - 6912; K = 3072; N = 768;  tx = tt % 24; ty = tt / 24; }
    const float* in = args.src[w];
    __half* out = args.dst[w];
    float sc = args.scale[w];
    int x = tx * 32 + threadIdx.x;
    int y0 = ty * 32;
    #pragma unroll
    for (int i = threadIdx.y; i < 32; i += 8)
        tbuf[i][threadIdx.x] = in[(size_t)(y0 + i) * N + x];
    __syncthreads();
    int xo = ty * 32 + threadIdx.x;
    int yo0 = tx * 32;
    #pragma unroll
    for (int i = threadIdx.y; i < 32; i += 8)
        out[(size_t)(yo0 + i) * K + xo] = __float2half(tbuf[threadIdx.x][i] * sc);
}

// ---------------- layernorm (shuffle reductions, vectorized I/O): fp32 in, half out ----------------
__global__ void ln_kernel(const float* __restrict__ x, const float* __restrict__ s,
                          const float* __restrict__ b, __half* __restrict__ out) {
    __shared__ float ws[8];
    __shared__ float ws2[8];
    int t = threadIdx.x;
    int warp = t >> 5, lane = t & 31;
    const float* xr = x + (size_t)blockIdx.x * EE;
    float2 va = *(const float2*)(xr + 2 * t);
    float v2 = xr[512 + t];
    float sum = va.x + va.y + v2;
    #pragma unroll
    for (int o = 16; o; o >>= 1) sum += __shfl_xor_sync(0xffffffffu, sum, o);
    if (lane == 0) ws[warp] = sum;
    __syncthreads();
    float tot = ws[0] + ws[1] + ws[2] + ws[3] + ws[4] + ws[5] + ws[6] + ws[7];
    float mean = tot * (1.0f / EE);
    float d0 = va.x - mean, d1 = va.y - mean, d2 = v2 - mean;
    float vsum = d0 * d0 + d1 * d1 + d2 * d2;
    #pragma unroll
    for (int o = 16; o; o >>= 1) vsum += __shfl_xor_sync(0xffffffffu, vsum, o);
    if (lane == 0) ws2[warp] = vsum;
    __syncthreads();
    float vtot = ws2[0] + ws2[1] + ws2[2] + ws2[3] + ws2[4] + ws2[5] + ws2[6] + ws2[7];
    float rstd = rsqrtf(vtot * (1.0f / EE) + 1e-6f);
    __half* orow = out + (size_t)blockIdx.x * EE;
    float2 sv = *(const float2*)(s + 2 * t);
    float2 bv = *(const float2*)(b + 2 * t);
    *(__half2*)(orow + 2 * t) =
        __floats2half2_rn(d0 * rstd * sv.x + bv.x, d1 * rstd * sv.y + bv.y);
    orow[512 + t] = __float2half(d2 * rstd * s[512 + t] + b[512 + t]);
}

// ================= tensor-core attention =================
#define AP 72   // smem pitch (halves) for 64-wide attention tiles

// ---- row scores (8-way split-r, wide j): partials over 64i x 128j tiles ----
// Single barrier per r: prefetch moved AFTER the barrier (WAIT0 -> barrier -> load -> compute).
__global__ void __launch_bounds__(256) row_scores_mma(
    const __half* __restrict__ qkv, float* __restrict__ aw, float* __restrict__ aw2)
{
    __shared__ __half qs[2][64 * AP];
    __shared__ __half ks[2][128 * AP];
    int h = blockIdx.z >> 3;
    int rc = blockIdx.z & 7;
    int i0 = blockIdx.y * 64, j0 = blockIdx.x * 128;
    int tid = threadIdx.x;
    int wid = tid >> 5, lane = tid & 31;
    int g = lane >> 2, t = lane & 3;
    int wm = wid & 3, wn = wid >> 2;
    uint32_t qb[2] = { smem_to_u32(qs[0]), smem_to_u32(qs[1]) };
    uint32_t kb[2] = { smem_to_u32(ks[0]), smem_to_u32(ks[1]) };

    int l16 = lane & 15;
    uint32_t offA = (uint32_t)((wm * 16 + l16) * AP) * 2 + (uint32_t)(lane >> 4) * 16;
    int l8 = lane & 7;
    int bh = (lane >> 3) & 1, bg = lane >> 4;
    uint32_t offB[4];
    #pragma unroll
    for (int p = 0; p < 4; p++)
        offB[p] = (uint32_t)((wn * 64 + p * 16 + bg * 8 + l8) * AP) * 2 + (uint32_t)bh * 16;

    float acc[8][4];
    #pragma unroll
    for (int i = 0; i < 8; i++)
        #pragma unroll
        for (int c = 0; c < 4; c++) acc[i][c] = 0.f;

    int rbase = rc * 8;

    #define LOADRS(r, b) do {                                                       \
        _Pragma("unroll")                                                           \
        for (int i = 0; i < 6; i++) {                                               \
            int idx = i * 256 + tid;                                                \
            int row = idx >> 3, c8 = (idx & 7) * 8;                                 \
            if (i < 2) {                                                            \
                cp_async16(qb[b] + (uint32_t)(row * AP + c8) * 2,                   \
                    qkv + (size_t)((r) * CC + i0 + row) * QLD + h * DD + c8);       \
            } else {                                                                \
                int krow = row - 64;                                                \
                cp_async16(kb[b] + (uint32_t)(krow * AP + c8) * 2,                  \
                    qkv + 768 + (size_t)((r) * CC + j0 + krow) * QLD + h * DD + c8);\
            }                                                                       \
        }                                                                           \
        CP_COMMIT();                                                                \
    } while (0)

    LOADRS(rbase, 0);
    for (int rr = 0; rr < 8; rr++) {
        CP_WAIT0();          // only group rr outstanding (issued one iteration ago)
        __syncthreads();     // all warps done with the buffer we're about to overwrite
        if (rr + 1 < 8) LOADRS(rbase + rr + 1, (rr + 1) & 1);
        int b = rr & 1;
        #pragma unroll
        for (int ks_ = 0; ks_ < 4; ks_++) {
            uint32_t koff = (uint32_t)ks_ * 32;
            uint32_t af[4], bfr[4][4];
            ldsm_x4(af, qb[b] + offA + koff);
            #pragma unroll
            for (int p = 0; p < 4; p++)
                ldsm_x4(bfr[p], kb[b] + offB[p] + koff);
            #pragma unroll
            for (int p = 0; p < 4; p++) {
                mma_f16(acc[2 * p    ], af, bfr[p][0], bfr[p][1]);
                mma_f16(acc[2 * p + 1], af, bfr[p][2], bfr[p][3]);
            }
        }
    }
    #undef LOADRS

    float* out = (rc < 4 ? aw + (size_t)rc * PHSZ : aw2 + (size_t)(rc - 4) * PHSZ)
               + (size_t)h * CC * CC;
    #pragma unroll
    for (int nt = 0; nt < 8; nt++) {
        int n = j0 + wn * 64 + (nt >> 1) * 16 + (nt & 1) * 8 + 2 * t;
        #pragma unroll
        for (int hf = 0; hf < 2; hf++) {
            int m = i0 + wm * 16 + g + hf * 8;
            float2 o; o.x = acc[nt][hf * 2]; o.y = acc[nt][hf * 2 + 1];
            *(float2*)(out + (size_t)m * CC + n) = o;
        }
    }
}

// ---- softmax 256-wide over 8 summed partials; writes HALF in-place at aw partial 0 ----
__global__ void softmax256_kernel(float* __restrict__ p, const float* __restrict__ p2) {
    __shared__ float red[256];
    int t = threadIdx.x;
    float* pr = p + (size_t)blockIdx.x * 256;
    const float* pr2 = p2 + (size_t)blockIdx.x * 256;
    float v = pr[t] + pr[t + PHSZ] + pr[t + 2 * (size_t)PHSZ] + pr[t + 3 * (size_t)PHSZ]
            + pr2[t] + pr2[t + PHSZ] + pr2[t + 2 * (size_t)PHSZ] + pr2[t + 3 * (size_t)PHSZ];
    red[t] = v;
    __syncthreads();
    for (int o = 128; o; o >>= 1) { if (t < o) red[t] = fmaxf(red[t], red[t + o]); __syncthreads(); }
    float mx = red[0];
    __syncthreads();
    float e = expf(v - mx);
    red[t] = e;
    __syncthreads();
    for (int o = 128; o; o >>= 1) { if (t < o) red[t] += red[t + o]; __syncthreads(); }
    float inv = 1.0f / red[0];
    __syncthreads();
    ((__half*)pr)[t] = __float2half(e * inv);
}

// ---- row ctx: CTA = 128i x 64d per (h,r), single-barrier double-buffered jc pipeline ----
__global__ void __launch_bounds__(256) row_ctx_mma(
    const float* __restrict__ paw, const __half* __restrict__ qkv, __half* __restrict__ ctx)
{
    __shared__ __half ps[2][128 * AP];
    __shared__ __half vs[2][64 * AP];
    int i0 = blockIdx.x * 128;
    int r = blockIdx.y, h = blockIdx.z;
    int tid = threadIdx.x;
    int wid = tid >> 5, lane = tid & 31;
    int g = lane >> 2, t = lane & 3;
    int wm = wid & 3, wn = wid >> 2;
    uint32_t pb[2] = { smem_to_u32(ps[0]), smem_to_u32(ps[1]) };
    uint32_t vb[2] = { smem_to_u32(vs[0]), smem_to_u32(vs[1]) };
    const __half* ph_g = (const __half*)paw;

    int l16 = lane & 15;
    uint32_t offA[2];
    #pragma unroll
    for (int mt = 0; mt < 2; mt++)
        offA[mt] = (uint32_t)((wm * 32 + mt * 16 + l16) * AP) * 2 + (uint32_t)(lane >> 4) * 16;
    int lr = lane & 7, sel = lane >> 3;
    uint32_t offBT[2];
    #pragma unroll
    for (int ng = 0; ng < 2; ng++)
        offBT[ng] = (uint32_t)(((sel & 1) * 8 + lr) * AP) * 2
                  + (uint32_t)(wn * 32 + ng * 16 + (sel >> 1) * 8) * 2;

    float acc[2][4][4];
    #pragma unroll
    for (int i = 0; i < 2; i++)
        #pragma unroll
        for (int j = 0; j < 4; j++)
            #pragma unroll
            for (int c = 0; c < 4; c++) acc[i][j][c] = 0.f;

    int prow = tid >> 1, pc0 = (tid & 1) * 32;
    int vrow = tid >> 2, vc8 = (tid & 3) * 16;

    #define LOADJC(jc, b) do {                                                        \
        const __half* pg = ph_g + (size_t)h * 131072 + (size_t)(i0 + prow) * 512 + (jc); \
        _Pragma("unroll")                                                             \
        for (int q = 0; q < 4; q++)                                                   \
            cp_async16(pb[b] + (uint32_t)(prow * AP + pc0 + q * 8) * 2, pg + pc0 + q * 8); \
        const __half* vg = qkv + 1536 + (size_t)(r * CC + (jc) + vrow) * QLD + h * DD; \
        cp_async16(vb[b] + (uint32_t)(vrow * AP + vc8) * 2,     vg + vc8);            \
        cp_async16(vb[b] + (uint32_t)(vrow * AP + vc8 + 8) * 2, vg + vc8 + 8);        \
        CP_COMMIT();                                                                  \
    } while (0)

    LOADJC(0, 0);
    #pragma unroll
    for (int it = 0; it < 4; it++) {
        CP_WAIT0();
        __syncthreads();
        if (it + 1 < 4) LOADJC((it + 1) * 64, (it + 1) & 1);
        int b = it & 1;
        #pragma unroll
        for (int ks_ = 0; ks_ < 4; ks_++) {
            uint32_t koffA = (uint32_t)ks_ * 32;
            uint32_t koffB = (uint32_t)(ks_ * 16 * AP) * 2;
            uint32_t af[2][4], bt0[4], bt1[4];
            ldsm_x4(af[0], pb[b] + offA[0] + koffA);
            ldsm_x4(af[1], pb[b] + offA[1] + koffA);
            ldsm_x4_t(bt0, vb[b] + offBT[0] + koffB);
            ldsm_x4_t(bt1, vb[b] + offBT[1] + koffB);
            #pragma unroll
            for (int mt = 0; mt < 2; mt++) {
                mma_f16(acc[mt][0], af[mt], bt0[0], bt0[1]);
                mma_f16(acc[mt][1], af[mt], bt0[2], bt0[3]);
                mma_f16(acc[mt][2], af[mt], bt1[0], bt1[1]);
                mma_f16(acc[mt][3], af[mt], bt1[2], bt1[3]);
            }
        }
    }
    #undef LOADJC

    #pragma unroll
    for (int mt = 0; mt < 2; mt++) {
        #pragma unroll
        for (int nt = 0; nt < 4; nt++) {
            int d = h * DD + wn * 32 + (nt >> 1) * 16 + (nt & 1) * 8 + 2 * t;
            #pragma unroll
            for (int hf = 0; hf < 2; hf++) {
                int m = i0 + wm * 32 + mt * 16 + g + hf * 8;
                *(__half2*)(ctx + (size_t)(r * CC + m) * EE + d) =
                    __floats2half2_rn(acc[mt][nt][hf * 2], acc[mt][nt][hf * 2 + 1]);
            }
        }
    }
}

// ---- FUSED col attention: scores + softmax + P@V per (h,c) CTA ----
__global__ void __launch_bounds__(256) col_attn_fused(
    const __half* __restrict__ qkv, __half* __restrict__ ctx)
{
    __shared__ __half qs[64 * AP];
    __shared__ __half ks[64 * AP];
    __shared__ __half vs[64 * AP];
    __shared__ float  Ss[64 * 68];
    __shared__ __half pshalf[64 * AP];
    int c = blockIdx.x, h = blockIdx.y;
    int tid = threadIdx.x;
    int wid = tid >> 5, lane = tid & 31;
    int g = lane >> 2, t = lane & 3;
    int wm = wid & 3, wn = wid >> 2;
    uint32_t qb = smem_to_u32(qs), kb = smem_to_u32(ks);
    uint32_t vb = smem_to_u32(vs), pb = smem_to_u32(pshalf);

    int lrow = tid >> 2, lc8 = (tid & 3) * 16;
    {
        const __half* qr = qkv + (size_t)(lrow * CC + c) * QLD + h * DD;
        const __half* kr = qr + 768;
        const __half* vr = qr + 1536;
        cp_async16(qb + (uint32_t)(lrow * AP + lc8) * 2,     qr + lc8);
        cp_async16(qb + (uint32_t)(lrow * AP + lc8 + 8) * 2, qr + lc8 + 8);
        cp_async16(kb + (uint32_t)(lrow * AP + lc8) * 2,     kr + lc8);
        cp_async16(kb + (uint32_t)(lrow * AP + lc8 + 8) * 2, kr + lc8 + 8);
        cp_async16(vb + (uint32_t)(lrow * AP + lc8) * 2,     vr + lc8);
        cp_async16(vb + (uint32_t)(lrow * AP + lc8 + 8) * 2, vr + lc8 + 8);
        CP_COMMIT(); CP_WAIT0();
    }
    __syncthreads();

    int l16 = lane & 15;
    uint32_t offA = (uint32_t)((wm * 16 + l16) * AP) * 2 + (uint32_t)(lane >> 4) * 16;
    int l8 = lane & 7;
    int bhv = (lane >> 3) & 1, bg = lane >> 4;
    uint32_t offB[2];
    #pragma unroll
    for (int p = 0; p < 2; p++)
        offB[p] = (uint32_t)((wn * 32 + p * 16 + bg * 8 + l8) * AP) * 2 + (uint32_t)bhv * 16;

    float acc[4][4];
    #pragma unroll
    for (int i = 0; i < 4; i++)
        #pragma unroll
        for (int cc2 = 0; cc2 < 4; cc2++) acc[i][cc2] = 0.f;

    #pragma unroll
    for (int ks_ = 0; ks_ < 4; ks_++) {
        uint32_t koff = (uint32_t)ks_ * 32;
        uint32_t af[4], bf0[4], bf1[4];
        ldsm_x4(af, qb + offA + koff);
        ldsm_x4(bf0, kb + offB[0] + koff);
        ldsm_x4(bf1, kb + offB[1] + koff);
        mma_f16(acc[0], af, bf0[0], bf0[1]);
        mma_f16(acc[1], af, bf0[2], bf0[3]);
        mma_f16(acc[2], af, bf1[0], bf1[1]);
        mma_f16(acc[3], af, bf1[2], bf1[3]);
    }

    #pragma unroll
    for (int nt = 0; nt < 4; nt++) {
        int n = wn * 32 + (nt >> 1) * 16 + (nt & 1) * 8 + 2 * t;
        #pragma unroll
        for (int hf = 0; hf < 2; hf++) {
            int m = wm * 16 + g + hf * 8;
            Ss[m * 68 + n    ] = acc[nt][hf * 2];
            Ss[m * 68 + n + 1] = acc[nt][hf * 2 + 1];
        }
    }
    __syncthreads();

    {
        int row = tid >> 2;
        int part = tid & 3;
        float* Sr = Ss + row * 68 + part * 16;
        float e[16];
        float mx = -1e30f;
        #pragma unroll
        for (int i = 0; i < 16; i++) { e[i] = Sr[i]; mx = fmaxf(mx, e[i]); }
        mx = fmaxf(mx, __shfl_xor_sync(0xffffffffu, mx, 1));
        mx = fmaxf(mx, __shfl_xor_sync(0xffffffffu, mx, 2));
        float sum = 0.f;
        #pragma unroll
        for (int i = 0; i < 16; i++) { e[i] = expf(e[i] - mx); sum += e[i]; }
        sum += __shfl_xor_sync(0xffffffffu, sum, 1);
        sum += __shfl_xor_sync(0xffffffffu, sum, 2);
        float inv = 1.0f / sum;
        __half* pr = pshalf + row * AP + part * 16;
        #pragma unroll
        for (int i = 0; i < 8; i++)
            *(__half2*)(pr + 2 * i) = __floats2half2_rn(e[2 * i] * inv, e[2 * i + 1] * inv);
    }
    __syncthreads();

    int lr = lane & 7, sel = lane >> 3;
    uint32_t offBT[2];
    #pragma unroll
    for (int ng = 0; ng < 2; ng++)
        offBT[ng] = (uint32_t)(((sel & 1) * 8 + lr) * AP) * 2
                  + (uint32_t)(wn * 32 + ng * 16 + (sel >> 1) * 8) * 2;

    float acc2[4][4];
    #pragma unroll
    for (int i = 0; i < 4; i++)
        #pragma unroll
        for (int cc2 = 0; cc2 < 4; cc2++) acc2[i][cc2] = 0.f;

    #pragma unroll
    for (int ks_ = 0; ks_ < 4; ks_++) {
        uint32_t koffA = (uint32_t)ks_ * 32;
        uint32_t koffB = (uint32_t)(ks_ * 16 * AP) * 2;
        uint32_t af[4], bt0[4], bt1[4];
        ldsm_x4(af, pb + offA + koffA);
        ldsm_x4_t(bt0, vb + offBT[0] + koffB);
        ldsm_x4_t(bt1, vb + offBT[1] + koffB);
        mma_f16(acc2[0], af, bt0[0], bt0[1]);
        mma_f16(acc2[1], af, bt0[2], bt0[3]);
        mma_f16(acc2[2], af, bt1[0], bt1[1]);
        mma_f16(acc2[3], af, bt1[2], bt1[3]);
    }

    #pragma unroll
    for (int nt = 0; nt < 4; nt++) {
        int d = h * DD + wn * 32 + (nt >> 1) * 16 + (nt & 1) * 8 + 2 * t;
        #pragma unroll
        for (int hf = 0; hf < 2; hf++) {
            int m = wm * 16 + g + hf * 8;
            *(__half2*)(ctx + (size_t)(m * CC + c) * EE + d) =
                __floats2half2_rn(acc2[nt][hf * 2], acc2[nt][hf * 2 + 1]);
        }
    }
}

// ---------------- host driver ----------------
#define GEMM_SMEM (NSTAGE * 2 * TILE_H * 2)   // 81920 bytes

static void run_gemm(const __half* A, const __half* BT, const float* bias, const float* res,
                     float* Cf, __half* Ch, int M, int N, int K, int gelu) {
    dim3 grid(N / 128, M / 128);
    mma_gemm_f16<<<grid, 256, GEMM_SMEM>>>(A, BT, bias, res, Cf, Ch, M, N, K, gelu);
}

extern "C" void kernel_launch(void* const* d_in, const int* in_sizes, int n_in,
                              void* d_out, int out_size) {
    const float* x_in = (const float*)d_in[0];
    const float* rq_w = (const float*)d_in[1];  const float* rq_b = (const float*)d_in[2];
    const float* rk_w = (const float*)d_in[3];  const float* rk_b = (const float*)d_in[4];
    const float* rv_w = (const float*)d_in[5];  const float* rv_b = (const float*)d_in[6];
    const float* ro_w = (const float*)d_in[7];  const float* ro_b = (const float*)d_in[8];
    const float* cq_w = (const float*)d_in[9];  const float* cq_b = (const float*)d_in[10];
    const float* ck_w = (const float*)d_in[11]; const float* ck_b = (const float*)d_in[12];
    const float* cv_w = (const float*)d_in[13]; const float* cv_b = (const float*)d_in[14];
    const float* co_w = (const float*)d_in[15]; const float* co_b = (const float*)d_in[16];
    const float* f1_w = (const float*)d_in[17]; const float* f1_b = (const float*)d_in[18];
    const float* f2_w = (const float*)d_in[19]; const float* f2_b = (const float*)d_in[20];
    const float* ln1_s = (const float*)d_in[21]; const float* ln1_b = (const float*)d_in[22];
    const float* ln2_s = (const float*)d_in[23]; const float* ln2_b = (const float*)d_in[24];
    const float* ln3_s = (const float*)d_in[25]; const float* ln3_b = (const float*)d_in[26];

    float *px, *paw, *pbias, *ph_f;
    void *vh, *vctx, *vbig, *vwt;
    cudaGetSymbolAddress((void**)&px,    g_x);
    cudaGetSymbolAddress(&vh,    g_h);
    cudaGetSymbolAddress(&vctx,  g_ctx);
    cudaGetSymbolAddress((void**)&paw,   g_aw);
    cudaGetSymbolAddress(&vbig,  g_big);
    cudaGetSymbolAddress(&vwt,   g_wt);
    cudaGetSymbolAddress((void**)&pbias, g_bias);
    __half* ph    = (__half*)vh;
    ph_f          = (float*)vh;          // row-score partials 4-7 (h is dead post-QKV)
    __half* pctx  = (__half*)vctx;
    __half* pqkv  = (__half*)vbig;
    __half* pffn  = (__half*)vbig;
    __half* pwt   = (__half*)vwt;

    cudaFuncSetAttribute(mma_gemm_f16, cudaFuncAttributeMaxDynamicSharedMemorySize, GEMM_SMEM);

    const float row_scale = 0.015625f;
    const float col_scale = 0.125f;

    const size_t WEE = (size_t)EE * EE;
    __half* rqkvT = pwt;
    __half* roT   = pwt + 3 * WEE;
    __half* cqkvT = pwt + 4 * WEE;
    __half* coT   = pwt + 7 * WEE;
    __half* f1T   = pwt + 8 * WEE;
    __half* f2T   = f1T + (size_t)EE * FF;
    float* biasr = pbias;
    float* biasc = pbias + 2304;

    {
        TPArgs a;
        a.src[0] = rq_w; a.dst[0] = pwt + 0 * WEE; a.scale[0] = row_scale;
        a.src[1] = rk_w; a.dst[1] = pwt + 1 * WEE; a.scale[1] = 1.f;
        a.src[2] = rv_w; a.dst[2] = pwt + 2 * WEE; a.scale[2] = 1.f;
        a.src[3] = ro_w; a.dst[3] = roT;           a.scale[3] = 1.f;
        a.src[4] = cq_w; a.dst[4] = pwt + 4 * WEE; a.scale[4] = col_scale;
        a.src[5] = ck_w; a.dst[5] = pwt + 5 * WEE; a.scale[5] = 1.f;
        a.src[6] = cv_w; a.dst[6] = pwt + 6 * WEE; a.scale[6] = 1.f;
        a.src[7] = co_w; a.dst[7] = coT;           a.scale[7] = 1.f;
        a.src[8] = f1_w; a.dst[8] = f1T;           a.scale[8] = 1.f;
        a.src[9] = f2_w; a.dst[9] = f2T;           a.scale[9] = 1.f;
        a.rb[0] = rq_b; a.rb[1] = rk_b; a.rb[2] = rv_b;
        a.cb[0] = cq_b; a.cb[1] = ck_b; a.cb[2] = cv_b;
        a.biasr = biasr; a.biasc = biasc;
        a.row_scale = row_scale; a.col_scale = col_scale;
        dim3 b(32, 8);
        transpose_all_kernel<<<9218, b>>>(a);
    }

    // ===== row attention =====
    ln_kernel<<<MM, 256>>>(x_in, ln1_s, ln1_b, ph);
    run_gemm(ph, rqkvT, biasr, nullptr, nullptr, pqkv, MM, QLD, EE, 0);
    { dim3 g(2, 4, HH * 8); row_scores_mma<<<g, 256>>>(pqkv, paw, ph_f); }
    softmax256_kernel<<<HH * CC, 256>>>(paw, ph_f);
    { dim3 g(2, RR, HH); row_ctx_mma<<<g, 256>>>(paw, pqkv, pctx); }
    run_gemm(pctx, roT, ro_b, x_in, px, nullptr, MM, EE, EE, 0);

    // ===== column attention (fused scores+softmax+ctx) =====
    ln_kernel<<<MM, 256>>>(px, ln2_s, ln2_b, ph);
    run_gemm(ph, cqkvT, biasc, nullptr, nullptr, pqkv, MM, QLD, EE, 0);
    { dim3 g(CC, HH); col_attn_fused<<<g, 256>>>(pqkv, pctx); }
    run_gemm(pctx, coT, co_b, px, px, nullptr, MM, EE, EE, 0);

    // ===== FFN =====
    ln_kernel<<<MM, 256>>>(px, ln3_s, ln3_b, ph);
    run_gemm(ph, f1T, f1_b, nullptr, nullptr, pffn, MM, FF, EE, 1);
    run_gemm(pffn, f2T, f2_b, px, (float*)d_out, nullptr, MM, EE, FF, 0);
}

// round 15
// speedup vs baseline: 1.1391x; 1.0367x over previous
#include <cuda_runtime.h>
#include <cuda_fp16.h>
#include <math.h>
#include <stdint.h>

// ---------------- problem constants ----------------
#define RR 64
#define CC 256
#define EE 768
#define HH 12
#define DD 64
#define FF 3072
#define MM (RR*CC)          // 16384 tokens
#define QLD 2304            // packed qkv row stride (halves)
#define PHSZ (HH*CC*CC)     // one row-scores partial: 786432 floats

// ---------------- scratch (device globals; no allocation allowed) ----------------
__device__ float g_x   [MM*EE];       // residual stream (fp32)
__device__ float g_h   [MM*EE];       // ln output (half) / row-score partials 4-7 (fp32)
__device__ float g_ctx [MM*EE];       // reused as __half
__device__ float g_aw  [HH*CC*RR*RR]; // row-score partials 0-3 (half p in-place post-softmax)
__device__ float g_big [MM*FF];       // reused: qkv (half) / ffn h1 (half)
__device__ float g_wt  [9437184/2 + 64];  // transposed half weights
__device__ float g_bias[4608];        // packed row/col qkv biases

// ---------------- helpers ----------------
__device__ __forceinline__ uint32_t smem_to_u32(const void* p) {
    uint32_t a;
    asm("{ .reg .u64 t; cvta.to.shared.u64 t, %1; cvt.u32.u64 %0, t; }" : "=r"(a) : "l"(p));
    return a;
}
__device__ __forceinline__ void cp_async16(uint32_t saddr, const void* gptr) {
    asm volatile("cp.async.cg.shared.global [%0], [%1], 16;" :: "r"(saddr), "l"(gptr));
}
#define CP_COMMIT() asm volatile("cp.async.commit_group;" ::: "memory")
#define CP_WAIT1()  asm volatile("cp.async.wait_group 1;" ::: "memory")
#define CP_WAIT0()  asm volatile("cp.async.wait_group 0;" ::: "memory")

__device__ __forceinline__ void ldsm_x4(uint32_t* r, uint32_t addr) {
    asm volatile("ldmatrix.sync.aligned.m8n8.x4.shared.b16 {%0,%1,%2,%3}, [%4];"
        : "=r"(r[0]), "=r"(r[1]), "=r"(r[2]), "=r"(r[3]) : "r"(addr));
}
__device__ __forceinline__ void ldsm_x4_t(uint32_t* r, uint32_t addr) {
    asm volatile("ldmatrix.sync.aligned.m8n8.x4.trans.shared.b16 {%0,%1,%2,%3}, [%4];"
        : "=r"(r[0]), "=r"(r[1]), "=r"(r[2]), "=r"(r[3]) : "r"(addr));
}

__device__ __forceinline__ void mma_f16(float* d, const uint32_t* a, uint32_t b0, uint32_t b1) {
    asm volatile("mma.sync.aligned.m16n8k16.row.col.f32.f16.f16.f32 "
        "{%0,%1,%2,%3}, {%4,%5,%6,%7}, {%8,%9}, {%0,%1,%2,%3};"
        : "+f"(d[0]), "+f"(d[1]), "+f"(d[2]), "+f"(d[3])
        : "r"(a[0]), "r"(a[1]), "r"(a[2]), "r"(a[3]), "r"(b0), "r"(b1));
}

// ---------------- gelu (tanh approx) ----------------
__device__ __forceinline__ float gelu_f(float x) {
    float x3 = x * x * x;
    return 0.5f * x * (1.0f + tanhf(0.7978845608028654f * (x + 0.044715f * x3)));
}

// ---------------- fp16 mma.sync GEMM: 128x128 tile, BK=64, 8 warps (4m x 2n), warp 32x64 ----------------
// Half the pipeline iterations of BK=32; single barrier per k-tile (3-stage ring, distance-2 prefetch).
#define BKH 64
#define PITCH_H 72
#define TILE_H (128 * PITCH_H)
#define NSTAGE 3

__global__ void __launch_bounds__(256, 2) mma_gemm_f16(
    const __half* __restrict__ A, const __half* __restrict__ BT,
    const float* __restrict__ bias, const float* __restrict__ res,
    float* __restrict__ Cf, __half* __restrict__ Ch,
    int M, int N, int K, int act_gelu)
{
    extern __shared__ __half smh[];
    uint32_t sbase = smem_to_u32(smh);
    uint32_t AbufU[NSTAGE], BbufU[NSTAGE];
    #pragma unroll
    for (int s = 0; s < NSTAGE; s++) {
        AbufU[s] = sbase + (uint32_t)(2 * s    ) * TILE_H * 2;
        BbufU[s] = sbase + (uint32_t)(2 * s + 1) * TILE_H * 2;
    }

    int tid = threadIdx.x;
    int wid = tid >> 5, lane = tid & 31;
    int g = lane >> 2, t = lane & 3;
    int wm = wid & 3, wn = wid >> 2;
    int m0 = blockIdx.y * 128, n0 = blockIdx.x * 128;

    int l16 = lane & 15;
    uint32_t a_koff = (uint32_t)(lane >> 4) * 16;
    uint32_t offA[2];
    #pragma unroll
    for (int mt = 0; mt < 2; mt++)
        offA[mt] = (uint32_t)((wm * 32 + mt * 16 + l16) * PITCH_H) * 2 + a_koff;
    int l8 = lane & 7;
    int b_half16 = (lane >> 3) & 1;
    int b_grp8 = lane >> 4;
    uint32_t offB[4];
    #pragma unroll
    for (int p = 0; p < 4; p++)
        offB[p] = (uint32_t)((wn * 64 + p * 16 + b_grp8 * 8 + l8) * PITCH_H) * 2 + (uint32_t)b_half16 * 16;

    float acc[2][8][4];
    #pragma unroll
    for (int i = 0; i < 2; i++)
        #pragma unroll
        for (int j = 0; j < 8; j++)
            #pragma unroll
            for (int c = 0; c < 4; c++) acc[i][j][c] = 0.f;

    const int NT = K / BKH;   // 12 for K=768, 48 for K=3072

    #define PREFETCH(kt, b) do {                                               \
        int k0p = (kt) * BKH;                                                  \
        _Pragma("unroll")                                                      \
        for (int i = 0; i < 4; i++) {                                          \
            int idx = i * 256 + tid;                                           \
            int row = idx >> 3, c8 = (idx & 7) * 8;                            \
            cp_async16(AbufU[b] + (uint32_t)(row * PITCH_H + c8) * 2,          \
                       A  + (size_t)(m0 + row) * K + k0p + c8);                \
            cp_async16(BbufU[b] + (uint32_t)(row * PITCH_H + c8) * 2,          \
                       BT + (size_t)(n0 + row) * K + k0p + c8);                \
        }                                                                      \
        CP_COMMIT();                                                           \
    } while (0)

    PREFETCH(0, 0);
    if (NT > 1) PREFETCH(1, 1);

    for (int kt = 0; kt < NT; kt++) {
        int b = kt % NSTAGE;
        if (kt + 1 < NT) CP_WAIT1(); else CP_WAIT0();
        __syncthreads();
        if (kt + 2 < NT) PREFETCH(kt + 2, (kt + 2) % NSTAGE);

        uint32_t Ab = AbufU[b], Bb = BbufU[b];
        #pragma unroll
        for (int ks = 0; ks < 4; ks++) {
            uint32_t koff = (uint32_t)ks * 32;     // 16 halves per k-step
            uint32_t af[2][4], bfr[4][4];
            ldsm_x4(af[0], Ab + offA[0] + koff);
            ldsm_x4(af[1], Ab + offA[1] + koff);
            #pragma unroll
            for (int p = 0; p < 4; p++)
                ldsm_x4(bfr[p], Bb + offB[p] + koff);
            #pragma unroll
            for (int mt = 0; mt < 2; mt++)
                #pragma unroll
                for (int p = 0; p < 4; p++) {
                    mma_f16(acc[mt][2 * p    ], af[mt], bfr[p][0], bfr[p][1]);
                    mma_f16(acc[mt][2 * p + 1], af[mt], bfr[p][2], bfr[p][3]);
                }
        }
        // single barrier per tile: stage reuse (3 apart) ordered by leading barriers
    }
    #undef PREFETCH

    #pragma unroll
    for (int mt = 0; mt < 2; mt++) {
        #pragma unroll
        for (int nt = 0; nt < 8; nt++) {
            int m = m0 + wm * 32 + mt * 16 + g;
            int n = n0 + wn * 64 + nt * 8 + 2 * t;
            float bx = bias[n], by = bias[n + 1];
            #pragma unroll
            for (int half = 0; half < 2; half++) {
                int mr = m + half * 8;
                float vx = acc[mt][nt][half * 2 + 0] + bx;
                float vy = acc[mt][nt][half * 2 + 1] + by;
                if (act_gelu) { vx = gelu_f(vx); vy = gelu_f(vy); }
                if (res) {
                    const float2 r2 = *(const float2*)(res + (size_t)mr * N + n);
                    vx += r2.x; vy += r2.y;
                }
                if (Cf) {
                    float2 o; o.x = vx; o.y = vy;
                    *(float2*)(Cf + (size_t)mr * N + n) = o;
                } else {
                    *(__half2*)(Ch + (size_t)mr * N + n) = __floats2half2_rn(vx, vy);
                }
            }
        }
    }
}

// ---------------- fused transpose of ALL 10 weights + bias packing ----------------
struct TPArgs {
    const float* src[10];
    __half* dst[10];
    float scale[10];
    const float* rb[3];
    const float* cb[3];
    float* biasr;
    float* biasc;
    float row_scale, col_scale;
};
__global__ void transpose_all_kernel(TPArgs args) {
    __shared__ float tbuf[32][33];
    int bid = blockIdx.x;
    if (bid >= 9216) {
        int which = bid - 9216;
        int tid = threadIdx.y * 32 + threadIdx.x;
        const float* const* src = which ? args.cb : args.rb;
        float* dst = which ? args.biasc : args.biasr;
        float qs = which ? args.col_scale : args.row_scale;
        for (int i = tid; i < 2304; i += 256) {
            int sec = i / 768, off = i % 768;
            float v = src[sec][off];
            if (sec == 0) v *= qs;
            dst[i] = v;
        }
        return;
    }
    int w, tx, ty, K, N;
    if (bid < 4608)      { w = bid / 576; int tt = bid % 576;  K = 768;  N = 768;  tx = tt % 24; ty = tt / 24; }
    else if (bid < 6912) { w = 8;         int tt = bid - 4608; K = 768;  N = 3072; tx = tt % 96; ty = tt / 96; }
    else                 { w = 9;         int tt = bid - 6912; K = 3072; N = 768;  tx = tt % 24; ty = tt / 24; }
    const float* in = args.src[w];
    __half* out = args.dst[w];
    float sc = args.scale[w];
    int x = tx * 32 + threadIdx.x;
    int y0 = ty * 32;
    #pragma unroll
    for (int i = threadIdx.y; i < 32; i += 8)
        tbuf[i][threadIdx.x] = in[(size_t)(y0 + i) * N + x];
    __syncthreads();
    int xo = ty * 32 + threadIdx.x;
    int yo0 = tx * 32;
    #pragma unroll
    for (int i = threadIdx.y; i < 32; i += 8)
        out[(size_t)(yo0 + i) * K + xo] = __float2half(tbuf[threadIdx.x][i] * sc);
}

// ---------------- layernorm (shuffle reductions, vectorized I/O): fp32 in, half out ----------------
__global__ void ln_kernel(const float* __restrict__ x, const float* __restrict__ s,
                          const float* __restrict__ b, __half* __restrict__ out) {
    __shared__ float ws[8];
    __shared__ float ws2[8];
    int t = threadIdx.x;
    int warp = t >> 5, lane = t & 31;
    const float* xr = x + (size_t)blockIdx.x * EE;
    float2 va = *(const float2*)(xr + 2 * t);
    float v2 = xr[512 + t];
    float sum = va.x + va.y + v2;
    #pragma unroll
    for (int o = 16; o; o >>= 1) sum += __shfl_xor_sync(0xffffffffu, sum, o);
    if (lane == 0) ws[warp] = sum;
    __syncthreads();
    float tot = ws[0] + ws[1] + ws[2] + ws[3] + ws[4] + ws[5] + ws[6] + ws[7];
    float mean = tot * (1.0f / EE);
    float d0 = va.x - mean, d1 = va.y - mean, d2 = v2 - mean;
    float vsum = d0 * d0 + d1 * d1 + d2 * d2;
    #pragma unroll
    for (int o = 16; o; o >>= 1) vsum += __shfl_xor_sync(0xffffffffu, vsum, o);
    if (lane == 0) ws2[warp] = vsum;
    __syncthreads();
    float vtot = ws2[0] + ws2[1] + ws2[2] + ws2[3] + ws2[4] + ws2[5] + ws2[6] + ws2[7];
    float rstd = rsqrtf(vtot * (1.0f / EE) + 1e-6f);
    __half* orow = out + (size_t)blockIdx.x * EE;
    float2 sv = *(const float2*)(s + 2 * t);
    float2 bv = *(const float2*)(b + 2 * t);
    *(__half2*)(orow + 2 * t) =
        __floats2half2_rn(d0 * rstd * sv.x + bv.x, d1 * rstd * sv.y + bv.y);
    orow[512 + t] = __float2half(d2 * rstd * s[512 + t] + b[512 + t]);
}

// ================= tensor-core attention =================
#define AP 72   // smem pitch (halves) for 64-wide attention tiles

// ---- row scores (8-way split-r, wide j): partials over 64i x 128j tiles ----
__global__ void __launch_bounds__(256) row_scores_mma(
    const __half* __restrict__ qkv, float* __restrict__ aw, float* __restrict__ aw2)
{
    __shared__ __half qs[2][64 * AP];
    __shared__ __half ks[2][128 * AP];
    int h = blockIdx.z >> 3;
    int rc = blockIdx.z & 7;
    int i0 = blockIdx.y * 64, j0 = blockIdx.x * 128;
    int tid = threadIdx.x;
    int wid = tid >> 5, lane = tid & 31;
    int g = lane >> 2, t = lane & 3;
    int wm = wid & 3, wn = wid >> 2;
    uint32_t qb[2] = { smem_to_u32(qs[0]), smem_to_u32(qs[1]) };
    uint32_t kb[2] = { smem_to_u32(ks[0]), smem_to_u32(ks[1]) };

    int l16 = lane & 15;
    uint32_t offA = (uint32_t)((wm * 16 + l16) * AP) * 2 + (uint32_t)(lane >> 4) * 16;
    int l8 = lane & 7;
    int bh = (lane >> 3) & 1, bg = lane >> 4;
    uint32_t offB[4];
    #pragma unroll
    for (int p = 0; p < 4; p++)
        offB[p] = (uint32_t)((wn * 64 + p * 16 + bg * 8 + l8) * AP) * 2 + (uint32_t)bh * 16;

    float acc[8][4];
    #pragma unroll
    for (int i = 0; i < 8; i++)
        #pragma unroll
        for (int c = 0; c < 4; c++) acc[i][c] = 0.f;

    int rbase = rc * 8;

    #define LOADRS(r, b) do {                                                       \
        _Pragma("unroll")                                                           \
        for (int i = 0; i < 6; i++) {                                               \
            int idx = i * 256 + tid;                                                \
            int row = idx >> 3, c8 = (idx & 7) * 8;                                 \
            if (i < 2) {                                                            \
                cp_async16(qb[b] + (uint32_t)(row * AP + c8) * 2,                   \
                    qkv + (size_t)((r) * CC + i0 + row) * QLD + h * DD + c8);       \
            } else {                                                                \
                int krow = row - 64;                                                \
                cp_async16(kb[b] + (uint32_t)(krow * AP + c8) * 2,                  \
                    qkv + 768 + (size_t)((r) * CC + j0 + krow) * QLD + h * DD + c8);\
            }                                                                       \
        }                                                                           \
        CP_COMMIT();                                                                \
    } while (0)

    LOADRS(rbase, 0);
    for (int rr = 0; rr < 8; rr++) {
        CP_WAIT0();
        __syncthreads();
        if (rr + 1 < 8) LOADRS(rbase + rr + 1, (rr + 1) & 1);
        int b = rr & 1;
        #pragma unroll
        for (int ks_ = 0; ks_ < 4; ks_++) {
            uint32_t koff = (uint32_t)ks_ * 32;
            uint32_t af[4], bfr[4][4];
            ldsm_x4(af, qb[b] + offA + koff);
            #pragma unroll
            for (int p = 0; p < 4; p++)
                ldsm_x4(bfr[p], kb[b] + offB[p] + koff);
            #pragma unroll
            for (int p = 0; p < 4; p++) {
                mma_f16(acc[2 * p    ], af, bfr[p][0], bfr[p][1]);
                mma_f16(acc[2 * p + 1], af, bfr[p][2], bfr[p][3]);
            }
        }
    }
    #undef LOADRS

    float* out = (rc < 4 ? aw + (size_t)rc * PHSZ : aw2 + (size_t)(rc - 4) * PHSZ)
               + (size_t)h * CC * CC;
    #pragma unroll
    for (int nt = 0; nt < 8; nt++) {
        int n = j0 + wn * 64 + (nt >> 1) * 16 + (nt & 1) * 8 + 2 * t;
        #pragma unroll
        for (int hf = 0; hf < 2; hf++) {
            int m = i0 + wm * 16 + g + hf * 8;
            float2 o; o.x = acc[nt][hf * 2]; o.y = acc[nt][hf * 2 + 1];
            *(float2*)(out + (size_t)m * CC + n) = o;
        }
    }
}

// ---- softmax 256-wide over 8 summed partials; writes HALF in-place at aw partial 0 ----
__global__ void softmax256_kernel(float* __restrict__ p, const float* __restrict__ p2) {
    __shared__ float red[256];
    int t = threadIdx.x;
    float* pr = p + (size_t)blockIdx.x * 256;
    const float* pr2 = p2 + (size_t)blockIdx.x * 256;
    float v = pr[t] + pr[t + PHSZ] + pr[t + 2 * (size_t)PHSZ] + pr[t + 3 * (size_t)PHSZ]
            + pr2[t] + pr2[t + PHSZ] + pr2[t + 2 * (size_t)PHSZ] + pr2[t + 3 * (size_t)PHSZ];
    red[t] = v;
    __syncthreads();
    for (int o = 128; o; o >>= 1) { if (t < o) red[t] = fmaxf(red[t], red[t + o]); __syncthreads(); }
    float mx = red[0];
    __syncthreads();
    float e = expf(v - mx);
    red[t] = e;
    __syncthreads();
    for (int o = 128; o; o >>= 1) { if (t < o) red[t] += red[t + o]; __syncthreads(); }
    float inv = 1.0f / red[0];
    __syncthreads();
    ((__half*)pr)[t] = __float2half(e * inv);
}

// ---- row ctx: CTA = 128i x 64d per (h,r), single-barrier double-buffered jc pipeline ----
__global__ void __launch_bounds__(256) row_ctx_mma(
    const float* __restrict__ paw, const __half* __restrict__ qkv, __half* __restrict__ ctx)
{
    __shared__ __half ps[2][128 * AP];
    __shared__ __half vs[2][64 * AP];
    int i0 = blockIdx.x * 128;
    int r = blockIdx.y, h = blockIdx.z;
    int tid = threadIdx.x;
    int wid = tid >> 5, lane = tid & 31;
    int g = lane >> 2, t = lane & 3;
    int wm = wid & 3, wn = wid >> 2;
    uint32_t pb[2] = { smem_to_u32(ps[0]), smem_to_u32(ps[1]) };
    uint32_t vb[2] = { smem_to_u32(vs[0]), smem_to_u32(vs[1]) };
    const __half* ph_g = (const __half*)paw;

    int l16 = lane & 15;
    uint32_t offA[2];
    #pragma unroll
    for (int mt = 0; mt < 2; mt++)
        offA[mt] = (uint32_t)((wm * 32 + mt * 16 + l16) * AP) * 2 + (uint32_t)(lane >> 4) * 16;
    int lr = lane & 7, sel = lane >> 3;
    uint32_t offBT[2];
    #pragma unroll
    for (int ng = 0; ng < 2; ng++)
        offBT[ng] = (uint32_t)(((sel & 1) * 8 + lr) * AP) * 2
                  + (uint32_t)(wn * 32 + ng * 16 + (sel >> 1) * 8) * 2;

    float acc[2][4][4];
    #pragma unroll
    for (int i = 0; i < 2; i++)
        #pragma unroll
        for (int j = 0; j < 4; j++)
            #pragma unroll
            for (int c = 0; c < 4; c++) acc[i][j][c] = 0.f;

    int prow = tid >> 1, pc0 = (tid & 1) * 32;
    int vrow = tid >> 2, vc8 = (tid & 3) * 16;

    #define LOADJC(jc, b) do {                                                        \
        const __half* pg = ph_g + (size_t)h * 131072 + (size_t)(i0 + prow) * 512 + (jc); \
        _Pragma("unroll")                                                             \
        for (int q = 0; q < 4; q++)                                                   \
            cp_async16(pb[b] + (uint32_t)(prow * AP + pc0 + q * 8) * 2, pg + pc0 + q * 8); \
        const __half* vg = qkv + 1536 + (size_t)(r * CC + (jc) + vrow) * QLD + h * DD; \
        cp_async16(vb[b] + (uint32_t)(vrow * AP + vc8) * 2,     vg + vc8);            \
        cp_async16(vb[b] + (uint32_t)(vrow * AP + vc8 + 8) * 2, vg + vc8 + 8);        \
        CP_COMMIT();                                                                  \
    } while (0)

    LOADJC(0, 0);
    #pragma unroll
    for (int it = 0; it < 4; it++) {
        CP_WAIT0();
        __syncthreads();
        if (it + 1 < 4) LOADJC((it + 1) * 64, (it + 1) & 1);
        int b = it & 1;
        #pragma unroll
        for (int ks_ = 0; ks_ < 4; ks_++) {
            uint32_t koffA = (uint32_t)ks_ * 32;
            uint32_t koffB = (uint32_t)(ks_ * 16 * AP) * 2;
            uint32_t af[2][4], bt0[4], bt1[4];
            ldsm_x4(af[0], pb[b] + offA[0] + koffA);
            ldsm_x4(af[1], pb[b] + offA[1] + koffA);
            ldsm_x4_t(bt0, vb[b] + offBT[0] + koffB);
            ldsm_x4_t(bt1, vb[b] + offBT[1] + koffB);
            #pragma unroll
            for (int mt = 0; mt < 2; mt++) {
                mma_f16(acc[mt][0], af[mt], bt0[0], bt0[1]);
                mma_f16(acc[mt][1], af[mt], bt0[2], bt0[3]);
                mma_f16(acc[mt][2], af[mt], bt1[0], bt1[1]);
                mma_f16(acc[mt][3], af[mt], bt1[2], bt1[3]);
            }
        }
    }
    #undef LOADJC

    #pragma unroll
    for (int mt = 0; mt < 2; mt++) {
        #pragma unroll
        for (int nt = 0; nt < 4; nt++) {
            int d = h * DD + wn * 32 + (nt >> 1) * 16 + (nt & 1) * 8 + 2 * t;
            #pragma unroll
            for (int hf = 0; hf < 2; hf++) {
                int m = i0 + wm * 32 + mt * 16 + g + hf * 8;
                *(__half2*)(ctx + (size_t)(r * CC + m) * EE + d) =
                    __floats2half2_rn(acc[mt][nt][hf * 2], acc[mt][nt][hf * 2 + 1]);
            }
        }
    }
}

// ---- FUSED col attention: scores + softmax + P@V per (h,c) CTA ----
__global__ void __launch_bounds__(256) col_attn_fused(
    const __half* __restrict__ qkv, __half* __restrict__ ctx)
{
    __shared__ __half qs[64 * AP];
    __shared__ __half ks[64 * AP];
    __shared__ __half vs[64 * AP];
    __shared__ float  Ss[64 * 68];
    __shared__ __half pshalf[64 * AP];
    int c = blockIdx.x, h = blockIdx.y;
    int tid = threadIdx.x;
    int wid = tid >> 5, lane = tid & 31;
    int g = lane >> 2, t = lane & 3;
    int wm = wid & 3, wn = wid >> 2;
    uint32_t qb = smem_to_u32(qs), kb = smem_to_u32(ks);
    uint32_t vb = smem_to_u32(vs), pb = smem_to_u32(pshalf);

    int lrow = tid >> 2, lc8 = (tid & 3) * 16;
    {
        const __half* qr = qkv + (size_t)(lrow * CC + c) * QLD + h * DD;
        const __half* kr = qr + 768;
        const __half* vr = qr + 1536;
        cp_async16(qb + (uint32_t)(lrow * AP + lc8) * 2,     qr + lc8);
        cp_async16(qb + (uint32_t)(lrow * AP + lc8 + 8) * 2, qr + lc8 + 8);
        cp_async16(kb + (uint32_t)(lrow * AP + lc8) * 2,     kr + lc8);
        cp_async16(kb + (uint32_t)(lrow * AP + lc8 + 8) * 2, kr + lc8 + 8);
        cp_async16(vb + (uint32_t)(lrow * AP + lc8) * 2,     vr + lc8);
        cp_async16(vb + (uint32_t)(lrow * AP + lc8 + 8) * 2, vr + lc8 + 8);
        CP_COMMIT(); CP_WAIT0();
    }
    __syncthreads();

    int l16 = lane & 15;
    uint32_t offA = (uint32_t)((wm * 16 + l16) * AP) * 2 + (uint32_t)(lane >> 4) * 16;
    int l8 = lane & 7;
    int bhv = (lane >> 3) & 1, bg = lane >> 4;
    uint32_t offB[2];
    #pragma unroll
    for (int p = 0; p < 2; p++)
        offB[p] = (uint32_t)((wn * 32 + p * 16 + bg * 8 + l8) * AP) * 2 + (uint32_t)bhv * 16;

    float acc[4][4];
    #pragma unroll
    for (int i = 0; i < 4; i++)
        #pragma unroll
        for (int cc2 = 0; cc2 < 4; cc2++) acc[i][cc2] = 0.f;

    #pragma unroll
    for (int ks_ = 0; ks_ < 4; ks_++) {
        uint32_t koff = (uint32_t)ks_ * 32;
        uint32_t af[4], bf0[4], bf1[4];
        ldsm_x4(af, qb + offA + koff);
        ldsm_x4(bf0, kb + offB[0] + koff);
        ldsm_x4(bf1, kb + offB[1] + koff);
        mma_f16(acc[0], af, bf0[0], bf0[1]);
        mma_f16(acc[1], af, bf0[2], bf0[3]);
        mma_f16(acc[2], af, bf1[0], bf1[1]);
        mma_f16(acc[3], af, bf1[2], bf1[3]);
    }

    #pragma unroll
    for (int nt = 0; nt < 4; nt++) {
        int n = wn * 32 + (nt >> 1) * 16 + (nt & 1) * 8 + 2 * t;
        #pragma unroll
        for (int hf = 0; hf < 2; hf++) {
            int m = wm * 16 + g + hf * 8;
            Ss[m * 68 + n    ] = acc[nt][hf * 2];
            Ss[m * 68 + n + 1] = acc[nt][hf * 2 + 1];
        }
    }
    __syncthreads();

    {
        int row = tid >> 2;
        int part = tid & 3;
        float* Sr = Ss + row * 68 + part * 16;
        float e[16];
        float mx = -1e30f;
        #pragma unroll
        for (int i = 0; i < 16; i++) { e[i] = Sr[i]; mx = fmaxf(mx, e[i]); }
        mx = fmaxf(mx, __shfl_xor_sync(0xffffffffu, mx, 1));
        mx = fmaxf(mx, __shfl_xor_sync(0xffffffffu, mx, 2));
        float sum = 0.f;
        #pragma unroll
        for (int i = 0; i < 16; i++) { e[i] = expf(e[i] - mx); sum += e[i]; }
        sum += __shfl_xor_sync(0xffffffffu, sum, 1);
        sum += __shfl_xor_sync(0xffffffffu, sum, 2);
        float inv = 1.0f / sum;
        __half* pr = pshalf + row * AP + part * 16;
        #pragma unroll
        for (int i = 0; i < 8; i++)
            *(__half2*)(pr + 2 * i) = __floats2half2_rn(e[2 * i] * inv, e[2 * i + 1] * inv);
    }
    __syncthreads();

    int lr = lane & 7, sel = lane >> 3;
    uint32_t offBT[2];
    #pragma unroll
    for (int ng = 0; ng < 2; ng++)
        offBT[ng] = (uint32_t)(((sel & 1) * 8 + lr) * AP) * 2
                  + (uint32_t)(wn * 32 + ng * 16 + (sel >> 1) * 8) * 2;

    float acc2[4][4];
    #pragma unroll
    for (int i = 0; i < 4; i++)
        #pragma unroll
        for (int cc2 = 0; cc2 < 4; cc2++) acc2[i][cc2] = 0.f;

    #pragma unroll
    for (int ks_ = 0; ks_ < 4; ks_++) {
        uint32_t koffA = (uint32_t)ks_ * 32;
        uint32_t koffB = (uint32_t)(ks_ * 16 * AP) * 2;
        uint32_t af[4], bt0[4], bt1[4];
        ldsm_x4(af, pb + offA + koffA);
        ldsm_x4_t(bt0, vb + offBT[0] + koffB);
        ldsm_x4_t(bt1, vb + offBT[1] + koffB);
        mma_f16(acc2[0], af, bt0[0], bt0[1]);
        mma_f16(acc2[1], af, bt0[2], bt0[3]);
        mma_f16(acc2[2], af, bt1[0], bt1[1]);
        mma_f16(acc2[3], af, bt1[2], bt1[3]);
    }

    #pragma unroll
    for (int nt = 0; nt < 4; nt++) {
        int d = h * DD + wn * 32 + (nt >> 1) * 16 + (nt & 1) * 8 + 2 * t;
        #pragma unroll
        for (int hf = 0; hf < 2; hf++) {
            int m = wm * 16 + g + hf * 8;
            *(__half2*)(ctx + (size_t)(m * CC + c) * EE + d) =
                __floats2half2_rn(acc2[nt][hf * 2], acc2[nt][hf * 2 + 1]);
        }
    }
}

// ---------------- host driver ----------------
#define GEMM_SMEM (NSTAGE * 2 * TILE_H * 2)   // 3 * 36864 = 110592 bytes

static void run_gemm(const __half* A, const __half* BT, const float* bias, const float* res,
                     float* Cf, __half* Ch, int M, int N, int K, int gelu) {
    dim3 grid(N / 128, M / 128);
    mma_gemm_f16<<<grid, 256, GEMM_SMEM>>>(A, BT, bias, res, Cf, Ch, M, N, K, gelu);
}

extern "C" void kernel_launch(void* const* d_in, const int* in_sizes, int n_in,
                              void* d_out, int out_size) {
    const float* x_in = (const float*)d_in[0];
    const float* rq_w = (const float*)d_in[1];  const float* rq_b = (const float*)d_in[2];
    const float* rk_w = (const float*)d_in[3];  const float* rk_b = (const float*)d_in[4];
    const float* rv_w = (const float*)d_in[5];  const float* rv_b = (const float*)d_in[6];
    const float* ro_w = (const float*)d_in[7];  const float* ro_b = (const float*)d_in[8];
    const float* cq_w = (const float*)d_in[9];  const float* cq_b = (const float*)d_in[10];
    const float* ck_w = (const float*)d_in[11]; const float* ck_b = (const float*)d_in[12];
    const float* cv_w = (const float*)d_in[13]; const float* cv_b = (const float*)d_in[14];
    const float* co_w = (const float*)d_in[15]; const float* co_b = (const float*)d_in[16];
    const float* f1_w = (const float*)d_in[17]; const float* f1_b = (const float*)d_in[18];
    const float* f2_w = (const float*)d_in[19]; const float* f2_b = (const float*)d_in[20];
    const float* ln1_s = (const float*)d_in[21]; const float* ln1_b = (const float*)d_in[22];
    const float* ln2_s = (const float*)d_in[23]; const float* ln2_b = (const float*)d_in[24];
    const float* ln3_s = (const float*)d_in[25]; const float* ln3_b = (const float*)d_in[26];

    float *px, *paw, *pbias, *ph_f;
    void *vh, *vctx, *vbig, *vwt;
    cudaGetSymbolAddress((void**)&px,    g_x);
    cudaGetSymbolAddress(&vh,    g_h);
    cudaGetSymbolAddress(&vctx,  g_ctx);
    cudaGetSymbolAddress((void**)&paw,   g_aw);
    cudaGetSymbolAddress(&vbig,  g_big);
    cudaGetSymbolAddress(&vwt,   g_wt);
    cudaGetSymbolAddress((void**)&pbias, g_bias);
    __half* ph    = (__half*)vh;
    ph_f          = (float*)vh;          // row-score partials 4-7 (h is dead post-QKV)
    __half* pctx  = (__half*)vctx;
    __half* pqkv  = (__half*)vbig;
    __half* pffn  = (__half*)vbig;
    __half* pwt   = (__half*)vwt;

    cudaFuncSetAttribute(mma_gemm_f16, cudaFuncAttributeMaxDynamicSharedMemorySize, GEMM_SMEM);

    const float row_scale = 0.015625f;
    const float col_scale = 0.125f;

    const size_t WEE = (size_t)EE * EE;
    __half* rqkvT = pwt;
    __half* roT   = pwt + 3 * WEE;
    __half* cqkvT = pwt + 4 * WEE;
    __half* coT   = pwt + 7 * WEE;
    __half* f1T   = pwt + 8 * WEE;
    __half* f2T   = f1T + (size_t)EE * FF;
    float* biasr = pbias;
    float* biasc = pbias + 2304;

    {
        TPArgs a;
        a.src[0] = rq_w; a.dst[0] = pwt + 0 * WEE; a.scale[0] = row_scale;
        a.src[1] = rk_w; a.dst[1] = pwt + 1 * WEE; a.scale[1] = 1.f;
        a.src[2] = rv_w; a.dst[2] = pwt + 2 * WEE; a.scale[2] = 1.f;
        a.src[3] = ro_w; a.dst[3] = roT;           a.scale[3] = 1.f;
        a.src[4] = cq_w; a.dst[4] = pwt + 4 * WEE; a.scale[4] = col_scale;
        a.src[5] = ck_w; a.dst[5] = pwt + 5 * WEE; a.scale[5] = 1.f;
        a.src[6] = cv_w; a.dst[6] = pwt + 6 * WEE; a.scale[6] = 1.f;
        a.src[7] = co_w; a.dst[7] = coT;           a.scale[7] = 1.f;
        a.src[8] = f1_w; a.dst[8] = f1T;           a.scale[8] = 1.f;
        a.src[9] = f2_w; a.dst[9] = f2T;           a.scale[9] = 1.f;
        a.rb[0] = rq_b; a.rb[1] = rk_b; a.rb[2] = rv_b;
        a.cb[0] = cq_b; a.cb[1] = ck_b; a.cb[2] = cv_b;
        a.biasr = biasr; a.biasc = biasc;
        a.row_scale = row_scale; a.col_scale = col_scale;
        dim3 b(32, 8);
        transpose_all_kernel<<<9218, b>>>(a);
    }

    // ===== row attention =====
    ln_kernel<<<MM, 256>>>(x_in, ln1_s, ln1_b, ph);
    run_gemm(ph, rqkvT, biasr, nullptr, nullptr, pqkv, MM, QLD, EE, 0);
    { dim3 g(2, 4, HH * 8); row_scores_mma<<<g, 256>>>(pqkv, paw, ph_f); }
    softmax256_kernel<<<HH * CC, 256>>>(paw, ph_f);
    { dim3 g(2, RR, HH); row_ctx_mma<<<g, 256>>>(paw, pqkv, pctx); }
    run_gemm(pctx, roT, ro_b, x_in, px, nullptr, MM, EE, EE, 0);

    // ===== column attention (fused scores+softmax+ctx) =====
    ln_kernel<<<MM, 256>>>(px, ln2_s, ln2_b, ph);
    run_gemm(ph, cqkvT, biasc, nullptr, nullptr, pqkv, MM, QLD, EE, 0);
    { dim3 g(CC, HH); col_attn_fused<<<g, 256>>>(pqkv, pctx); }
    run_gemm(pctx, coT, co_b, px, px, nullptr, MM, EE, EE, 0);

    // ===== FFN =====
    ln_kernel<<<MM, 256>>>(px, ln3_s, ln3_b, ph);
    run_gemm(ph, f1T, f1_b, nullptr, nullptr, pffn, MM, FF, EE, 1);
    run_gemm(pffn, f2T, f2_b, px, (float*)d_out, nullptr, MM, EE, FF, 0);
}